// round 5
// baseline (speedup 1.0000x reference)
#include <cuda_runtime.h>
#include <cuda_bf16.h>
#include <cstdint>

#define NB   2
#define NS   1024
#define ND   1024
#define NH   16
#define NHD  64
#define NNC  64
#define NCB  16
#define NSB  8
#define NJ   2
#define NWIN 256

#define INVS 0.125f
#define NEG  (-1e30f)

#define KA   1024
#define BM   128
#define BN   128
#define BK   32
#define AST  40
#define NIT  (KA / BK)            // 32

// ---------------- scratch (device globals; no allocation allowed) ----------------
__device__ __align__(16) float g_q [NB*NS*ND];
__device__ __align__(16) float g_k [NB*NS*ND];
__device__ __align__(16) float g_v [NB*NS*ND];
__device__ __align__(16) float g_ck[NB*NNC*ND];
__device__ __align__(16) float g_cv[NB*NNC*ND];
__device__ __align__(16) float g_oc[NB*NS*ND];
__device__ __align__(16) float g_os[NB*NS*ND];
__device__ __align__(16) float g_ow[NB*NS*ND];
__device__ __align__(16) float g_pre[NB*NS*ND];
__device__ int   g_top[NB*NS*NJ];
__device__ __align__(16) __nv_bfloat16 g_ah[(size_t)NB*NS*ND];   // A hi [2048,1024]
__device__ __align__(16) __nv_bfloat16 g_al[(size_t)NB*NS*ND];   // A lo
__device__ __align__(16) __nv_bfloat16 g_wh[(size_t)ND*ND];      // W^T hi [1024,1024]
__device__ __align__(16) __nv_bfloat16 g_wl[(size_t)ND*ND];      // W^T lo
__device__ __align__(16) float g_xkc[NB*NNC*ND];   // wkc-combined x rows [128,1024]
__device__ __align__(16) float g_xvc[NB*NNC*ND];
__device__ __align__(16) float g_pec[ND];          // wkc-combined pe row
__device__ __align__(16) float g_pvc[ND];
__device__ __align__(16) float g_tt [NB*NNC*ND];   // Tt[b][n][d'] = sum_d ck[b,n,d]*Wq[d',d]
__device__ __align__(16) float g_imp[NB*NS*NNC];   // imp[b][s][n]

// ======================= PTX helpers ================================================
__device__ __forceinline__ void cp16(uint32_t d, const void* s) {
    asm volatile("cp.async.cg.shared.global [%0], [%1], 16;" :: "r"(d), "l"(s));
}
__device__ __forceinline__ void cp_commit() {
    asm volatile("cp.async.commit_group;");
}
__device__ __forceinline__ void cp_wait1() {
    asm volatile("cp.async.wait_group 1;");
}
__device__ __forceinline__ void ldsm_x4(uint32_t& r0, uint32_t& r1, uint32_t& r2, uint32_t& r3,
                                        uint32_t addr) {
    asm volatile("ldmatrix.sync.aligned.m8n8.x4.shared.b16 {%0,%1,%2,%3}, [%4];"
        : "=r"(r0), "=r"(r1), "=r"(r2), "=r"(r3) : "r"(addr));
}
__device__ __forceinline__ void mma16816(float* c, const uint32_t* a, const uint32_t* b) {
    asm volatile("mma.sync.aligned.m16n8k16.row.col.f32.bf16.bf16.f32 "
        "{%0,%1,%2,%3}, {%4,%5,%6,%7}, {%8,%9}, {%0,%1,%2,%3};"
        : "+f"(c[0]), "+f"(c[1]), "+f"(c[2]), "+f"(c[3])
        : "r"(a[0]), "r"(a[1]), "r"(a[2]), "r"(a[3]), "r"(b[0]), "r"(b[1]));
}

// ======================= split conversions =========================================
__global__ __launch_bounds__(256) void split_kernel(
    const float* __restrict__ src, __nv_bfloat16* __restrict__ hi,
    __nv_bfloat16* __restrict__ lo)
{
    int idx = blockIdx.x * 256 + threadIdx.x;
    float v = src[idx];
    __nv_bfloat16 h = __float2bfloat16(v);
    hi[idx] = h;
    lo[idx] = __float2bfloat16(v - __bfloat162float(h));
}

// W[k][n] -> Wh/Wl [n][k]
__global__ __launch_bounds__(256) void convert_w_kernel(
    const float* __restrict__ W, __nv_bfloat16* __restrict__ Wh,
    __nv_bfloat16* __restrict__ Wl)
{
    __shared__ float t[32][33];
    int n0 = blockIdx.x * 32, k0 = blockIdx.y * 32;
    int tx = threadIdx.x & 31, ty = threadIdx.x >> 5;
#pragma unroll
    for (int i = 0; i < 32; i += 8)
        t[ty + i][tx] = W[(k0 + ty + i) * 1024 + n0 + tx];
    __syncthreads();
#pragma unroll
    for (int i = 0; i < 32; i += 8) {
        int n = n0 + ty + i, k = k0 + tx;
        float v = t[tx][ty + i];
        __nv_bfloat16 h = __float2bfloat16(v);
        Wh[(size_t)n * 1024 + k] = h;
        Wl[(size_t)n * 1024 + k] = __float2bfloat16(v - __bfloat162float(h));
    }
}

// ======================= HMMA GEMM (K=1024) =========================================
// C[2048,1024] (+)= A[2048,1024] @ B[1024,1024]^T, bf16 in, f32 accum.
// mode 0: store | 1: store += wpe[(m&15)*1024+n] | 2: store += bias[n] | 3: C += acc
__global__ __launch_bounds__(256) void mma_gemm_kernel(
    const __nv_bfloat16* __restrict__ A, const __nv_bfloat16* __restrict__ B,
    float* __restrict__ C, int mode, const float* __restrict__ extra)
{
    __shared__ __nv_bfloat16 sA[2][BM * AST];
    __shared__ __nv_bfloat16 sB[2][BN * AST];

    const int tid = threadIdx.x;
    const int wid = tid >> 5, lane = tid & 31;
    const int wm = wid >> 2, wn = wid & 3;
    const int mt = blockIdx.y * BM, nt = blockIdx.x * BN;

    const uint32_t sAb = (uint32_t)__cvta_generic_to_shared(&sA[0][0]);
    const uint32_t sBb = (uint32_t)__cvta_generic_to_shared(&sB[0][0]);
    const uint32_t STG_A = BM * AST * 2;
    const uint32_t STG_B = BN * AST * 2;

    const int lrow = tid >> 1;
    const int lc   = (tid & 1) * 2;
    const __nv_bfloat16* gA = A + (size_t)(mt + lrow) * KA + lc * 8;
    const __nv_bfloat16* gB = B + (size_t)(nt + lrow) * KA + lc * 8;
    const uint32_t dA = sAb + (lrow * AST + lc * 8) * 2;
    const uint32_t dB = sBb + (lrow * AST + lc * 8) * 2;

    float c[4][4][4];
#pragma unroll
    for (int i = 0; i < 4; i++)
#pragma unroll
        for (int j = 0; j < 4; j++)
#pragma unroll
            for (int r = 0; r < 4; r++) c[i][j][r] = 0.f;

    const int al  = lane & 15;
    const int ahi = lane >> 4;

    cp16(dA, gA);            cp16(dA + 16, gA + 8);
    cp16(dB, gB);            cp16(dB + 16, gB + 8);
    cp_commit();

    int buf = 0;
    for (int it = 0; it < NIT; it++) {
        if (it + 1 < NIT) {
            const int k0 = (it + 1) * BK;
            cp16(dA + (buf ^ 1) * STG_A,      gA + k0);
            cp16(dA + (buf ^ 1) * STG_A + 16, gA + k0 + 8);
            cp16(dB + (buf ^ 1) * STG_B,      gB + k0);
            cp16(dB + (buf ^ 1) * STG_B + 16, gB + k0 + 8);
        }
        cp_commit();
        cp_wait1();
        __syncthreads();

#pragma unroll
        for (int ks = 0; ks < 2; ks++) {
            const int kg = ks * 2 + ahi;
            uint32_t a[4][4], b[4][2];
#pragma unroll
            for (int i = 0; i < 4; i++) {
                uint32_t ad = sAb + buf * STG_A +
                              ((wm * 64 + i * 16 + al) * AST + kg * 8) * 2;
                ldsm_x4(a[i][0], a[i][1], a[i][2], a[i][3], ad);
            }
#pragma unroll
            for (int jj = 0; jj < 2; jj++) {
                uint32_t bd = sBb + buf * STG_B +
                              ((wn * 32 + jj * 16 + al) * AST + kg * 8) * 2;
                uint32_t r0, r1, r2, r3;
                ldsm_x4(r0, r1, r2, r3, bd);
                b[jj * 2 + 0][0] = r0; b[jj * 2 + 1][0] = r1;
                b[jj * 2 + 0][1] = r2; b[jj * 2 + 1][1] = r3;
            }
#pragma unroll
            for (int i = 0; i < 4; i++)
#pragma unroll
                for (int j = 0; j < 4; j++) mma16816(c[i][j], a[i], b[j]);
        }
        __syncthreads();
        buf ^= 1;
    }

    const int mbase = mt + wm * 64;
    const int nbase = nt + wn * 32;
    const int rr = lane >> 2, cc = (lane & 3) * 2;
#pragma unroll
    for (int i = 0; i < 4; i++) {
#pragma unroll
        for (int j = 0; j < 4; j++) {
            int row = mbase + i * 16 + rr;
            int col = nbase + j * 8 + cc;
            float* p0c = C + (size_t)row * 1024 + col;
            float* p1c = C + (size_t)(row + 8) * 1024 + col;
            float2 v0 = make_float2(c[i][j][0], c[i][j][1]);
            float2 v1 = make_float2(c[i][j][2], c[i][j][3]);
            if (mode == 3) {
                float2 o0 = *(float2*)p0c, o1 = *(float2*)p1c;
                v0.x += o0.x; v0.y += o0.y;
                v1.x += o1.x; v1.y += o1.y;
            } else if (mode == 1) {
                const float* p0 = extra + (row & 15) * 1024 + col;
                const float* p1 = extra + ((row + 8) & 15) * 1024 + col;
                v0.x += p0[0]; v0.y += p0[1];
                v1.x += p1[0]; v1.y += p1[1];
            } else if (mode == 2) {
                v0.x += extra[col]; v0.y += extra[col + 1];
                v1.x += extra[col]; v1.y += extra[col + 1];
            }
            *(float2*)p0c = v0;
            *(float2*)p1c = v1;
        }
    }
}

// ======================= fp32 SGEMM (for exact ck/cv) ===============================
// C[M,N] = A[M,K] @ B[K,N]; mode 2: += bias[n]
__global__ __launch_bounds__(256) void sgemm_kernel(
    const float* __restrict__ A, const float* __restrict__ Bm,
    float* __restrict__ C, int M, int N, int K,
    int mode, const float* __restrict__ extra)
{
    __shared__ float As[16][132];
    __shared__ float Bs[16][64];

    const int tid = threadIdx.x;
    const int bm  = blockIdx.y * 128;
    const int bn  = blockIdx.x * 64;
    const int tx  = tid & 15;
    const int ty  = tid >> 4;

    const int arow = tid >> 1;
    const int acol = (tid & 1) * 8;
    const int brow = tid >> 4;
    const int bcol = (tid & 15) * 4;

    float acc[8][4];
#pragma unroll
    for (int i = 0; i < 8; i++)
#pragma unroll
        for (int j = 0; j < 4; j++) acc[i][j] = 0.f;

    for (int k0 = 0; k0 < K; k0 += 16) {
        float4 a0 = *(const float4*)(A + (bm + arow) * K + k0 + acol);
        float4 a1 = *(const float4*)(A + (bm + arow) * K + k0 + acol + 4);
        As[acol+0][arow] = a0.x; As[acol+1][arow] = a0.y;
        As[acol+2][arow] = a0.z; As[acol+3][arow] = a0.w;
        As[acol+4][arow] = a1.x; As[acol+5][arow] = a1.y;
        As[acol+6][arow] = a1.z; As[acol+7][arow] = a1.w;
        float4 b4 = *(const float4*)(Bm + (k0 + brow) * N + bn + bcol);
        *(float4*)&Bs[brow][bcol] = b4;
        __syncthreads();

#pragma unroll
        for (int kk = 0; kk < 16; kk++) {
            float4 t0 = *(const float4*)&As[kk][ty * 8];
            float4 t1 = *(const float4*)&As[kk][ty * 8 + 4];
            float4 bb = *(const float4*)&Bs[kk][tx * 4];
            float ar[8] = {t0.x, t0.y, t0.z, t0.w, t1.x, t1.y, t1.z, t1.w};
            float br[4] = {bb.x, bb.y, bb.z, bb.w};
#pragma unroll
            for (int i = 0; i < 8; i++)
#pragma unroll
                for (int j = 0; j < 4; j++) acc[i][j] += ar[i] * br[j];
        }
        __syncthreads();
    }

#pragma unroll
    for (int i = 0; i < 8; i++) {
        int m = bm + ty * 8 + i;
#pragma unroll
        for (int j = 0; j < 4; j++) {
            int n = bn + tx * 4 + j;
            float vv = acc[i][j];
            if (mode == 2) vv += extra[n];
            C[m * N + n] = vv;
        }
    }
}

// ======================= fp32 NT GEMM: C[i,j] = sum_k A[i,k]*B[j,k], K=1024 =========
__global__ __launch_bounds__(256) void nt_gemm_kernel(
    const float* __restrict__ A, const float* __restrict__ B, float* __restrict__ C,
    int N, long aB, long bB, long cB)
{
    const float* Ab = A + (size_t)blockIdx.z * aB;
    const float* Bb = B + (size_t)blockIdx.z * bB;
    float* Cb = C + (size_t)blockIdx.z * cB;

    __shared__ float As[64][33];
    __shared__ float Bs[64][33];

    const int tid = threadIdx.x;
    const int row = tid >> 2;
    const int c4  = (tid & 3) * 8;
    const int ty = tid >> 4, tx = tid & 15;
    const int i0 = blockIdx.y * 64, j0 = blockIdx.x * 64;

    float acc[4][4];
#pragma unroll
    for (int i = 0; i < 4; i++)
#pragma unroll
        for (int j = 0; j < 4; j++) acc[i][j] = 0.f;

    for (int k0 = 0; k0 < 1024; k0 += 32) {
        float4 a0 = *(const float4*)(Ab + (size_t)(i0 + row) * 1024 + k0 + c4);
        float4 a1 = *(const float4*)(Ab + (size_t)(i0 + row) * 1024 + k0 + c4 + 4);
        // scalar smem stores: As row stride (33 floats) is not 16B-aligned
        As[row][c4+0] = a0.x; As[row][c4+1] = a0.y;
        As[row][c4+2] = a0.z; As[row][c4+3] = a0.w;
        As[row][c4+4] = a1.x; As[row][c4+5] = a1.y;
        As[row][c4+6] = a1.z; As[row][c4+7] = a1.w;
        float4 b0 = *(const float4*)(Bb + (size_t)(j0 + row) * 1024 + k0 + c4);
        float4 b1 = *(const float4*)(Bb + (size_t)(j0 + row) * 1024 + k0 + c4 + 4);
        Bs[row][c4+0] = b0.x; Bs[row][c4+1] = b0.y;
        Bs[row][c4+2] = b0.z; Bs[row][c4+3] = b0.w;
        Bs[row][c4+4] = b1.x; Bs[row][c4+5] = b1.y;
        Bs[row][c4+6] = b1.z; Bs[row][c4+7] = b1.w;
        __syncthreads();

#pragma unroll 8
        for (int k = 0; k < 32; k++) {
            float ar[4], br[4];
#pragma unroll
            for (int i = 0; i < 4; i++) ar[i] = As[ty * 4 + i][k];
#pragma unroll
            for (int j = 0; j < 4; j++) br[j] = Bs[tx * 4 + j][k];
#pragma unroll
            for (int i = 0; i < 4; i++)
#pragma unroll
                for (int j = 0; j < 4; j++) acc[i][j] += ar[i] * br[j];
        }
        __syncthreads();
    }

#pragma unroll
    for (int i = 0; i < 4; i++)
#pragma unroll
        for (int j = 0; j < 4; j++)
            Cb[(size_t)(i0 + ty * 4 + i) * N + j0 + tx * 4 + j] = acc[i][j];
}

// ---------------- exact compressed-row inputs ---------------------------------------
// xkc/xvc[b,n,d] = sum_t wkc/wvc[t] * x[b, n*16+t, d]
__global__ __launch_bounds__(256) void xc_kernel(
    const float* __restrict__ x, const float* __restrict__ wkc,
    const float* __restrict__ wvc)
{
    int idx = blockIdx.x * 256 + threadIdx.x;   // 131072
    int d = idx & 1023;
    int n = (idx >> 10) & 63;
    int b = idx >> 16;
    const float* xb = x + ((size_t)(b * NS + n * NCB)) * ND + d;
    float sk = 0.f, sv = 0.f;
#pragma unroll
    for (int t = 0; t < NCB; t++) {
        float xv = xb[t * ND];
        sk += wkc[t] * xv;
        sv += wvc[t] * xv;
    }
    g_xkc[idx] = sk;
    g_xvc[idx] = sv;
}

__global__ __launch_bounds__(256) void pe_comb_kernel(
    const float* __restrict__ wpe, const float* __restrict__ wkc,
    const float* __restrict__ wvc)
{
    int d = blockIdx.x * 256 + threadIdx.x;   // 1024
    float sk = 0.f, sv = 0.f;
#pragma unroll
    for (int t = 0; t < NCB; t++) {
        float p = wpe[t * ND + d];
        sk += wkc[t] * p;
        sv += wvc[t] * p;
    }
    g_pec[d] = sk;
    g_pvc[d] = sv;
}

// ---------------- top-2 over exact imp ----------------------------------------------
__global__ __launch_bounds__(256) void top2_kernel()
{
    const int bs = blockIdx.x * 8 + (threadIdx.x >> 5);
    const int lane = threadIdx.x & 31;
    const float* row = g_imp + (size_t)bs * 64;
    float v0 = row[lane], v1 = row[lane + 32];

    float bv; int bi;
    if (v0 >= v1) { bv = v0; bi = lane; } else { bv = v1; bi = lane + 32; }
#pragma unroll
    for (int off = 16; off > 0; off >>= 1) {
        float ov = __shfl_xor_sync(0xffffffffu, bv, off);
        int   oi = __shfl_xor_sync(0xffffffffu, bi, off);
        if (ov > bv || (ov == bv && oi < bi)) { bv = ov; bi = oi; }
    }
    int top1 = bi;
    float w0 = (lane == top1)      ? NEG : v0;
    float w1 = (lane + 32 == top1) ? NEG : v1;
    float bv2; int bi2;
    if (w0 >= w1) { bv2 = w0; bi2 = lane; } else { bv2 = w1; bi2 = lane + 32; }
#pragma unroll
    for (int off = 16; off > 0; off >>= 1) {
        float ov = __shfl_xor_sync(0xffffffffu, bv2, off);
        int   oi = __shfl_xor_sync(0xffffffffu, bi2, off);
        if (ov > bv2 || (ov == bv2 && oi < bi2)) { bv2 = ov; bi2 = oi; }
    }
    if (lane == 0) { g_top[bs * 2] = top1; g_top[bs * 2 + 1] = bi2; }
}

// ---------------- compressed attention (output only) --------------------------------
__global__ __launch_bounds__(512) void comp_attn_kernel()
{
    const int bs = blockIdx.x;
    const int b  = bs >> 10;
    const int tid = threadIdx.x;
    const int h = tid >> 5, lane = tid & 31;

    const float2 q2 = *(const float2*)(g_q + bs * ND + h * 64 + lane * 2);

    float s0 = 0.f, s1 = 0.f;
    for (int n = 0; n < 64; n++) {
        float2 c2 = *(const float2*)(g_ck + (b * 64 + n) * ND + h * 64 + lane * 2);
        float p = q2.x * c2.x + q2.y * c2.y;
#pragma unroll
        for (int off = 16; off > 0; off >>= 1)
            p += __shfl_xor_sync(0xffffffffu, p, off);
        p *= INVS;
        if (lane == (n & 31)) { if (n < 32) s0 = p; else s1 = p; }
    }
    float mx = fmaxf(s0, s1);
#pragma unroll
    for (int off = 16; off > 0; off >>= 1)
        mx = fmaxf(mx, __shfl_xor_sync(0xffffffffu, mx, off));
    float p0 = __expf(s0 - mx), p1 = __expf(s1 - mx);
    float sum = p0 + p1;
#pragma unroll
    for (int off = 16; off > 0; off >>= 1)
        sum += __shfl_xor_sync(0xffffffffu, sum, off);
    float rs = 1.f / sum;

    float2 acc = make_float2(0.f, 0.f);
    for (int n = 0; n < 64; n++) {
        float pn = __shfl_sync(0xffffffffu, n < 32 ? p0 : p1, n & 31);
        float2 v2 = *(const float2*)(g_cv + (b * 64 + n) * ND + h * 64 + lane * 2);
        acc.x += pn * v2.x; acc.y += pn * v2.y;
    }
    acc.x *= rs; acc.y *= rs;
    *(float2*)(g_oc + bs * ND + h * 64 + lane * 2) = acc;
}

// ---------------- selected attention -------------------------------------------------
__global__ __launch_bounds__(512) void sel_attn_kernel()
{
    const int bs = blockIdx.x;
    const int b  = bs >> 10, s = bs & 1023;
    const int tid = threadIdx.x;
    const int h = tid >> 5, lane = tid & 31;

    __shared__ int blk_s[2];
    if (tid < 2) blk_s[tid] = g_top[(tid * NS + s) * 2 + b];
    __syncthreads();

    const float2 q2 = *(const float2*)(g_q + bs * ND + h * 64 + lane * 2);

    float myscore = NEG;
#pragma unroll
    for (int m = 0; m < 16; m++) {
        int j = m >> 3, t = m & 7;
        int tok = blk_s[j] * NCB + t;
        float2 k2 = *(const float2*)(g_k + (j * NS + tok) * ND + h * 64 + lane * 2);
        float p = q2.x * k2.x + q2.y * k2.y;
#pragma unroll
        for (int off = 16; off > 0; off >>= 1)
            p += __shfl_xor_sync(0xffffffffu, p, off);
        p *= INVS;
        if (lane == m) myscore = p;
    }
    float mx = myscore;
#pragma unroll
    for (int off = 16; off > 0; off >>= 1)
        mx = fmaxf(mx, __shfl_xor_sync(0xffffffffu, mx, off));
    float p = __expf(myscore - mx);
    float sum = p;
#pragma unroll
    for (int off = 16; off > 0; off >>= 1)
        sum += __shfl_xor_sync(0xffffffffu, sum, off);
    float rs = 1.f / sum;

    float2 acc = make_float2(0.f, 0.f);
#pragma unroll
    for (int m = 0; m < 16; m++) {
        float pm = __shfl_sync(0xffffffffu, p, m);
        int j = m >> 3, t = m & 7;
        int tok = blk_s[j] * NCB + t;
        float2 v2 = *(const float2*)(g_v + (j * NS + tok) * ND + h * 64 + lane * 2);
        acc.x += pm * v2.x; acc.y += pm * v2.y;
    }
    acc.x *= rs; acc.y *= rs;
    *(float2*)(g_os + bs * ND + h * 64 + lane * 2) = acc;
}

// ---------------- sliding-window attention -------------------------------------------
__global__ __launch_bounds__(512) void win_attn_kernel()
{
    const int qt = blockIdx.x, h = blockIdx.y, b = blockIdx.z;
    const int tid = threadIdx.x;
    const int w = tid >> 5, lane = tid & 31;

    __shared__ float q_s[64 * 64];
    __shared__ float kT [64 * 64];
    __shared__ float v_s[64 * 64];

    const int qbase = qt * 64;

    for (int i = tid; i < 4096; i += 512) {
        int r = i >> 6, d = i & 63;
        q_s[i] = g_q[(b * NS + qbase + r) * ND + h * 64 + d];
    }

    float2 acc[4];
    float mrow[4], lrow[4];
#pragma unroll
    for (int i = 0; i < 4; i++) {
        acc[i] = make_float2(0.f, 0.f);
        mrow[i] = NEG; lrow[i] = 0.f;
    }

    const int kt_lo = (qt >= 4) ? qt - 4 : 0;
    for (int kt = kt_lo; kt <= qt; kt++) {
        const int kbase = kt * 64;
        __syncthreads();
        for (int i = tid; i < 4096; i += 512) {
            int c = i >> 6, d = i & 63;
            const int g = (b * NS + kbase + c) * ND + h * 64 + d;
            kT [d * 64 + (c ^ (d & 31))] = g_k[g];
            v_s[i] = g_v[g];
        }
        __syncthreads();

#pragma unroll
        for (int i = 0; i < 4; i++) {
            const int r  = w * 4 + i;
            const int qi = qbase + r;
            const float* qrow = q_s + r * 64;
            float sc0 = 0.f, sc1 = 0.f;
#pragma unroll 16
            for (int d = 0; d < 64; d++) {
                float qv = qrow[d];
                sc0 += qv * kT[d * 64 + ( lane       ^ (d & 31))];
                sc1 += qv * kT[d * 64 + ((lane + 32) ^ (d & 31))];
            }
            const int j0 = kbase + lane, j1 = kbase + lane + 32;
            sc0 = (j0 <= qi && qi - j0 <= NWIN) ? sc0 * INVS : NEG;
            sc1 = (j1 <= qi && qi - j1 <= NWIN) ? sc1 * INVS : NEG;

            float mnew = fmaxf(sc0, sc1);
#pragma unroll
            for (int off = 16; off > 0; off >>= 1)
                mnew = fmaxf(mnew, __shfl_xor_sync(0xffffffffu, mnew, off));
            mnew = fmaxf(mnew, mrow[i]);
            float scale = __expf(mrow[i] - mnew);
            float p0 = __expf(sc0 - mnew), p1 = __expf(sc1 - mnew);
            float ps = p0 + p1;
#pragma unroll
            for (int off = 16; off > 0; off >>= 1)
                ps += __shfl_xor_sync(0xffffffffu, ps, off);
            lrow[i] = lrow[i] * scale + ps;
            mrow[i] = mnew;

            float ax = acc[i].x * scale, ay = acc[i].y * scale;
#pragma unroll 16
            for (int c = 0; c < 64; c++) {
                float pc = __shfl_sync(0xffffffffu, c < 32 ? p0 : p1, c & 31);
                float2 v2 = *(const float2*)&v_s[c * 64 + lane * 2];
                ax += pc * v2.x; ay += pc * v2.y;
            }
            acc[i].x = ax; acc[i].y = ay;
        }
    }

#pragma unroll
    for (int i = 0; i < 4; i++) {
        const int r = w * 4 + i;
        const float rl = 1.f / lrow[i];
        float2 o = make_float2(acc[i].x * rl, acc[i].y * rl);
        *(float2*)(g_ow + (b * NS + qbase + r) * ND + h * 64 + lane * 2) = o;
    }
}

// ---------------- gates + combine ----------------------------------------------------
__global__ __launch_bounds__(256) void gate_combine_kernel(
    const float* __restrict__ x, const float* __restrict__ Wg,
    const float* __restrict__ bg)
{
    const int bs = blockIdx.x;
    const int tid = threadIdx.x;
    __shared__ float red[3][256];
    __shared__ float gsh[3];

    const float* xr = x + bs * ND;
    float a0 = 0.f, a1 = 0.f, a2 = 0.f;
    for (int d = tid; d < ND; d += 256) {
        float xv = xr[d];
        a0 += xv * Wg[d * 3 + 0];
        a1 += xv * Wg[d * 3 + 1];
        a2 += xv * Wg[d * 3 + 2];
    }
    red[0][tid] = a0; red[1][tid] = a1; red[2][tid] = a2;
    __syncthreads();
    for (int sft = 128; sft > 0; sft >>= 1) {
        if (tid < sft) {
            red[0][tid] += red[0][tid + sft];
            red[1][tid] += red[1][tid + sft];
            red[2][tid] += red[2][tid + sft];
        }
        __syncthreads();
    }
    if (tid < 3) gsh[tid] = 1.f / (1.f + __expf(-(red[tid][0] + bg[tid])));
    __syncthreads();
    const float g0 = gsh[0], g1 = gsh[1], g2 = gsh[2];
    const int base = bs * ND;
    for (int d = tid; d < ND; d += 256)
        g_pre[base + d] = g0 * g_oc[base + d] + g1 * g_os[base + d] + g2 * g_ow[base + d];
}

// ---------------- launcher ------------------------------------------------------------
extern "C" void kernel_launch(void* const* d_in, const int* in_sizes, int n_in,
                              void* d_out, int out_size)
{
    (void)in_sizes; (void)n_in; (void)out_size;
    const float* x   = (const float*)d_in[0];
    const float* Wq  = (const float*)d_in[1];
    const float* Wk  = (const float*)d_in[2];
    const float* Wv  = (const float*)d_in[3];
    const float* Wo  = (const float*)d_in[4];
    const float* bo  = (const float*)d_in[5];
    const float* Wg  = (const float*)d_in[6];
    const float* bg  = (const float*)d_in[7];
    const float* wkc = (const float*)d_in[8];
    const float* wvc = (const float*)d_in[9];
    const float* wpe = (const float*)d_in[10];
    float* out = (float*)d_out;

    void *pq, *pk, *pv, *ppre, *pah, *pal, *pwh, *pwl;
    void *pxkc, *pxvc, *pck, *pcv, *ptt, *pimp, *ppec, *ppvc;
    cudaGetSymbolAddress(&pq,   g_q);
    cudaGetSymbolAddress(&pk,   g_k);
    cudaGetSymbolAddress(&pv,   g_v);
    cudaGetSymbolAddress(&ppre, g_pre);
    cudaGetSymbolAddress(&pah,  g_ah);
    cudaGetSymbolAddress(&pal,  g_al);
    cudaGetSymbolAddress(&pwh,  g_wh);
    cudaGetSymbolAddress(&pwl,  g_wl);
    cudaGetSymbolAddress(&pxkc, g_xkc);
    cudaGetSymbolAddress(&pxvc, g_xvc);
    cudaGetSymbolAddress(&pck,  g_ck);
    cudaGetSymbolAddress(&pcv,  g_cv);
    cudaGetSymbolAddress(&ptt,  g_tt);
    cudaGetSymbolAddress(&pimp, g_imp);
    cudaGetSymbolAddress(&ppec, g_pec);
    cudaGetSymbolAddress(&ppvc, g_pvc);

    const __nv_bfloat16* ah = (const __nv_bfloat16*)pah;
    const __nv_bfloat16* alo = (const __nv_bfloat16*)pal;
    const __nv_bfloat16* wh = (const __nv_bfloat16*)pwh;
    const __nv_bfloat16* wl = (const __nv_bfloat16*)pwl;

    const dim3 ggrid(ND / BN, (NB * NS) / BM);     // (8, 16)
    const dim3 wgrid(32, 32);
    const int NEL = NB * NS * ND;

    // ---- split x ----
    split_kernel<<<NEL / 256, 256>>>(x, (__nv_bfloat16*)pah, (__nv_bfloat16*)pal);

    // ---- q = x@Wq (3-launch split) ----
    convert_w_kernel<<<wgrid, 256>>>(Wq, (__nv_bfloat16*)pwh, (__nv_bfloat16*)pwl);
    mma_gemm_kernel<<<ggrid, 256>>>(ah,  wh, (float*)pq, 0, nullptr);
    mma_gemm_kernel<<<ggrid, 256>>>(ah,  wl, (float*)pq, 3, nullptr);
    mma_gemm_kernel<<<ggrid, 256>>>(alo, wh, (float*)pq, 3, nullptr);

    // ---- k = x@Wk + pe ----
    convert_w_kernel<<<wgrid, 256>>>(Wk, (__nv_bfloat16*)pwh, (__nv_bfloat16*)pwl);
    mma_gemm_kernel<<<ggrid, 256>>>(ah,  wh, (float*)pk, 1, wpe);
    mma_gemm_kernel<<<ggrid, 256>>>(ah,  wl, (float*)pk, 3, nullptr);
    mma_gemm_kernel<<<ggrid, 256>>>(alo, wh, (float*)pk, 3, nullptr);

    // ---- v = x@Wv + pe ----
    convert_w_kernel<<<wgrid, 256>>>(Wv, (__nv_bfloat16*)pwh, (__nv_bfloat16*)pwl);
    mma_gemm_kernel<<<ggrid, 256>>>(ah,  wh, (float*)pv, 1, wpe);
    mma_gemm_kernel<<<ggrid, 256>>>(ah,  wl, (float*)pv, 3, nullptr);
    mma_gemm_kernel<<<ggrid, 256>>>(alo, wh, (float*)pv, 3, nullptr);

    // ---- exact fp32 ck/cv:  ck = (wkc . x_blocks) @ Wk + (wkc . pe) ----
    xc_kernel<<<(NB * NNC * ND) / 256, 256>>>(x, wkc, wvc);
    pe_comb_kernel<<<ND / 256, 256>>>(wpe, wkc, wvc);
    sgemm_kernel<<<dim3(16, 1), 256>>>((const float*)pxkc, Wk, (float*)pck,
                                       128, 1024, 1024, 2, (const float*)ppec);
    sgemm_kernel<<<dim3(16, 1), 256>>>((const float*)pxvc, Wv, (float*)pcv,
                                       128, 1024, 1024, 2, (const float*)ppvc);

    // ---- exact fp32 imp via associativity: Tt[b] = ck[b]@Wq^T ; imp[b] = x[b]@Tt[b]^T
    nt_gemm_kernel<<<dim3(16, 1, 2), 256>>>((const float*)pck, Wq, (float*)ptt,
                                            1024, 64L * 1024, 0L, 64L * 1024);
    nt_gemm_kernel<<<dim3(1, 16, 2), 256>>>(x, (const float*)ptt, (float*)pimp,
                                            64, 1024L * 1024, 64L * 1024, 1024L * 64);
    top2_kernel<<<(NB * NS) / 8, 256>>>();

    // ---- attention branches ----
    comp_attn_kernel<<<NB * NS, 512>>>();
    sel_attn_kernel<<<NB * NS, 512>>>();
    win_attn_kernel<<<dim3(NS / 64, NH, NB), 512>>>();
    gate_combine_kernel<<<NB * NS, 256>>>(x, Wg, bg);

    // ---- out = pre@Wo + bo ----
    split_kernel<<<NEL / 256, 256>>>((const float*)ppre, (__nv_bfloat16*)pah,
                                     (__nv_bfloat16*)pal);
    convert_w_kernel<<<wgrid, 256>>>(Wo, (__nv_bfloat16*)pwh, (__nv_bfloat16*)pwl);
    mma_gemm_kernel<<<ggrid, 256>>>(ah,  wh, out, 2, bo);
    mma_gemm_kernel<<<ggrid, 256>>>(ah,  wl, out, 3, nullptr);
    mma_gemm_kernel<<<ggrid, 256>>>(alo, wh, out, 3, nullptr);
}

// round 6
// speedup vs baseline: 1.1684x; 1.1684x over previous
#include <cuda_runtime.h>
#include <cuda_bf16.h>
#include <cstdint>

#define NB   2
#define NS   1024
#define ND   1024
#define NH   16
#define NHD  64
#define NNC  64
#define NCB  16
#define NSB  8
#define NJ   2
#define NWIN 256

#define INVS 0.125f
#define NEG  (-1e30f)

#define KA   1024
#define BM   128
#define BN   128
#define BK   32
#define AST  40
#define NIT3 96                   // 3 terms x 32 k-iters

// ---------------- scratch (device globals; no allocation allowed) ----------------
__device__ __align__(16) float g_q [NB*NS*ND];
__device__ __align__(16) float g_k [NB*NS*ND];
__device__ __align__(16) float g_v [NB*NS*ND];
__device__ __align__(16) float g_ck[NB*NNC*ND];
__device__ __align__(16) float g_cv[NB*NNC*ND];
__device__ __align__(16) float g_oc[NB*NS*ND];
__device__ __align__(16) float g_os[NB*NS*ND];
__device__ __align__(16) float g_ow[NB*NS*ND];
__device__ __align__(16) float g_pre[NB*NS*ND];
__device__ int   g_top[NB*NS*NJ];
__device__ __align__(16) float g_gates[NB*NS*3];
__device__ __align__(16) __nv_bfloat16 g_ah[(size_t)NB*NS*ND];    // A hi [2048,1024]
__device__ __align__(16) __nv_bfloat16 g_al[(size_t)NB*NS*ND];    // A lo
__device__ __align__(16) __nv_bfloat16 g_wh[(size_t)3*ND*ND];     // packed Wq|Wk|Wv ^T hi
__device__ __align__(16) __nv_bfloat16 g_wl[(size_t)3*ND*ND];     // packed lo
__device__ __align__(16) __nv_bfloat16 g_woh[(size_t)ND*ND];      // Wo^T hi
__device__ __align__(16) __nv_bfloat16 g_wol[(size_t)ND*ND];      // Wo^T lo
__device__ __align__(16) float g_xkc[NB*NNC*ND];
__device__ __align__(16) float g_xvc[NB*NNC*ND];
__device__ __align__(16) float g_pec[ND];
__device__ __align__(16) float g_pvc[ND];
__device__ __align__(16) float g_tt [NB*NNC*ND];
__device__ __align__(16) float g_imp[NB*NS*NNC];

// ======================= PTX helpers ================================================
__device__ __forceinline__ void cp16(uint32_t d, const void* s) {
    asm volatile("cp.async.cg.shared.global [%0], [%1], 16;" :: "r"(d), "l"(s));
}
__device__ __forceinline__ void cp_commit() {
    asm volatile("cp.async.commit_group;");
}
__device__ __forceinline__ void cp_wait1() {
    asm volatile("cp.async.wait_group 1;");
}
__device__ __forceinline__ void ldsm_x4(uint32_t& r0, uint32_t& r1, uint32_t& r2, uint32_t& r3,
                                        uint32_t addr) {
    asm volatile("ldmatrix.sync.aligned.m8n8.x4.shared.b16 {%0,%1,%2,%3}, [%4];"
        : "=r"(r0), "=r"(r1), "=r"(r2), "=r"(r3) : "r"(addr));
}
__device__ __forceinline__ void mma16816(float* c, const uint32_t* a, const uint32_t* b) {
    asm volatile("mma.sync.aligned.m16n8k16.row.col.f32.bf16.bf16.f32 "
        "{%0,%1,%2,%3}, {%4,%5,%6,%7}, {%8,%9}, {%0,%1,%2,%3};"
        : "+f"(c[0]), "+f"(c[1]), "+f"(c[2]), "+f"(c[3])
        : "r"(a[0]), "r"(a[1]), "r"(a[2]), "r"(a[3]), "r"(b[0]), "r"(b[1]));
}

// ======================= split conversions =========================================
__global__ __launch_bounds__(256) void split_kernel(
    const float* __restrict__ src, __nv_bfloat16* __restrict__ hi,
    __nv_bfloat16* __restrict__ lo)
{
    int idx = blockIdx.x * 256 + threadIdx.x;
    float v = src[idx];
    __nv_bfloat16 h = __float2bfloat16(v);
    hi[idx] = h;
    lo[idx] = __float2bfloat16(v - __bfloat162float(h));
}

// W[k][n] -> Wh/Wl [row_off + n][k]
__global__ __launch_bounds__(256) void convert_w_kernel(
    const float* __restrict__ W, __nv_bfloat16* __restrict__ Wh,
    __nv_bfloat16* __restrict__ Wl, int row_off)
{
    __shared__ float t[32][33];
    int n0 = blockIdx.x * 32, k0 = blockIdx.y * 32;
    int tx = threadIdx.x & 31, ty = threadIdx.x >> 5;
#pragma unroll
    for (int i = 0; i < 32; i += 8)
        t[ty + i][tx] = W[(k0 + ty + i) * 1024 + n0 + tx];
    __syncthreads();
#pragma unroll
    for (int i = 0; i < 32; i += 8) {
        int n = row_off + n0 + ty + i, k = k0 + tx;
        float v = t[tx][ty + i];
        __nv_bfloat16 h = __float2bfloat16(v);
        Wh[(size_t)n * 1024 + k] = h;
        Wl[(size_t)n * 1024 + k] = __float2bfloat16(v - __bfloat162float(h));
    }
}

// ======================= fused 3-term HMMA GEMM =====================================
// acc = Ah@Wh^T + Ah@Wl^T + Al@Wh^T  (96 pipelined k-iters, one epilogue)
// qkv_mode=1: N=3072 grid; col segment 0->Cq, 1->Ck(+pe), 2->Cv(+pe)
// qkv_mode=0: single dest Cq, += bias extra[col]
__global__ __launch_bounds__(256) void mma_gemm3_kernel(
    const __nv_bfloat16* __restrict__ Ah, const __nv_bfloat16* __restrict__ Al,
    const __nv_bfloat16* __restrict__ Wh, const __nv_bfloat16* __restrict__ Wl,
    float* __restrict__ Cq, float* __restrict__ Ck, float* __restrict__ Cv,
    const float* __restrict__ extra, int qkv_mode)
{
    __shared__ __nv_bfloat16 sA[2][BM * AST];
    __shared__ __nv_bfloat16 sB[2][BN * AST];

    const int tid = threadIdx.x;
    const int wid = tid >> 5, lane = tid & 31;
    const int wm = wid >> 2, wn = wid & 3;
    const int mt = blockIdx.y * BM, nt = blockIdx.x * BN;

    const uint32_t sAb = (uint32_t)__cvta_generic_to_shared(&sA[0][0]);
    const uint32_t sBb = (uint32_t)__cvta_generic_to_shared(&sB[0][0]);
    const uint32_t STG_A = BM * AST * 2;
    const uint32_t STG_B = BN * AST * 2;

    const int lrow = tid >> 1;
    const int lc   = (tid & 1) * 2;
    const size_t aoff = (size_t)(mt + lrow) * KA + lc * 8;
    const size_t boff = (size_t)(nt + lrow) * KA + lc * 8;
    const __nv_bfloat16* aSrc[2] = {Ah + aoff, Al + aoff};
    const __nv_bfloat16* bSrc[2] = {Wh + boff, Wl + boff};
    const uint32_t dA = sAb + (lrow * AST + lc * 8) * 2;
    const uint32_t dB = sBb + (lrow * AST + lc * 8) * 2;

    float c[4][4][4];
#pragma unroll
    for (int i = 0; i < 4; i++)
#pragma unroll
        for (int j = 0; j < 4; j++)
#pragma unroll
            for (int r = 0; r < 4; r++) c[i][j][r] = 0.f;

    const int al  = lane & 15;
    const int ahi = lane >> 4;

    // prologue: term 0 (Ah,Wh), k-block 0
    cp16(dA, aSrc[0]);        cp16(dA + 16, aSrc[0] + 8);
    cp16(dB, bSrc[0]);        cp16(dB + 16, bSrc[0] + 8);
    cp_commit();

    int buf = 0;
    for (int it = 0; it < NIT3; it++) {
        if (it + 1 < NIT3) {
            const int t  = (it + 1) >> 5;          // 0,1,2
            const int k0 = ((it + 1) & 31) * BK;
            const __nv_bfloat16* ga = aSrc[t == 2 ? 1 : 0] + k0;
            const __nv_bfloat16* gb = bSrc[t == 1 ? 1 : 0] + k0;
            cp16(dA + (buf ^ 1) * STG_A,      ga);
            cp16(dA + (buf ^ 1) * STG_A + 16, ga + 8);
            cp16(dB + (buf ^ 1) * STG_B,      gb);
            cp16(dB + (buf ^ 1) * STG_B + 16, gb + 8);
        }
        cp_commit();
        cp_wait1();
        __syncthreads();

#pragma unroll
        for (int ks = 0; ks < 2; ks++) {
            const int kg = ks * 2 + ahi;
            uint32_t a[4][4], b[4][2];
#pragma unroll
            for (int i = 0; i < 4; i++) {
                uint32_t ad = sAb + buf * STG_A +
                              ((wm * 64 + i * 16 + al) * AST + kg * 8) * 2;
                ldsm_x4(a[i][0], a[i][1], a[i][2], a[i][3], ad);
            }
#pragma unroll
            for (int jj = 0; jj < 2; jj++) {
                uint32_t bd = sBb + buf * STG_B +
                              ((wn * 32 + jj * 16 + al) * AST + kg * 8) * 2;
                uint32_t r0, r1, r2, r3;
                ldsm_x4(r0, r1, r2, r3, bd);
                b[jj * 2 + 0][0] = r0; b[jj * 2 + 1][0] = r1;
                b[jj * 2 + 0][1] = r2; b[jj * 2 + 1][1] = r3;
            }
#pragma unroll
            for (int i = 0; i < 4; i++)
#pragma unroll
                for (int j = 0; j < 4; j++) mma16816(c[i][j], a[i], b[j]);
        }
        __syncthreads();
        buf ^= 1;
    }

    // epilogue
    float* dst;
    bool add_pe = false;
    int ncol0;
    if (qkv_mode) {
        const int seg = nt >> 10;
        dst = (seg == 0) ? Cq : (seg == 1 ? Ck : Cv);
        add_pe = (seg != 0);
        ncol0 = nt & 1023;
    } else {
        dst = Cq;
        ncol0 = nt;
    }

    const int mbase = mt + wm * 64;
    const int nbase = ncol0 + wn * 32;
    const int rr = lane >> 2, cc = (lane & 3) * 2;
#pragma unroll
    for (int i = 0; i < 4; i++) {
#pragma unroll
        for (int j = 0; j < 4; j++) {
            int row = mbase + i * 16 + rr;
            int col = nbase + j * 8 + cc;
            float2 v0 = make_float2(c[i][j][0], c[i][j][1]);
            float2 v1 = make_float2(c[i][j][2], c[i][j][3]);
            if (qkv_mode) {
                if (add_pe) {
                    const float* p0 = extra + (row & 15) * 1024 + col;
                    const float* p1 = extra + ((row + 8) & 15) * 1024 + col;
                    v0.x += p0[0]; v0.y += p0[1];
                    v1.x += p1[0]; v1.y += p1[1];
                }
            } else {
                v0.x += extra[col]; v0.y += extra[col + 1];
                v1.x += extra[col]; v1.y += extra[col + 1];
            }
            *(float2*)(dst + (size_t)row * 1024 + col)       = v0;
            *(float2*)(dst + (size_t)(row + 8) * 1024 + col) = v1;
        }
    }
}

// ======================= fp32 SGEMM (exact ck/cv; z selects k/v path) ===============
__global__ __launch_bounds__(256) void csgemm_kernel(
    const float* __restrict__ Ak, const float* __restrict__ Av,
    const float* __restrict__ Wk, const float* __restrict__ Wv,
    float* __restrict__ Ck, float* __restrict__ Cv,
    const float* __restrict__ bk, const float* __restrict__ bv)
{
    const int z = blockIdx.z;
    const float* A    = z ? Av : Ak;
    const float* Bm   = z ? Wv : Wk;
    float* C          = z ? Cv : Ck;
    const float* bias = z ? bv : bk;

    __shared__ float As[16][132];
    __shared__ float Bs[16][64];

    const int tid = threadIdx.x;
    const int bn  = blockIdx.x * 64;
    const int tx  = tid & 15;
    const int ty  = tid >> 4;

    const int arow = tid >> 1;
    const int acol = (tid & 1) * 8;
    const int brow = tid >> 4;
    const int bcol = (tid & 15) * 4;

    float acc[8][4];
#pragma unroll
    for (int i = 0; i < 8; i++)
#pragma unroll
        for (int j = 0; j < 4; j++) acc[i][j] = 0.f;

    for (int k0 = 0; k0 < 1024; k0 += 16) {
        float4 a0 = *(const float4*)(A + arow * 1024 + k0 + acol);
        float4 a1 = *(const float4*)(A + arow * 1024 + k0 + acol + 4);
        As[acol+0][arow] = a0.x; As[acol+1][arow] = a0.y;
        As[acol+2][arow] = a0.z; As[acol+3][arow] = a0.w;
        As[acol+4][arow] = a1.x; As[acol+5][arow] = a1.y;
        As[acol+6][arow] = a1.z; As[acol+7][arow] = a1.w;
        float4 b4 = *(const float4*)(Bm + (k0 + brow) * 1024 + bn + bcol);
        *(float4*)&Bs[brow][bcol] = b4;
        __syncthreads();

#pragma unroll
        for (int kk = 0; kk < 16; kk++) {
            float4 t0 = *(const float4*)&As[kk][ty * 8];
            float4 t1 = *(const float4*)&As[kk][ty * 8 + 4];
            float4 bb = *(const float4*)&Bs[kk][tx * 4];
            float ar[8] = {t0.x, t0.y, t0.z, t0.w, t1.x, t1.y, t1.z, t1.w};
            float br[4] = {bb.x, bb.y, bb.z, bb.w};
#pragma unroll
            for (int i = 0; i < 8; i++)
#pragma unroll
                for (int j = 0; j < 4; j++) acc[i][j] += ar[i] * br[j];
        }
        __syncthreads();
    }

#pragma unroll
    for (int i = 0; i < 8; i++) {
        int m = ty * 8 + i;
#pragma unroll
        for (int j = 0; j < 4; j++) {
            int n = bn + tx * 4 + j;
            C[m * 1024 + n] = acc[i][j] + bias[n];
        }
    }
}

// ======================= fp32 NT GEMM: C[i,j] = sum_k A[i,k]*B[j,k], K=1024 =========
__global__ __launch_bounds__(256) void nt_gemm_kernel(
    const float* __restrict__ A, const float* __restrict__ B, float* __restrict__ C,
    int N, long aB, long bB, long cB)
{
    const float* Ab = A + (size_t)blockIdx.z * aB;
    const float* Bb = B + (size_t)blockIdx.z * bB;
    float* Cb = C + (size_t)blockIdx.z * cB;

    __shared__ float As[64][33];
    __shared__ float Bs[64][33];

    const int tid = threadIdx.x;
    const int row = tid >> 2;
    const int c4  = (tid & 3) * 8;
    const int ty = tid >> 4, tx = tid & 15;
    const int i0 = blockIdx.y * 64, j0 = blockIdx.x * 64;

    float acc[4][4];
#pragma unroll
    for (int i = 0; i < 4; i++)
#pragma unroll
        for (int j = 0; j < 4; j++) acc[i][j] = 0.f;

    for (int k0 = 0; k0 < 1024; k0 += 32) {
        float4 a0 = *(const float4*)(Ab + (size_t)(i0 + row) * 1024 + k0 + c4);
        float4 a1 = *(const float4*)(Ab + (size_t)(i0 + row) * 1024 + k0 + c4 + 4);
        As[row][c4+0] = a0.x; As[row][c4+1] = a0.y;
        As[row][c4+2] = a0.z; As[row][c4+3] = a0.w;
        As[row][c4+4] = a1.x; As[row][c4+5] = a1.y;
        As[row][c4+6] = a1.z; As[row][c4+7] = a1.w;
        float4 b0 = *(const float4*)(Bb + (size_t)(j0 + row) * 1024 + k0 + c4);
        float4 b1 = *(const float4*)(Bb + (size_t)(j0 + row) * 1024 + k0 + c4 + 4);
        Bs[row][c4+0] = b0.x; Bs[row][c4+1] = b0.y;
        Bs[row][c4+2] = b0.z; Bs[row][c4+3] = b0.w;
        Bs[row][c4+4] = b1.x; Bs[row][c4+5] = b1.y;
        Bs[row][c4+6] = b1.z; Bs[row][c4+7] = b1.w;
        __syncthreads();

#pragma unroll 8
        for (int k = 0; k < 32; k++) {
            float ar[4], br[4];
#pragma unroll
            for (int i = 0; i < 4; i++) ar[i] = As[ty * 4 + i][k];
#pragma unroll
            for (int j = 0; j < 4; j++) br[j] = Bs[tx * 4 + j][k];
#pragma unroll
            for (int i = 0; i < 4; i++)
#pragma unroll
                for (int j = 0; j < 4; j++) acc[i][j] += ar[i] * br[j];
        }
        __syncthreads();
    }

#pragma unroll
    for (int i = 0; i < 4; i++)
#pragma unroll
        for (int j = 0; j < 4; j++)
            Cb[(size_t)(i0 + ty * 4 + i) * N + j0 + tx * 4 + j] = acc[i][j];
}

// ---------------- exact compressed-row inputs ---------------------------------------
__global__ __launch_bounds__(256) void xc_kernel(
    const float* __restrict__ x, const float* __restrict__ wkc,
    const float* __restrict__ wvc)
{
    int idx = blockIdx.x * 256 + threadIdx.x;
    int d = idx & 1023;
    int n = (idx >> 10) & 63;
    int b = idx >> 16;
    const float* xb = x + ((size_t)(b * NS + n * NCB)) * ND + d;
    float sk = 0.f, sv = 0.f;
#pragma unroll
    for (int t = 0; t < NCB; t++) {
        float xv = xb[t * ND];
        sk += wkc[t] * xv;
        sv += wvc[t] * xv;
    }
    g_xkc[idx] = sk;
    g_xvc[idx] = sv;
}

__global__ __launch_bounds__(256) void pe_comb_kernel(
    const float* __restrict__ wpe, const float* __restrict__ wkc,
    const float* __restrict__ wvc)
{
    int d = blockIdx.x * 256 + threadIdx.x;
    float sk = 0.f, sv = 0.f;
#pragma unroll
    for (int t = 0; t < NCB; t++) {
        float p = wpe[t * ND + d];
        sk += wkc[t] * p;
        sv += wvc[t] * p;
    }
    g_pec[d] = sk;
    g_pvc[d] = sv;
}

// ---------------- top-2 ---------------------------------------------------------------
__global__ __launch_bounds__(256) void top2_kernel()
{
    const int bs = blockIdx.x * 8 + (threadIdx.x >> 5);
    const int lane = threadIdx.x & 31;
    const float* row = g_imp + (size_t)bs * 64;
    float v0 = row[lane], v1 = row[lane + 32];

    float bv; int bi;
    if (v0 >= v1) { bv = v0; bi = lane; } else { bv = v1; bi = lane + 32; }
#pragma unroll
    for (int off = 16; off > 0; off >>= 1) {
        float ov = __shfl_xor_sync(0xffffffffu, bv, off);
        int   oi = __shfl_xor_sync(0xffffffffu, bi, off);
        if (ov > bv || (ov == bv && oi < bi)) { bv = ov; bi = oi; }
    }
    int top1 = bi;
    float w0 = (lane == top1)      ? NEG : v0;
    float w1 = (lane + 32 == top1) ? NEG : v1;
    float bv2; int bi2;
    if (w0 >= w1) { bv2 = w0; bi2 = lane; } else { bv2 = w1; bi2 = lane + 32; }
#pragma unroll
    for (int off = 16; off > 0; off >>= 1) {
        float ov = __shfl_xor_sync(0xffffffffu, bv2, off);
        int   oi = __shfl_xor_sync(0xffffffffu, bi2, off);
        if (ov > bv2 || (ov == bv2 && oi < bi2)) { bv2 = ov; bi2 = oi; }
    }
    if (lane == 0) { g_top[bs * 2] = top1; g_top[bs * 2 + 1] = bi2; }
}

// ---------------- compressed attention, 64x64 tile style ------------------------------
// grid (16 s-tiles, 16 heads, 2 batch), 512 threads; single k-tile of all 64 blocks.
__global__ __launch_bounds__(512) void comp_attn_tile_kernel()
{
    const int st = blockIdx.x, h = blockIdx.y, b = blockIdx.z;
    const int tid = threadIdx.x;
    const int w = tid >> 5, lane = tid & 31;

    __shared__ float q_s[64 * 64];
    __shared__ float kT [64 * 64];   // [d][n], xor-swizzled
    __shared__ float v_s[64 * 64];   // [n][d]

    const int qbase = st * 64;

    for (int i = tid; i < 4096; i += 512) {
        int r = i >> 6, d = i & 63;
        q_s[i] = g_q[((size_t)(b * NS + qbase + r)) * ND + h * 64 + d];
        int n = r;
        const size_t gc = ((size_t)(b * 64 + n)) * ND + h * 64 + d;
        kT [d * 64 + (n ^ (d & 31))] = g_ck[gc];
        v_s[i] = g_cv[gc];
    }
    __syncthreads();

#pragma unroll
    for (int i = 0; i < 4; i++) {
        const int r = w * 4 + i;
        const float* qrow = q_s + r * 64;
        float sc0 = 0.f, sc1 = 0.f;
#pragma unroll 16
        for (int d = 0; d < 64; d++) {
            float qv = qrow[d];
            sc0 += qv * kT[d * 64 + ( lane       ^ (d & 31))];
            sc1 += qv * kT[d * 64 + ((lane + 32) ^ (d & 31))];
        }
        sc0 *= INVS; sc1 *= INVS;

        float mx = fmaxf(sc0, sc1);
#pragma unroll
        for (int off = 16; off > 0; off >>= 1)
            mx = fmaxf(mx, __shfl_xor_sync(0xffffffffu, mx, off));
        float p0 = __expf(sc0 - mx), p1 = __expf(sc1 - mx);
        float ps = p0 + p1;
#pragma unroll
        for (int off = 16; off > 0; off >>= 1)
            ps += __shfl_xor_sync(0xffffffffu, ps, off);
        const float rs = 1.f / ps;

        float ax = 0.f, ay = 0.f;
#pragma unroll 16
        for (int n = 0; n < 64; n++) {
            float pn = __shfl_sync(0xffffffffu, n < 32 ? p0 : p1, n & 31);
            float2 v2 = *(const float2*)&v_s[n * 64 + lane * 2];
            ax += pn * v2.x; ay += pn * v2.y;
        }
        float2 o = make_float2(ax * rs, ay * rs);
        *(float2*)(g_oc + ((size_t)(b * NS + qbase + r)) * ND + h * 64 + lane * 2) = o;
    }
}

// ---------------- selected attention ---------------------------------------------------
__global__ __launch_bounds__(512) void sel_attn_kernel()
{
    const int bs = blockIdx.x;
    const int b  = bs >> 10, s = bs & 1023;
    const int tid = threadIdx.x;
    const int h = tid >> 5, lane = tid & 31;

    __shared__ int blk_s[2];
    if (tid < 2) blk_s[tid] = g_top[(tid * NS + s) * 2 + b];
    __syncthreads();

    const float2 q2 = *(const float2*)(g_q + bs * ND + h * 64 + lane * 2);

    float myscore = NEG;
#pragma unroll
    for (int m = 0; m < 16; m++) {
        int j = m >> 3, t = m & 7;
        int tok = blk_s[j] * NCB + t;
        float2 k2 = *(const float2*)(g_k + (j * NS + tok) * ND + h * 64 + lane * 2);
        float p = q2.x * k2.x + q2.y * k2.y;
#pragma unroll
        for (int off = 16; off > 0; off >>= 1)
            p += __shfl_xor_sync(0xffffffffu, p, off);
        p *= INVS;
        if (lane == m) myscore = p;
    }
    float mx = myscore;
#pragma unroll
    for (int off = 16; off > 0; off >>= 1)
        mx = fmaxf(mx, __shfl_xor_sync(0xffffffffu, mx, off));
    float p = __expf(myscore - mx);
    float sum = p;
#pragma unroll
    for (int off = 16; off > 0; off >>= 1)
        sum += __shfl_xor_sync(0xffffffffu, sum, off);
    float rs = 1.f / sum;

    float2 acc = make_float2(0.f, 0.f);
#pragma unroll
    for (int m = 0; m < 16; m++) {
        float pm = __shfl_sync(0xffffffffu, p, m);
        int j = m >> 3, t = m & 7;
        int tok = blk_s[j] * NCB + t;
        float2 v2 = *(const float2*)(g_v + (j * NS + tok) * ND + h * 64 + lane * 2);
        acc.x += pm * v2.x; acc.y += pm * v2.y;
    }
    acc.x *= rs; acc.y *= rs;
    *(float2*)(g_os + bs * ND + h * 64 + lane * 2) = acc;
}

// ---------------- sliding-window attention ---------------------------------------------
__global__ __launch_bounds__(512) void win_attn_kernel()
{
    const int qt = blockIdx.x, h = blockIdx.y, b = blockIdx.z;
    const int tid = threadIdx.x;
    const int w = tid >> 5, lane = tid & 31;

    __shared__ float q_s[64 * 64];
    __shared__ float kT [64 * 64];
    __shared__ float v_s[64 * 64];

    const int qbase = qt * 64;

    for (int i = tid; i < 4096; i += 512) {
        int r = i >> 6, d = i & 63;
        q_s[i] = g_q[(b * NS + qbase + r) * ND + h * 64 + d];
    }

    float2 acc[4];
    float mrow[4], lrow[4];
#pragma unroll
    for (int i = 0; i < 4; i++) {
        acc[i] = make_float2(0.f, 0.f);
        mrow[i] = NEG; lrow[i] = 0.f;
    }

    const int kt_lo = (qt >= 4) ? qt - 4 : 0;
    for (int kt = kt_lo; kt <= qt; kt++) {
        const int kbase = kt * 64;
        __syncthreads();
        for (int i = tid; i < 4096; i += 512) {
            int c = i >> 6, d = i & 63;
            const int g = (b * NS + kbase + c) * ND + h * 64 + d;
            kT [d * 64 + (c ^ (d & 31))] = g_k[g];
            v_s[i] = g_v[g];
        }
        __syncthreads();

#pragma unroll
        for (int i = 0; i < 4; i++) {
            const int r  = w * 4 + i;
            const int qi = qbase + r;
            const float* qrow = q_s + r * 64;
            float sc0 = 0.f, sc1 = 0.f;
#pragma unroll 16
            for (int d = 0; d < 64; d++) {
                float qv = qrow[d];
                sc0 += qv * kT[d * 64 + ( lane       ^ (d & 31))];
                sc1 += qv * kT[d * 64 + ((lane + 32) ^ (d & 31))];
            }
            const int j0 = kbase + lane, j1 = kbase + lane + 32;
            sc0 = (j0 <= qi && qi - j0 <= NWIN) ? sc0 * INVS : NEG;
            sc1 = (j1 <= qi && qi - j1 <= NWIN) ? sc1 * INVS : NEG;

            float mnew = fmaxf(sc0, sc1);
#pragma unroll
            for (int off = 16; off > 0; off >>= 1)
                mnew = fmaxf(mnew, __shfl_xor_sync(0xffffffffu, mnew, off));
            mnew = fmaxf(mnew, mrow[i]);
            float scale = __expf(mrow[i] - mnew);
            float p0 = __expf(sc0 - mnew), p1 = __expf(sc1 - mnew);
            float ps = p0 + p1;
#pragma unroll
            for (int off = 16; off > 0; off >>= 1)
                ps += __shfl_xor_sync(0xffffffffu, ps, off);
            lrow[i] = lrow[i] * scale + ps;
            mrow[i] = mnew;

            float ax = acc[i].x * scale, ay = acc[i].y * scale;
#pragma unroll 16
            for (int c = 0; c < 64; c++) {
                float pc = __shfl_sync(0xffffffffu, c < 32 ? p0 : p1, c & 31);
                float2 v2 = *(const float2*)&v_s[c * 64 + lane * 2];
                ax += pc * v2.x; ay += pc * v2.y;
            }
            acc[i].x = ax; acc[i].y = ay;
        }
    }

#pragma unroll
    for (int i = 0; i < 4; i++) {
        const int r = w * 4 + i;
        const float rl = 1.f / lrow[i];
        float2 o = make_float2(acc[i].x * rl, acc[i].y * rl);
        *(float2*)(g_ow + (b * NS + qbase + r) * ND + h * 64 + lane * 2) = o;
    }
}

// ---------------- gates (warp per row) + elementwise combine ---------------------------
__global__ __launch_bounds__(256) void gate_kernel(
    const float* __restrict__ x, const float* __restrict__ Wg,
    const float* __restrict__ bg)
{
    const int row = blockIdx.x * 8 + (threadIdx.x >> 5);
    const int lane = threadIdx.x & 31;
    const float* xr = x + (size_t)row * ND;
    float a0 = 0.f, a1 = 0.f, a2 = 0.f;
    for (int d = lane; d < ND; d += 32) {
        float xv = xr[d];
        a0 += xv * Wg[d * 3 + 0];
        a1 += xv * Wg[d * 3 + 1];
        a2 += xv * Wg[d * 3 + 2];
    }
#pragma unroll
    for (int off = 16; off > 0; off >>= 1) {
        a0 += __shfl_xor_sync(0xffffffffu, a0, off);
        a1 += __shfl_xor_sync(0xffffffffu, a1, off);
        a2 += __shfl_xor_sync(0xffffffffu, a2, off);
    }
    if (lane == 0) {
        g_gates[row * 3 + 0] = 1.f / (1.f + __expf(-(a0 + bg[0])));
        g_gates[row * 3 + 1] = 1.f / (1.f + __expf(-(a1 + bg[1])));
        g_gates[row * 3 + 2] = 1.f / (1.f + __expf(-(a2 + bg[2])));
    }
}

__global__ __launch_bounds__(256) void combine_kernel()
{
    int idx = blockIdx.x * 256 + threadIdx.x;
    int bs = idx >> 10;
    float g0 = g_gates[bs * 3 + 0];
    float g1 = g_gates[bs * 3 + 1];
    float g2 = g_gates[bs * 3 + 2];
    g_pre[idx] = g0 * g_oc[idx] + g1 * g_os[idx] + g2 * g_ow[idx];
}

// ---------------- launcher ---------------------------------------------------------------
extern "C" void kernel_launch(void* const* d_in, const int* in_sizes, int n_in,
                              void* d_out, int out_size)
{
    (void)in_sizes; (void)n_in; (void)out_size;
    const float* x   = (const float*)d_in[0];
    const float* Wq  = (const float*)d_in[1];
    const float* Wk  = (const float*)d_in[2];
    const float* Wv  = (const float*)d_in[3];
    const float* Wo  = (const float*)d_in[4];
    const float* bo  = (const float*)d_in[5];
    const float* Wg  = (const float*)d_in[6];
    const float* bg  = (const float*)d_in[7];
    const float* wkc = (const float*)d_in[8];
    const float* wvc = (const float*)d_in[9];
    const float* wpe = (const float*)d_in[10];
    float* out = (float*)d_out;

    void *pq, *pk, *pv, *ppre, *pah, *pal, *pwh, *pwl, *pwoh, *pwol;
    void *pxkc, *pxvc, *pck, *pcv, *ptt, *pimp, *ppec, *ppvc;
    cudaGetSymbolAddress(&pq,   g_q);
    cudaGetSymbolAddress(&pk,   g_k);
    cudaGetSymbolAddress(&pv,   g_v);
    cudaGetSymbolAddress(&ppre, g_pre);
    cudaGetSymbolAddress(&pah,  g_ah);
    cudaGetSymbolAddress(&pal,  g_al);
    cudaGetSymbolAddress(&pwh,  g_wh);
    cudaGetSymbolAddress(&pwl,  g_wl);
    cudaGetSymbolAddress(&pwoh, g_woh);
    cudaGetSymbolAddress(&pwol, g_wol);
    cudaGetSymbolAddress(&pxkc, g_xkc);
    cudaGetSymbolAddress(&pxvc, g_xvc);
    cudaGetSymbolAddress(&pck,  g_ck);
    cudaGetSymbolAddress(&pcv,  g_cv);
    cudaGetSymbolAddress(&ptt,  g_tt);
    cudaGetSymbolAddress(&pimp, g_imp);
    cudaGetSymbolAddress(&ppec, g_pec);
    cudaGetSymbolAddress(&ppvc, g_pvc);

    const __nv_bfloat16* ah  = (const __nv_bfloat16*)pah;
    const __nv_bfloat16* alo = (const __nv_bfloat16*)pal;
    const dim3 wgrid(32, 32);
    const int NEL = NB * NS * ND;

    // split x; pack Wq|Wk|Wv and Wo (transposed hi/lo)
    split_kernel<<<NEL / 256, 256>>>(x, (__nv_bfloat16*)pah, (__nv_bfloat16*)pal);
    convert_w_kernel<<<wgrid, 256>>>(Wq, (__nv_bfloat16*)pwh, (__nv_bfloat16*)pwl, 0);
    convert_w_kernel<<<wgrid, 256>>>(Wk, (__nv_bfloat16*)pwh, (__nv_bfloat16*)pwl, 1024);
    convert_w_kernel<<<wgrid, 256>>>(Wv, (__nv_bfloat16*)pwh, (__nv_bfloat16*)pwl, 2048);
    convert_w_kernel<<<wgrid, 256>>>(Wo, (__nv_bfloat16*)pwoh, (__nv_bfloat16*)pwol, 0);

    // fused QKV GEMM: one launch, 384 CTAs
    mma_gemm3_kernel<<<dim3(24, 16), 256>>>(
        ah, alo, (const __nv_bfloat16*)pwh, (const __nv_bfloat16*)pwl,
        (float*)pq, (float*)pk, (float*)pv, wpe, 1);

    // exact fp32 ck/cv
    xc_kernel<<<(NB * NNC * ND) / 256, 256>>>(x, wkc, wvc);
    pe_comb_kernel<<<ND / 256, 256>>>(wpe, wkc, wvc);
    csgemm_kernel<<<dim3(16, 1, 2), 256>>>(
        (const float*)pxkc, (const float*)pxvc, Wk, Wv,
        (float*)pck, (float*)pcv, (const float*)ppec, (const float*)ppvc);

    // exact fp32 imp + top2
    nt_gemm_kernel<<<dim3(16, 1, 2), 256>>>((const float*)pck, Wq, (float*)ptt,
                                            1024, 64L * 1024, 0L, 64L * 1024);
    nt_gemm_kernel<<<dim3(1, 16, 2), 256>>>(x, (const float*)ptt, (float*)pimp,
                                            64, 1024L * 1024, 64L * 1024, 1024L * 64);
    top2_kernel<<<(NB * NS) / 8, 256>>>();

    // attention branches
    comp_attn_tile_kernel<<<dim3(16, 16, 2), 512>>>();
    sel_attn_kernel<<<NB * NS, 512>>>();
    win_attn_kernel<<<dim3(NS / 64, NH, NB), 512>>>();

    // gates + combine
    gate_kernel<<<(NB * NS) / 8, 256>>>(x, Wg, bg);
    combine_kernel<<<NEL / 256, 256>>>();

    // fused OUT GEMM
    split_kernel<<<NEL / 256, 256>>>((const float*)ppre, (__nv_bfloat16*)pah,
                                     (__nv_bfloat16*)pal);
    mma_gemm3_kernel<<<dim3(8, 16), 256>>>(
        ah, alo, (const __nv_bfloat16*)pwoh, (const __nv_bfloat16*)pwol,
        out, out, out, bo, 0);
}

// round 7
// speedup vs baseline: 1.1816x; 1.0113x over previous
#include <cuda_runtime.h>
#include <cuda_bf16.h>
#include <cstdint>

#define NB   2
#define NS   1024
#define ND   1024
#define NH   16
#define NHD  64
#define NNC  64
#define NCB  16
#define NSB  8
#define NJ   2
#define NWIN 256

#define INVS 0.125f
#define NEG  (-1e30f)

#define KA   1024
#define BM   128
#define BN   128
#define BK   32
#define AST  40
#define NIT3 96                   // 3 terms x 32 k-iters
#define STAGE_BYTES ((BM + BN) * AST * 2)     // 20480
#define SMEM_GEMM   (4 * STAGE_BYTES)         // 81920

// ---------------- scratch (device globals; no allocation allowed) ----------------
__device__ __align__(16) float g_q [NB*NS*ND];
__device__ __align__(16) float g_k [NB*NS*ND];
__device__ __align__(16) float g_v [NB*NS*ND];
__device__ __align__(16) float g_ck[NB*NNC*ND];
__device__ __align__(16) float g_cv[NB*NNC*ND];
__device__ __align__(16) float g_oc[NB*NS*ND];
__device__ __align__(16) float g_os[NB*NS*ND];
__device__ __align__(16) float g_ow[NB*NS*ND];
__device__ __align__(16) float g_pre[NB*NS*ND];
__device__ int   g_top[NB*NS*NJ];
__device__ __align__(16) float g_gates[NB*NS*3];
__device__ __align__(16) __nv_bfloat16 g_ah[(size_t)NB*NS*ND];
__device__ __align__(16) __nv_bfloat16 g_al[(size_t)NB*NS*ND];
__device__ __align__(16) __nv_bfloat16 g_wh[(size_t)3*ND*ND];     // Wq|Wk|Wv ^T hi
__device__ __align__(16) __nv_bfloat16 g_wl[(size_t)3*ND*ND];
__device__ __align__(16) __nv_bfloat16 g_woh[(size_t)ND*ND];
__device__ __align__(16) __nv_bfloat16 g_wol[(size_t)ND*ND];
__device__ __align__(16) float g_xkc[NB*NNC*ND];
__device__ __align__(16) float g_xvc[NB*NNC*ND];
__device__ __align__(16) float g_pec[ND];
__device__ __align__(16) float g_pvc[ND];
__device__ __align__(16) float g_tt [NB*NNC*ND];
__device__ __align__(16) float g_imp[NB*NS*NNC];

// ======================= PTX helpers ================================================
__device__ __forceinline__ void cp16(uint32_t d, const void* s) {
    asm volatile("cp.async.cg.shared.global [%0], [%1], 16;" :: "r"(d), "l"(s));
}
__device__ __forceinline__ void cp_commit() {
    asm volatile("cp.async.commit_group;");
}
__device__ __forceinline__ void cp_wait2() {
    asm volatile("cp.async.wait_group 2;");
}
__device__ __forceinline__ void ldsm_x4(uint32_t& r0, uint32_t& r1, uint32_t& r2, uint32_t& r3,
                                        uint32_t addr) {
    asm volatile("ldmatrix.sync.aligned.m8n8.x4.shared.b16 {%0,%1,%2,%3}, [%4];"
        : "=r"(r0), "=r"(r1), "=r"(r2), "=r"(r3) : "r"(addr));
}
__device__ __forceinline__ void mma16816(float* c, const uint32_t* a, const uint32_t* b) {
    asm volatile("mma.sync.aligned.m16n8k16.row.col.f32.bf16.bf16.f32 "
        "{%0,%1,%2,%3}, {%4,%5,%6,%7}, {%8,%9}, {%0,%1,%2,%3};"
        : "+f"(c[0]), "+f"(c[1]), "+f"(c[2]), "+f"(c[3])
        : "r"(a[0]), "r"(a[1]), "r"(a[2]), "r"(a[3]), "r"(b[0]), "r"(b[1]));
}

// ======================= split conversions =========================================
__global__ __launch_bounds__(256) void split_kernel(
    const float* __restrict__ src, __nv_bfloat16* __restrict__ hi,
    __nv_bfloat16* __restrict__ lo)
{
    int idx = (blockIdx.x * 256 + threadIdx.x) * 4;
    float4 v = *(const float4*)(src + idx);
    __nv_bfloat16 h0 = __float2bfloat16(v.x), h1 = __float2bfloat16(v.y);
    __nv_bfloat16 h2 = __float2bfloat16(v.z), h3 = __float2bfloat16(v.w);
    __nv_bfloat162 hA = __halves2bfloat162(h0, h1);
    __nv_bfloat162 hB = __halves2bfloat162(h2, h3);
    *(__nv_bfloat162*)(hi + idx)     = hA;
    *(__nv_bfloat162*)(hi + idx + 2) = hB;
    __nv_bfloat162 lA = __halves2bfloat162(
        __float2bfloat16(v.x - __bfloat162float(h0)),
        __float2bfloat16(v.y - __bfloat162float(h1)));
    __nv_bfloat162 lB = __halves2bfloat162(
        __float2bfloat16(v.z - __bfloat162float(h2)),
        __float2bfloat16(v.w - __bfloat162float(h3)));
    *(__nv_bfloat162*)(lo + idx)     = lA;
    *(__nv_bfloat162*)(lo + idx + 2) = lB;
}

// batched: z=0..2 -> Wq/Wk/Wv into g_wh/g_wl at row_off z*1024 ; z=3 -> Wo into g_woh/g_wol
__global__ __launch_bounds__(256) void convert_w4_kernel(
    const float* __restrict__ W0, const float* __restrict__ W1,
    const float* __restrict__ W2, const float* __restrict__ W3,
    __nv_bfloat16* __restrict__ Wh, __nv_bfloat16* __restrict__ Wl,
    __nv_bfloat16* __restrict__ Woh, __nv_bfloat16* __restrict__ Wol)
{
    const int z = blockIdx.z;
    const float* W = (z == 0) ? W0 : (z == 1) ? W1 : (z == 2) ? W2 : W3;
    __nv_bfloat16* Dh = (z == 3) ? Woh : Wh;
    __nv_bfloat16* Dl = (z == 3) ? Wol : Wl;
    const int row_off = (z == 3) ? 0 : z * 1024;

    __shared__ float t[32][33];
    int n0 = blockIdx.x * 32, k0 = blockIdx.y * 32;
    int tx = threadIdx.x & 31, ty = threadIdx.x >> 5;
#pragma unroll
    for (int i = 0; i < 32; i += 8)
        t[ty + i][tx] = W[(k0 + ty + i) * 1024 + n0 + tx];
    __syncthreads();
#pragma unroll
    for (int i = 0; i < 32; i += 8) {
        int n = row_off + n0 + ty + i, k = k0 + tx;
        float v = t[tx][ty + i];
        __nv_bfloat16 h = __float2bfloat16(v);
        Dh[(size_t)n * 1024 + k] = h;
        Dl[(size_t)n * 1024 + k] = __float2bfloat16(v - __bfloat162float(h));
    }
}

// ======================= fused 3-term HMMA GEMM (4-stage pipeline) ==================
// acc = Ah@Wh^T + Ah@Wl^T + Al@Wh^T  (96 pipelined k-iters, single epilogue)
// qkv_mode=1: N=3072 grid; col segment 0->Cq, 1->Ck(+pe), 2->Cv(+pe)
// qkv_mode=0: single dest Cq, += bias extra[col]
__global__ __launch_bounds__(256) void mma_gemm3_kernel(
    const __nv_bfloat16* __restrict__ Ah, const __nv_bfloat16* __restrict__ Al,
    const __nv_bfloat16* __restrict__ Wh, const __nv_bfloat16* __restrict__ Wl,
    float* __restrict__ Cq, float* __restrict__ Ck, float* __restrict__ Cv,
    const float* __restrict__ extra, int qkv_mode)
{
    extern __shared__ __nv_bfloat16 smem[];

    const int tid = threadIdx.x;
    const int wid = tid >> 5, lane = tid & 31;
    const int wm = wid >> 2, wn = wid & 3;
    const int mt = blockIdx.y * BM, nt = blockIdx.x * BN;

    const uint32_t sb = (uint32_t)__cvta_generic_to_shared(smem);
    const uint32_t B_OFF = BM * AST * 2;

    const int lrow = tid >> 1;
    const int lc   = (tid & 1) * 2;
    const size_t aoff = (size_t)(mt + lrow) * KA + lc * 8;
    const size_t boff = (size_t)(nt + lrow) * KA + lc * 8;
    const __nv_bfloat16* aSrc[2] = {Ah + aoff, Al + aoff};
    const __nv_bfloat16* bSrc[2] = {Wh + boff, Wl + boff};
    const uint32_t dA = sb + (lrow * AST + lc * 8) * 2;
    const uint32_t dB = sb + B_OFF + (lrow * AST + lc * 8) * 2;

    float c[4][4][4];
#pragma unroll
    for (int i = 0; i < 4; i++)
#pragma unroll
        for (int j = 0; j < 4; j++)
#pragma unroll
            for (int r = 0; r < 4; r++) c[i][j][r] = 0.f;

    const int al  = lane & 15;
    const int ahi = lane >> 4;

    // issue loads for iteration j into slot j%4
#define ISSUE(j) do {                                                       \
        const int t_  = (j) >> 5;                                           \
        const int k0_ = ((j) & 31) * BK;                                    \
        const __nv_bfloat16* ga_ = aSrc[t_ == 2 ? 1 : 0] + k0_;             \
        const __nv_bfloat16* gb_ = bSrc[t_ == 1 ? 1 : 0] + k0_;             \
        const uint32_t so_ = ((j) & 3) * STAGE_BYTES;                       \
        cp16(dA + so_, ga_);       cp16(dA + so_ + 16, ga_ + 8);            \
        cp16(dB + so_, gb_);       cp16(dB + so_ + 16, gb_ + 8);            \
    } while (0)

    ISSUE(0); cp_commit();
    ISSUE(1); cp_commit();
    ISSUE(2); cp_commit();

    for (int it = 0; it < NIT3; it++) {
        cp_wait2();
        __syncthreads();
        if (it + 3 < NIT3) ISSUE(it + 3);
        cp_commit();

        const uint32_t sA = sb + (it & 3) * STAGE_BYTES;
        const uint32_t sB = sA + B_OFF;
#pragma unroll
        for (int ks = 0; ks < 2; ks++) {
            const int kg = ks * 2 + ahi;
            uint32_t a[4][4], b[4][2];
#pragma unroll
            for (int i = 0; i < 4; i++) {
                uint32_t ad = sA + ((wm * 64 + i * 16 + al) * AST + kg * 8) * 2;
                ldsm_x4(a[i][0], a[i][1], a[i][2], a[i][3], ad);
            }
#pragma unroll
            for (int jj = 0; jj < 2; jj++) {
                uint32_t bd = sB + ((wn * 32 + jj * 16 + al) * AST + kg * 8) * 2;
                uint32_t r0, r1, r2, r3;
                ldsm_x4(r0, r1, r2, r3, bd);
                b[jj * 2 + 0][0] = r0; b[jj * 2 + 1][0] = r1;
                b[jj * 2 + 0][1] = r2; b[jj * 2 + 1][1] = r3;
            }
#pragma unroll
            for (int i = 0; i < 4; i++)
#pragma unroll
                for (int j = 0; j < 4; j++) mma16816(c[i][j], a[i], b[j]);
        }
    }
#undef ISSUE

    // epilogue
    float* dst;
    bool add_pe = false;
    int ncol0;
    if (qkv_mode) {
        const int seg = nt >> 10;
        dst = (seg == 0) ? Cq : (seg == 1 ? Ck : Cv);
        add_pe = (seg != 0);
        ncol0 = nt & 1023;
    } else {
        dst = Cq;
        ncol0 = nt;
    }

    const int mbase = mt + wm * 64;
    const int nbase = ncol0 + wn * 32;
    const int rr = lane >> 2, cc = (lane & 3) * 2;
#pragma unroll
    for (int i = 0; i < 4; i++) {
#pragma unroll
        for (int j = 0; j < 4; j++) {
            int row = mbase + i * 16 + rr;
            int col = nbase + j * 8 + cc;
            float2 v0 = make_float2(c[i][j][0], c[i][j][1]);
            float2 v1 = make_float2(c[i][j][2], c[i][j][3]);
            if (qkv_mode) {
                if (add_pe) {
                    const float* p0 = extra + (row & 15) * 1024 + col;
                    const float* p1 = extra + ((row + 8) & 15) * 1024 + col;
                    v0.x += p0[0]; v0.y += p0[1];
                    v1.x += p1[0]; v1.y += p1[1];
                }
            } else {
                v0.x += extra[col]; v0.y += extra[col + 1];
                v1.x += extra[col]; v1.y += extra[col + 1];
            }
            *(float2*)(dst + (size_t)row * 1024 + col)       = v0;
            *(float2*)(dst + (size_t)(row + 8) * 1024 + col) = v1;
        }
    }
}

// ======================= fp32 SGEMM (exact ck/cv; z selects k/v path) ===============
__global__ __launch_bounds__(256) void csgemm_kernel(
    const float* __restrict__ Ak, const float* __restrict__ Av,
    const float* __restrict__ Wk, const float* __restrict__ Wv,
    float* __restrict__ Ck, float* __restrict__ Cv,
    const float* __restrict__ bk, const float* __restrict__ bv)
{
    const int z = blockIdx.z;
    const float* A    = z ? Av : Ak;
    const float* Bm   = z ? Wv : Wk;
    float* C          = z ? Cv : Ck;
    const float* bias = z ? bv : bk;

    __shared__ float As[16][132];
    __shared__ float Bs[16][64];

    const int tid = threadIdx.x;
    const int bn  = blockIdx.x * 64;
    const int tx  = tid & 15;
    const int ty  = tid >> 4;

    const int arow = tid >> 1;
    const int acol = (tid & 1) * 8;
    const int brow = tid >> 4;
    const int bcol = (tid & 15) * 4;

    float acc[8][4];
#pragma unroll
    for (int i = 0; i < 8; i++)
#pragma unroll
        for (int j = 0; j < 4; j++) acc[i][j] = 0.f;

    for (int k0 = 0; k0 < 1024; k0 += 16) {
        float4 a0 = *(const float4*)(A + arow * 1024 + k0 + acol);
        float4 a1 = *(const float4*)(A + arow * 1024 + k0 + acol + 4);
        As[acol+0][arow] = a0.x; As[acol+1][arow] = a0.y;
        As[acol+2][arow] = a0.z; As[acol+3][arow] = a0.w;
        As[acol+4][arow] = a1.x; As[acol+5][arow] = a1.y;
        As[acol+6][arow] = a1.z; As[acol+7][arow] = a1.w;
        float4 b4 = *(const float4*)(Bm + (k0 + brow) * 1024 + bn + bcol);
        *(float4*)&Bs[brow][bcol] = b4;
        __syncthreads();

#pragma unroll
        for (int kk = 0; kk < 16; kk++) {
            float4 t0 = *(const float4*)&As[kk][ty * 8];
            float4 t1 = *(const float4*)&As[kk][ty * 8 + 4];
            float4 bb = *(const float4*)&Bs[kk][tx * 4];
            float ar[8] = {t0.x, t0.y, t0.z, t0.w, t1.x, t1.y, t1.z, t1.w};
            float br[4] = {bb.x, bb.y, bb.z, bb.w};
#pragma unroll
            for (int i = 0; i < 8; i++)
#pragma unroll
                for (int j = 0; j < 4; j++) acc[i][j] += ar[i] * br[j];
        }
        __syncthreads();
    }

#pragma unroll
    for (int i = 0; i < 8; i++) {
        int m = ty * 8 + i;
#pragma unroll
        for (int j = 0; j < 4; j++) {
            int n = bn + tx * 4 + j;
            C[m * 1024 + n] = acc[i][j] + bias[n];
        }
    }
}

// ======================= fp32 NT GEMM: C[i,j] = sum_k A[i,k]*B[j,k], K=1024 =========
__global__ __launch_bounds__(256) void nt_gemm_kernel(
    const float* __restrict__ A, const float* __restrict__ B, float* __restrict__ C,
    int N, long aB, long bB, long cB)
{
    const float* Ab = A + (size_t)blockIdx.z * aB;
    const float* Bb = B + (size_t)blockIdx.z * bB;
    float* Cb = C + (size_t)blockIdx.z * cB;

    __shared__ float As[64][33];
    __shared__ float Bs[64][33];

    const int tid = threadIdx.x;
    const int row = tid >> 2;
    const int c4  = (tid & 3) * 8;
    const int ty = tid >> 4, tx = tid & 15;
    const int i0 = blockIdx.y * 64, j0 = blockIdx.x * 64;

    float acc[4][4];
#pragma unroll
    for (int i = 0; i < 4; i++)
#pragma unroll
        for (int j = 0; j < 4; j++) acc[i][j] = 0.f;

    for (int k0 = 0; k0 < 1024; k0 += 32) {
        float4 a0 = *(const float4*)(Ab + (size_t)(i0 + row) * 1024 + k0 + c4);
        float4 a1 = *(const float4*)(Ab + (size_t)(i0 + row) * 1024 + k0 + c4 + 4);
        As[row][c4+0] = a0.x; As[row][c4+1] = a0.y;
        As[row][c4+2] = a0.z; As[row][c4+3] = a0.w;
        As[row][c4+4] = a1.x; As[row][c4+5] = a1.y;
        As[row][c4+6] = a1.z; As[row][c4+7] = a1.w;
        float4 b0 = *(const float4*)(Bb + (size_t)(j0 + row) * 1024 + k0 + c4);
        float4 b1 = *(const float4*)(Bb + (size_t)(j0 + row) * 1024 + k0 + c4 + 4);
        Bs[row][c4+0] = b0.x; Bs[row][c4+1] = b0.y;
        Bs[row][c4+2] = b0.z; Bs[row][c4+3] = b0.w;
        Bs[row][c4+4] = b1.x; Bs[row][c4+5] = b1.y;
        Bs[row][c4+6] = b1.z; Bs[row][c4+7] = b1.w;
        __syncthreads();

#pragma unroll 8
        for (int k = 0; k < 32; k++) {
            float ar[4], br[4];
#pragma unroll
            for (int i = 0; i < 4; i++) ar[i] = As[ty * 4 + i][k];
#pragma unroll
            for (int j = 0; j < 4; j++) br[j] = Bs[tx * 4 + j][k];
#pragma unroll
            for (int i = 0; i < 4; i++)
#pragma unroll
                for (int j = 0; j < 4; j++) acc[i][j] += ar[i] * br[j];
        }
        __syncthreads();
    }

#pragma unroll
    for (int i = 0; i < 4; i++)
#pragma unroll
        for (int j = 0; j < 4; j++)
            Cb[(size_t)(i0 + ty * 4 + i) * N + j0 + tx * 4 + j] = acc[i][j];
}

// ---------------- exact compressed-row inputs ---------------------------------------
__global__ __launch_bounds__(256) void xc_kernel(
    const float* __restrict__ x, const float* __restrict__ wkc,
    const float* __restrict__ wvc)
{
    int idx = blockIdx.x * 256 + threadIdx.x;
    int d = idx & 1023;
    int n = (idx >> 10) & 63;
    int b = idx >> 16;
    const float* xb = x + ((size_t)(b * NS + n * NCB)) * ND + d;
    float sk = 0.f, sv = 0.f;
#pragma unroll
    for (int t = 0; t < NCB; t++) {
        float xv = xb[t * ND];
        sk += wkc[t] * xv;
        sv += wvc[t] * xv;
    }
    g_xkc[idx] = sk;
    g_xvc[idx] = sv;
}

__global__ __launch_bounds__(256) void pe_comb_kernel(
    const float* __restrict__ wpe, const float* __restrict__ wkc,
    const float* __restrict__ wvc)
{
    int d = blockIdx.x * 256 + threadIdx.x;
    float sk = 0.f, sv = 0.f;
#pragma unroll
    for (int t = 0; t < NCB; t++) {
        float p = wpe[t * ND + d];
        sk += wkc[t] * p;
        sv += wvc[t] * p;
    }
    g_pec[d] = sk;
    g_pvc[d] = sv;
}

// ---------------- top-2 ---------------------------------------------------------------
__global__ __launch_bounds__(256) void top2_kernel()
{
    const int bs = blockIdx.x * 8 + (threadIdx.x >> 5);
    const int lane = threadIdx.x & 31;
    const float* row = g_imp + (size_t)bs * 64;
    float v0 = row[lane], v1 = row[lane + 32];

    float bv; int bi;
    if (v0 >= v1) { bv = v0; bi = lane; } else { bv = v1; bi = lane + 32; }
#pragma unroll
    for (int off = 16; off > 0; off >>= 1) {
        float ov = __shfl_xor_sync(0xffffffffu, bv, off);
        int   oi = __shfl_xor_sync(0xffffffffu, bi, off);
        if (ov > bv || (ov == bv && oi < bi)) { bv = ov; bi = oi; }
    }
    int top1 = bi;
    float w0 = (lane == top1)      ? NEG : v0;
    float w1 = (lane + 32 == top1) ? NEG : v1;
    float bv2; int bi2;
    if (w0 >= w1) { bv2 = w0; bi2 = lane; } else { bv2 = w1; bi2 = lane + 32; }
#pragma unroll
    for (int off = 16; off > 0; off >>= 1) {
        float ov = __shfl_xor_sync(0xffffffffu, bv2, off);
        int   oi = __shfl_xor_sync(0xffffffffu, bi2, off);
        if (ov > bv2 || (ov == bv2 && oi < bi2)) { bv2 = ov; bi2 = oi; }
    }
    if (lane == 0) { g_top[bs * 2] = top1; g_top[bs * 2 + 1] = bi2; }
}

// ---------------- compressed attention, 64x64 tile -----------------------------------
__global__ __launch_bounds__(512) void comp_attn_tile_kernel()
{
    const int st = blockIdx.x, h = blockIdx.y, b = blockIdx.z;
    const int tid = threadIdx.x;
    const int w = tid >> 5, lane = tid & 31;

    __shared__ float q_s[64 * 64];
    __shared__ float kT [64 * 64];
    __shared__ float v_s[64 * 64];

    const int qbase = st * 64;

    for (int i = tid; i < 4096; i += 512) {
        int r = i >> 6, d = i & 63;
        q_s[i] = g_q[((size_t)(b * NS + qbase + r)) * ND + h * 64 + d];
        int n = r;
        const size_t gc = ((size_t)(b * 64 + n)) * ND + h * 64 + d;
        kT [d * 64 + (n ^ (d & 31))] = g_ck[gc];
        v_s[i] = g_cv[gc];
    }
    __syncthreads();

#pragma unroll
    for (int i = 0; i < 4; i++) {
        const int r = w * 4 + i;
        const float* qrow = q_s + r * 64;
        float sc0 = 0.f, sc1 = 0.f;
#pragma unroll 16
        for (int d = 0; d < 64; d++) {
            float qv = qrow[d];
            sc0 += qv * kT[d * 64 + ( lane       ^ (d & 31))];
            sc1 += qv * kT[d * 64 + ((lane + 32) ^ (d & 31))];
        }
        sc0 *= INVS; sc1 *= INVS;

        float mx = fmaxf(sc0, sc1);
#pragma unroll
        for (int off = 16; off > 0; off >>= 1)
            mx = fmaxf(mx, __shfl_xor_sync(0xffffffffu, mx, off));
        float p0 = __expf(sc0 - mx), p1 = __expf(sc1 - mx);
        float ps = p0 + p1;
#pragma unroll
        for (int off = 16; off > 0; off >>= 1)
            ps += __shfl_xor_sync(0xffffffffu, ps, off);
        const float rs = 1.f / ps;

        float ax = 0.f, ay = 0.f;
#pragma unroll 16
        for (int n = 0; n < 64; n++) {
            float pn = __shfl_sync(0xffffffffu, n < 32 ? p0 : p1, n & 31);
            float2 v2 = *(const float2*)&v_s[n * 64 + lane * 2];
            ax += pn * v2.x; ay += pn * v2.y;
        }
        float2 o = make_float2(ax * rs, ay * rs);
        *(float2*)(g_oc + ((size_t)(b * NS + qbase + r)) * ND + h * 64 + lane * 2) = o;
    }
}

// ---------------- selected attention ---------------------------------------------------
__global__ __launch_bounds__(512) void sel_attn_kernel()
{
    const int bs = blockIdx.x;
    const int b  = bs >> 10, s = bs & 1023;
    const int tid = threadIdx.x;
    const int h = tid >> 5, lane = tid & 31;

    __shared__ int blk_s[2];
    if (tid < 2) blk_s[tid] = g_top[(tid * NS + s) * 2 + b];
    __syncthreads();

    const float2 q2 = *(const float2*)(g_q + bs * ND + h * 64 + lane * 2);

    float myscore = NEG;
#pragma unroll
    for (int m = 0; m < 16; m++) {
        int j = m >> 3, t = m & 7;
        int tok = blk_s[j] * NCB + t;
        float2 k2 = *(const float2*)(g_k + (j * NS + tok) * ND + h * 64 + lane * 2);
        float p = q2.x * k2.x + q2.y * k2.y;
#pragma unroll
        for (int off = 16; off > 0; off >>= 1)
            p += __shfl_xor_sync(0xffffffffu, p, off);
        p *= INVS;
        if (lane == m) myscore = p;
    }
    float mx = myscore;
#pragma unroll
    for (int off = 16; off > 0; off >>= 1)
        mx = fmaxf(mx, __shfl_xor_sync(0xffffffffu, mx, off));
    float p = __expf(myscore - mx);
    float sum = p;
#pragma unroll
    for (int off = 16; off > 0; off >>= 1)
        sum += __shfl_xor_sync(0xffffffffu, sum, off);
    float rs = 1.f / sum;

    float2 acc = make_float2(0.f, 0.f);
#pragma unroll
    for (int m = 0; m < 16; m++) {
        float pm = __shfl_sync(0xffffffffu, p, m);
        int j = m >> 3, t = m & 7;
        int tok = blk_s[j] * NCB + t;
        float2 v2 = *(const float2*)(g_v + (j * NS + tok) * ND + h * 64 + lane * 2);
        acc.x += pm * v2.x; acc.y += pm * v2.y;
    }
    acc.x *= rs; acc.y *= rs;
    *(float2*)(g_os + bs * ND + h * 64 + lane * 2) = acc;
}

// ---------------- sliding-window attention ---------------------------------------------
__global__ __launch_bounds__(512) void win_attn_kernel()
{
    const int qt = blockIdx.x, h = blockIdx.y, b = blockIdx.z;
    const int tid = threadIdx.x;
    const int w = tid >> 5, lane = tid & 31;

    __shared__ float q_s[64 * 64];
    __shared__ float kT [64 * 64];
    __shared__ float v_s[64 * 64];

    const int qbase = qt * 64;

    for (int i = tid; i < 4096; i += 512) {
        int r = i >> 6, d = i & 63;
        q_s[i] = g_q[(b * NS + qbase + r) * ND + h * 64 + d];
    }

    float2 acc[4];
    float mrow[4], lrow[4];
#pragma unroll
    for (int i = 0; i < 4; i++) {
        acc[i] = make_float2(0.f, 0.f);
        mrow[i] = NEG; lrow[i] = 0.f;
    }

    const int kt_lo = (qt >= 4) ? qt - 4 : 0;
    for (int kt = kt_lo; kt <= qt; kt++) {
        const int kbase = kt * 64;
        __syncthreads();
        for (int i = tid; i < 4096; i += 512) {
            int c = i >> 6, d = i & 63;
            const int g = (b * NS + kbase + c) * ND + h * 64 + d;
            kT [d * 64 + (c ^ (d & 31))] = g_k[g];
            v_s[i] = g_v[g];
        }
        __syncthreads();

#pragma unroll
        for (int i = 0; i < 4; i++) {
            const int r  = w * 4 + i;
            const int qi = qbase + r;
            const float* qrow = q_s + r * 64;
            float sc0 = 0.f, sc1 = 0.f;
#pragma unroll 16
            for (int d = 0; d < 64; d++) {
                float qv = qrow[d];
                sc0 += qv * kT[d * 64 + ( lane       ^ (d & 31))];
                sc1 += qv * kT[d * 64 + ((lane + 32) ^ (d & 31))];
            }
            const int j0 = kbase + lane, j1 = kbase + lane + 32;
            sc0 = (j0 <= qi && qi - j0 <= NWIN) ? sc0 * INVS : NEG;
            sc1 = (j1 <= qi && qi - j1 <= NWIN) ? sc1 * INVS : NEG;

            float mnew = fmaxf(sc0, sc1);
#pragma unroll
            for (int off = 16; off > 0; off >>= 1)
                mnew = fmaxf(mnew, __shfl_xor_sync(0xffffffffu, mnew, off));
            mnew = fmaxf(mnew, mrow[i]);
            float scale = __expf(mrow[i] - mnew);
            float p0 = __expf(sc0 - mnew), p1 = __expf(sc1 - mnew);
            float ps = p0 + p1;
#pragma unroll
            for (int off = 16; off > 0; off >>= 1)
                ps += __shfl_xor_sync(0xffffffffu, ps, off);
            lrow[i] = lrow[i] * scale + ps;
            mrow[i] = mnew;

            float ax = acc[i].x * scale, ay = acc[i].y * scale;
#pragma unroll 16
            for (int c = 0; c < 64; c++) {
                float pc = __shfl_sync(0xffffffffu, c < 32 ? p0 : p1, c & 31);
                float2 v2 = *(const float2*)&v_s[c * 64 + lane * 2];
                ax += pc * v2.x; ay += pc * v2.y;
            }
            acc[i].x = ax; acc[i].y = ay;
        }
    }

#pragma unroll
    for (int i = 0; i < 4; i++) {
        const int r = w * 4 + i;
        const float rl = 1.f / lrow[i];
        float2 o = make_float2(acc[i].x * rl, acc[i].y * rl);
        *(float2*)(g_ow + (b * NS + qbase + r) * ND + h * 64 + lane * 2) = o;
    }
}

// ---------------- gates + combine -------------------------------------------------------
__global__ __launch_bounds__(256) void gate_kernel(
    const float* __restrict__ x, const float* __restrict__ Wg,
    const float* __restrict__ bg)
{
    const int row = blockIdx.x * 8 + (threadIdx.x >> 5);
    const int lane = threadIdx.x & 31;
    const float* xr = x + (size_t)row * ND;
    float a0 = 0.f, a1 = 0.f, a2 = 0.f;
    for (int d = lane; d < ND; d += 32) {
        float xv = xr[d];
        a0 += xv * Wg[d * 3 + 0];
        a1 += xv * Wg[d * 3 + 1];
        a2 += xv * Wg[d * 3 + 2];
    }
#pragma unroll
    for (int off = 16; off > 0; off >>= 1) {
        a0 += __shfl_xor_sync(0xffffffffu, a0, off);
        a1 += __shfl_xor_sync(0xffffffffu, a1, off);
        a2 += __shfl_xor_sync(0xffffffffu, a2, off);
    }
    if (lane == 0) {
        g_gates[row * 3 + 0] = 1.f / (1.f + __expf(-(a0 + bg[0])));
        g_gates[row * 3 + 1] = 1.f / (1.f + __expf(-(a1 + bg[1])));
        g_gates[row * 3 + 2] = 1.f / (1.f + __expf(-(a2 + bg[2])));
    }
}

__global__ __launch_bounds__(256) void combine_kernel()
{
    int idx = blockIdx.x * 256 + threadIdx.x;
    int bs = idx >> 10;
    float g0 = g_gates[bs * 3 + 0];
    float g1 = g_gates[bs * 3 + 1];
    float g2 = g_gates[bs * 3 + 2];
    g_pre[idx] = g0 * g_oc[idx] + g1 * g_os[idx] + g2 * g_ow[idx];
}

// ---------------- launcher ---------------------------------------------------------------
extern "C" void kernel_launch(void* const* d_in, const int* in_sizes, int n_in,
                              void* d_out, int out_size)
{
    (void)in_sizes; (void)n_in; (void)out_size;
    const float* x   = (const float*)d_in[0];
    const float* Wq  = (const float*)d_in[1];
    const float* Wk  = (const float*)d_in[2];
    const float* Wv  = (const float*)d_in[3];
    const float* Wo  = (const float*)d_in[4];
    const float* bo  = (const float*)d_in[5];
    const float* Wg  = (const float*)d_in[6];
    const float* bg  = (const float*)d_in[7];
    const float* wkc = (const float*)d_in[8];
    const float* wvc = (const float*)d_in[9];
    const float* wpe = (const float*)d_in[10];
    float* out = (float*)d_out;

    void *pq, *pk, *pv, *ppre, *pah, *pal, *pwh, *pwl, *pwoh, *pwol;
    void *pxkc, *pxvc, *pck, *pcv, *ptt, *pimp, *ppec, *ppvc;
    cudaGetSymbolAddress(&pq,   g_q);
    cudaGetSymbolAddress(&pk,   g_k);
    cudaGetSymbolAddress(&pv,   g_v);
    cudaGetSymbolAddress(&ppre, g_pre);
    cudaGetSymbolAddress(&pah,  g_ah);
    cudaGetSymbolAddress(&pal,  g_al);
    cudaGetSymbolAddress(&pwh,  g_wh);
    cudaGetSymbolAddress(&pwl,  g_wl);
    cudaGetSymbolAddress(&pwoh, g_woh);
    cudaGetSymbolAddress(&pwol, g_wol);
    cudaGetSymbolAddress(&pxkc, g_xkc);
    cudaGetSymbolAddress(&pxvc, g_xvc);
    cudaGetSymbolAddress(&pck,  g_ck);
    cudaGetSymbolAddress(&pcv,  g_cv);
    cudaGetSymbolAddress(&ptt,  g_tt);
    cudaGetSymbolAddress(&pimp, g_imp);
    cudaGetSymbolAddress(&ppec, g_pec);
    cudaGetSymbolAddress(&ppvc, g_pvc);

    const __nv_bfloat16* ah  = (const __nv_bfloat16*)pah;
    const __nv_bfloat16* alo = (const __nv_bfloat16*)pal;
    const int NEL = NB * NS * ND;

    cudaFuncSetAttribute(mma_gemm3_kernel,
                         cudaFuncAttributeMaxDynamicSharedMemorySize, SMEM_GEMM);

    // split x; convert all 4 weights in one batched launch
    split_kernel<<<NEL / 1024, 256>>>(x, (__nv_bfloat16*)pah, (__nv_bfloat16*)pal);
    convert_w4_kernel<<<dim3(32, 32, 4), 256>>>(
        Wq, Wk, Wv, Wo,
        (__nv_bfloat16*)pwh, (__nv_bfloat16*)pwl,
        (__nv_bfloat16*)pwoh, (__nv_bfloat16*)pwol);

    // fused QKV GEMM
    mma_gemm3_kernel<<<dim3(24, 16), 256, SMEM_GEMM>>>(
        ah, alo, (const __nv_bfloat16*)pwh, (const __nv_bfloat16*)pwl,
        (float*)pq, (float*)pk, (float*)pv, wpe, 1);

    // exact fp32 ck/cv
    xc_kernel<<<(NB * NNC * ND) / 256, 256>>>(x, wkc, wvc);
    pe_comb_kernel<<<ND / 256, 256>>>(wpe, wkc, wvc);
    csgemm_kernel<<<dim3(16, 1, 2), 256>>>(
        (const float*)pxkc, (const float*)pxvc, Wk, Wv,
        (float*)pck, (float*)pcv, (const float*)ppec, (const float*)ppvc);

    // exact fp32 imp + top2
    nt_gemm_kernel<<<dim3(16, 1, 2), 256>>>((const float*)pck, Wq, (float*)ptt,
                                            1024, 64L * 1024, 0L, 64L * 1024);
    nt_gemm_kernel<<<dim3(1, 16, 2), 256>>>(x, (const float*)ptt, (float*)pimp,
                                            64, 1024L * 1024, 64L * 1024, 1024L * 64);
    top2_kernel<<<(NB * NS) / 8, 256>>>();

    // attention branches
    comp_attn_tile_kernel<<<dim3(16, 16, 2), 512>>>();
    sel_attn_kernel<<<NB * NS, 512>>>();
    win_attn_kernel<<<dim3(NS / 64, NH, NB), 512>>>();

    // gates + combine
    gate_kernel<<<(NB * NS) / 8, 256>>>(x, Wg, bg);
    combine_kernel<<<NEL / 256, 256>>>();

    // fused OUT GEMM
    split_kernel<<<NEL / 1024, 256>>>((const float*)ppre, (__nv_bfloat16*)pah,
                                      (__nv_bfloat16*)pal);
    mma_gemm3_kernel<<<dim3(8, 16), 256, SMEM_GEMM>>>(
        ah, alo, (const __nv_bfloat16*)pwoh, (const __nv_bfloat16*)pwol,
        out, out, out, bo, 0);
}

// round 8
// speedup vs baseline: 1.9790x; 1.6749x over previous
#include <cuda_runtime.h>
#include <cuda_bf16.h>
#include <cstdint>

#define NB   2
#define NS   1024
#define ND   1024
#define NH   16
#define NHD  64
#define NNC  64
#define NCB  16
#define NSB  8
#define NJ   2
#define NWIN 256

#define INVS 0.125f
#define NEG  (-1e30f)

#define KA   1024
#define BM   128
#define BN   128
#define BK   32
#define AST  40
#define NIT3 96
#define STAGE_BYTES ((BM + BN) * AST * 2)
#define SMEM_GEMM   (4 * STAGE_BYTES)

// attention tile smem: Qt/Kt/Vs stride 68 (float4-aligned), Ps stride 65
#define TS   68
#define PS   65
#define SMEM_ATT ((3 * 64 * TS + 64 * PS) * 4)   // 68864 B

// ---------------- scratch ----------------
__device__ __align__(16) float g_q [NB*NS*ND];
__device__ __align__(16) float g_k [NB*NS*ND];
__device__ __align__(16) float g_v [NB*NS*ND];
__device__ __align__(16) float g_ck[NB*NNC*ND];
__device__ __align__(16) float g_cv[NB*NNC*ND];
__device__ __align__(16) float g_oc[NB*NS*ND];
__device__ __align__(16) float g_os[NB*NS*ND];
__device__ __align__(16) float g_ow[NB*NS*ND];
__device__ __align__(16) float g_pre[NB*NS*ND];
__device__ int   g_top[NB*NS*NJ];
__device__ __align__(16) float g_gates[NB*NS*3];
__device__ __align__(16) __nv_bfloat16 g_ah[(size_t)NB*NS*ND];
__device__ __align__(16) __nv_bfloat16 g_al[(size_t)NB*NS*ND];
__device__ __align__(16) __nv_bfloat16 g_wh[(size_t)3*ND*ND];
__device__ __align__(16) __nv_bfloat16 g_wl[(size_t)3*ND*ND];
__device__ __align__(16) __nv_bfloat16 g_woh[(size_t)ND*ND];
__device__ __align__(16) __nv_bfloat16 g_wol[(size_t)ND*ND];
__device__ __align__(16) float g_xkc[NB*NNC*ND];
__device__ __align__(16) float g_xvc[NB*NNC*ND];
__device__ __align__(16) float g_pec[ND];
__device__ __align__(16) float g_pvc[ND];
__device__ __align__(16) float g_tt [NB*NNC*ND];
__device__ __align__(16) float g_imp[NB*NS*NNC];
// K-split partial buffers
__device__ __align__(16) float g_cp  [2*4*128*1024];   // ck/cv partials
__device__ __align__(16) float g_ttp [2*4*64*1024];    // Tt partials
__device__ __align__(16) float g_impp[2*4*1024*64];    // imp partials

// ======================= PTX helpers ================================================
__device__ __forceinline__ void cp16(uint32_t d, const void* s) {
    asm volatile("cp.async.cg.shared.global [%0], [%1], 16;" :: "r"(d), "l"(s));
}
__device__ __forceinline__ void cp_commit() {
    asm volatile("cp.async.commit_group;");
}
__device__ __forceinline__ void cp_wait2() {
    asm volatile("cp.async.wait_group 2;");
}
__device__ __forceinline__ void ldsm_x4(uint32_t& r0, uint32_t& r1, uint32_t& r2, uint32_t& r3,
                                        uint32_t addr) {
    asm volatile("ldmatrix.sync.aligned.m8n8.x4.shared.b16 {%0,%1,%2,%3}, [%4];"
        : "=r"(r0), "=r"(r1), "=r"(r2), "=r"(r3) : "r"(addr));
}
__device__ __forceinline__ void mma16816(float* c, const uint32_t* a, const uint32_t* b) {
    asm volatile("mma.sync.aligned.m16n8k16.row.col.f32.bf16.bf16.f32 "
        "{%0,%1,%2,%3}, {%4,%5,%6,%7}, {%8,%9}, {%0,%1,%2,%3};"
        : "+f"(c[0]), "+f"(c[1]), "+f"(c[2]), "+f"(c[3])
        : "r"(a[0]), "r"(a[1]), "r"(a[2]), "r"(a[3]), "r"(b[0]), "r"(b[1]));
}

// ======================= split conversions =========================================
__global__ __launch_bounds__(256) void split_kernel(
    const float* __restrict__ src, __nv_bfloat16* __restrict__ hi,
    __nv_bfloat16* __restrict__ lo)
{
    int idx = (blockIdx.x * 256 + threadIdx.x) * 4;
    float4 v = *(const float4*)(src + idx);
    __nv_bfloat16 h0 = __float2bfloat16(v.x), h1 = __float2bfloat16(v.y);
    __nv_bfloat16 h2 = __float2bfloat16(v.z), h3 = __float2bfloat16(v.w);
    *(__nv_bfloat162*)(hi + idx)     = __halves2bfloat162(h0, h1);
    *(__nv_bfloat162*)(hi + idx + 2) = __halves2bfloat162(h2, h3);
    *(__nv_bfloat162*)(lo + idx) = __halves2bfloat162(
        __float2bfloat16(v.x - __bfloat162float(h0)),
        __float2bfloat16(v.y - __bfloat162float(h1)));
    *(__nv_bfloat162*)(lo + idx + 2) = __halves2bfloat162(
        __float2bfloat16(v.z - __bfloat162float(h2)),
        __float2bfloat16(v.w - __bfloat162float(h3)));
}

__global__ __launch_bounds__(256) void convert_w4_kernel(
    const float* __restrict__ W0, const float* __restrict__ W1,
    const float* __restrict__ W2, const float* __restrict__ W3,
    __nv_bfloat16* __restrict__ Wh, __nv_bfloat16* __restrict__ Wl,
    __nv_bfloat16* __restrict__ Woh, __nv_bfloat16* __restrict__ Wol)
{
    const int z = blockIdx.z;
    const float* W = (z == 0) ? W0 : (z == 1) ? W1 : (z == 2) ? W2 : W3;
    __nv_bfloat16* Dh = (z == 3) ? Woh : Wh;
    __nv_bfloat16* Dl = (z == 3) ? Wol : Wl;
    const int row_off = (z == 3) ? 0 : z * 1024;

    __shared__ float t[32][33];
    int n0 = blockIdx.x * 32, k0 = blockIdx.y * 32;
    int tx = threadIdx.x & 31, ty = threadIdx.x >> 5;
#pragma unroll
    for (int i = 0; i < 32; i += 8)
        t[ty + i][tx] = W[(k0 + ty + i) * 1024 + n0 + tx];
    __syncthreads();
#pragma unroll
    for (int i = 0; i < 32; i += 8) {
        int n = row_off + n0 + ty + i, k = k0 + tx;
        float v = t[tx][ty + i];
        __nv_bfloat16 h = __float2bfloat16(v);
        Dh[(size_t)n * 1024 + k] = h;
        Dl[(size_t)n * 1024 + k] = __float2bfloat16(v - __bfloat162float(h));
    }
}

// ======================= fused 3-term HMMA GEMM (4-stage) ===========================
__global__ __launch_bounds__(256) void mma_gemm3_kernel(
    const __nv_bfloat16* __restrict__ Ah, const __nv_bfloat16* __restrict__ Al,
    const __nv_bfloat16* __restrict__ Wh, const __nv_bfloat16* __restrict__ Wl,
    float* __restrict__ Cq, float* __restrict__ Ck, float* __restrict__ Cv,
    const float* __restrict__ extra, int qkv_mode)
{
    extern __shared__ __nv_bfloat16 smem[];

    const int tid = threadIdx.x;
    const int wid = tid >> 5, lane = tid & 31;
    const int wm = wid >> 2, wn = wid & 3;
    const int mt = blockIdx.y * BM, nt = blockIdx.x * BN;

    const uint32_t sb = (uint32_t)__cvta_generic_to_shared(smem);
    const uint32_t B_OFF = BM * AST * 2;

    const int lrow = tid >> 1;
    const int lc   = (tid & 1) * 2;
    const size_t aoff = (size_t)(mt + lrow) * KA + lc * 8;
    const size_t boff = (size_t)(nt + lrow) * KA + lc * 8;
    const __nv_bfloat16* aSrc[2] = {Ah + aoff, Al + aoff};
    const __nv_bfloat16* bSrc[2] = {Wh + boff, Wl + boff};
    const uint32_t dA = sb + (lrow * AST + lc * 8) * 2;
    const uint32_t dB = sb + B_OFF + (lrow * AST + lc * 8) * 2;

    float c[4][4][4];
#pragma unroll
    for (int i = 0; i < 4; i++)
#pragma unroll
        for (int j = 0; j < 4; j++)
#pragma unroll
            for (int r = 0; r < 4; r++) c[i][j][r] = 0.f;

    const int al  = lane & 15;
    const int ahi = lane >> 4;

#define ISSUE(j) do {                                                       \
        const int t_  = (j) >> 5;                                           \
        const int k0_ = ((j) & 31) * BK;                                    \
        const __nv_bfloat16* ga_ = aSrc[t_ == 2 ? 1 : 0] + k0_;             \
        const __nv_bfloat16* gb_ = bSrc[t_ == 1 ? 1 : 0] + k0_;             \
        const uint32_t so_ = ((j) & 3) * STAGE_BYTES;                       \
        cp16(dA + so_, ga_);       cp16(dA + so_ + 16, ga_ + 8);            \
        cp16(dB + so_, gb_);       cp16(dB + so_ + 16, gb_ + 8);            \
    } while (0)

    ISSUE(0); cp_commit();
    ISSUE(1); cp_commit();
    ISSUE(2); cp_commit();

    for (int it = 0; it < NIT3; it++) {
        cp_wait2();
        __syncthreads();
        if (it + 3 < NIT3) ISSUE(it + 3);
        cp_commit();

        const uint32_t sA = sb + (it & 3) * STAGE_BYTES;
        const uint32_t sB = sA + B_OFF;
#pragma unroll
        for (int ks = 0; ks < 2; ks++) {
            const int kg = ks * 2 + ahi;
            uint32_t a[4][4], b[4][2];
#pragma unroll
            for (int i = 0; i < 4; i++) {
                uint32_t ad = sA + ((wm * 64 + i * 16 + al) * AST + kg * 8) * 2;
                ldsm_x4(a[i][0], a[i][1], a[i][2], a[i][3], ad);
            }
#pragma unroll
            for (int jj = 0; jj < 2; jj++) {
                uint32_t bd = sB + ((wn * 32 + jj * 16 + al) * AST + kg * 8) * 2;
                uint32_t r0, r1, r2, r3;
                ldsm_x4(r0, r1, r2, r3, bd);
                b[jj * 2 + 0][0] = r0; b[jj * 2 + 1][0] = r1;
                b[jj * 2 + 0][1] = r2; b[jj * 2 + 1][1] = r3;
            }
#pragma unroll
            for (int i = 0; i < 4; i++)
#pragma unroll
                for (int j = 0; j < 4; j++) mma16816(c[i][j], a[i], b[j]);
        }
    }
#undef ISSUE

    float* dst;
    bool add_pe = false;
    int ncol0;
    if (qkv_mode) {
        const int seg = nt >> 10;
        dst = (seg == 0) ? Cq : (seg == 1 ? Ck : Cv);
        add_pe = (seg != 0);
        ncol0 = nt & 1023;
    } else {
        dst = Cq;
        ncol0 = nt;
    }

    const int mbase = mt + wm * 64;
    const int nbase = ncol0 + wn * 32;
    const int rr = lane >> 2, cc = (lane & 3) * 2;
#pragma unroll
    for (int i = 0; i < 4; i++) {
#pragma unroll
        for (int j = 0; j < 4; j++) {
            int row = mbase + i * 16 + rr;
            int col = nbase + j * 8 + cc;
            float2 v0 = make_float2(c[i][j][0], c[i][j][1]);
            float2 v1 = make_float2(c[i][j][2], c[i][j][3]);
            if (qkv_mode) {
                if (add_pe) {
                    const float* p0 = extra + (row & 15) * 1024 + col;
                    const float* p1 = extra + ((row + 8) & 15) * 1024 + col;
                    v0.x += p0[0]; v0.y += p0[1];
                    v1.x += p1[0]; v1.y += p1[1];
                }
            } else {
                v0.x += extra[col]; v0.y += extra[col + 1];
                v1.x += extra[col]; v1.y += extra[col + 1];
            }
            *(float2*)(dst + (size_t)row * 1024 + col)       = v0;
            *(float2*)(dst + (size_t)(row + 8) * 1024 + col) = v1;
        }
    }
}

// ======================= fp32 SGEMM, K-split x4 (ck/cv partials) ====================
// grid (16,1,8): z -> path(=z>>2: 0 k-path, 1 v-path), kc(=z&3). C partial only.
__global__ __launch_bounds__(256) void csgemm_kernel(
    const float* __restrict__ Ak, const float* __restrict__ Av,
    const float* __restrict__ Wk, const float* __restrict__ Wv)
{
    const int path = blockIdx.z >> 2, kc = blockIdx.z & 3;
    const float* A  = path ? Av : Ak;
    const float* Bm = path ? Wv : Wk;
    float* C = g_cp + (size_t)blockIdx.z * (128 * 1024);

    __shared__ float As[16][132];
    __shared__ float Bs[16][64];

    const int tid = threadIdx.x;
    const int bn  = blockIdx.x * 64;
    const int tx  = tid & 15;
    const int ty  = tid >> 4;

    const int arow = tid >> 1;
    const int acol = (tid & 1) * 8;
    const int brow = tid >> 4;
    const int bcol = (tid & 15) * 4;

    float acc[8][4];
#pragma unroll
    for (int i = 0; i < 8; i++)
#pragma unroll
        for (int j = 0; j < 4; j++) acc[i][j] = 0.f;

    const int kbeg = kc * 256, kend = kbeg + 256;
    for (int k0 = kbeg; k0 < kend; k0 += 16) {
        float4 a0 = *(const float4*)(A + arow * 1024 + k0 + acol);
        float4 a1 = *(const float4*)(A + arow * 1024 + k0 + acol + 4);
        As[acol+0][arow] = a0.x; As[acol+1][arow] = a0.y;
        As[acol+2][arow] = a0.z; As[acol+3][arow] = a0.w;
        As[acol+4][arow] = a1.x; As[acol+5][arow] = a1.y;
        As[acol+6][arow] = a1.z; As[acol+7][arow] = a1.w;
        float4 b4 = *(const float4*)(Bm + (k0 + brow) * 1024 + bn + bcol);
        *(float4*)&Bs[brow][bcol] = b4;
        __syncthreads();

#pragma unroll
        for (int kk = 0; kk < 16; kk++) {
            float4 t0 = *(const float4*)&As[kk][ty * 8];
            float4 t1 = *(const float4*)&As[kk][ty * 8 + 4];
            float4 bb = *(const float4*)&Bs[kk][tx * 4];
            float ar[8] = {t0.x, t0.y, t0.z, t0.w, t1.x, t1.y, t1.z, t1.w};
            float br[4] = {bb.x, bb.y, bb.z, bb.w};
#pragma unroll
            for (int i = 0; i < 8; i++)
#pragma unroll
                for (int j = 0; j < 4; j++) acc[i][j] += ar[i] * br[j];
        }
        __syncthreads();
    }

#pragma unroll
    for (int i = 0; i < 8; i++) {
        int m = ty * 8 + i;
#pragma unroll
        for (int j = 0; j < 4; j++)
            C[m * 1024 + bn + tx * 4 + j] = acc[i][j];
    }
}

// reduce ck/cv partials: out = sum4 + bias (path interleaved: g_cp[path*4+kc])
__global__ __launch_bounds__(256) void reduce_ckcv_kernel(
    const float* __restrict__ bk, const float* __restrict__ bv)
{
    int idx = blockIdx.x * 256 + threadIdx.x;     // 2*131072
    int path = idx >> 17, off = idx & 131071;
    const float* P = g_cp + (size_t)path * 4 * 131072;
    float s = P[off] + P[131072 + off] + P[2 * 131072 + off] + P[3 * 131072 + off];
    s += (path ? bv : bk)[off & 1023];
    (path ? g_cv : g_ck)[off] = s;
}

// ======================= fp32 NT GEMM, K-split x4 ===================================
// z = b*4 + kc ; C partial at C + z*cB
__global__ __launch_bounds__(256) void nt_gemm_kernel(
    const float* __restrict__ A, const float* __restrict__ B, float* __restrict__ C,
    int N, long aB, long bB, long cB)
{
    const int b = blockIdx.z >> 2, kc = blockIdx.z & 3;
    const float* Ab = A + (size_t)b * aB;
    const float* Bb = B + (size_t)b * bB;
    float* Cb = C + (size_t)blockIdx.z * cB;

    __shared__ float As[64][33];
    __shared__ float Bs[64][33];

    const int tid = threadIdx.x;
    const int row = tid >> 2;
    const int c4  = (tid & 3) * 8;
    const int ty = tid >> 4, tx = tid & 15;
    const int i0 = blockIdx.y * 64, j0 = blockIdx.x * 64;

    float acc[4][4];
#pragma unroll
    for (int i = 0; i < 4; i++)
#pragma unroll
        for (int j = 0; j < 4; j++) acc[i][j] = 0.f;

    const int kbeg = kc * 256, kend = kbeg + 256;
    for (int k0 = kbeg; k0 < kend; k0 += 32) {
        float4 a0 = *(const float4*)(Ab + (size_t)(i0 + row) * 1024 + k0 + c4);
        float4 a1 = *(const float4*)(Ab + (size_t)(i0 + row) * 1024 + k0 + c4 + 4);
        As[row][c4+0] = a0.x; As[row][c4+1] = a0.y;
        As[row][c4+2] = a0.z; As[row][c4+3] = a0.w;
        As[row][c4+4] = a1.x; As[row][c4+5] = a1.y;
        As[row][c4+6] = a1.z; As[row][c4+7] = a1.w;
        float4 b0 = *(const float4*)(Bb + (size_t)(j0 + row) * 1024 + k0 + c4);
        float4 b1 = *(const float4*)(Bb + (size_t)(j0 + row) * 1024 + k0 + c4 + 4);
        Bs[row][c4+0] = b0.x; Bs[row][c4+1] = b0.y;
        Bs[row][c4+2] = b0.z; Bs[row][c4+3] = b0.w;
        Bs[row][c4+4] = b1.x; Bs[row][c4+5] = b1.y;
        Bs[row][c4+6] = b1.z; Bs[row][c4+7] = b1.w;
        __syncthreads();

#pragma unroll 8
        for (int k = 0; k < 32; k++) {
            float ar[4], br[4];
#pragma unroll
            for (int i = 0; i < 4; i++) ar[i] = As[ty * 4 + i][k];
#pragma unroll
            for (int j = 0; j < 4; j++) br[j] = Bs[tx * 4 + j][k];
#pragma unroll
            for (int i = 0; i < 4; i++)
#pragma unroll
                for (int j = 0; j < 4; j++) acc[i][j] += ar[i] * br[j];
        }
        __syncthreads();
    }

#pragma unroll
    for (int i = 0; i < 4; i++)
#pragma unroll
        for (int j = 0; j < 4; j++)
            Cb[(size_t)(i0 + ty * 4 + i) * N + j0 + tx * 4 + j] = acc[i][j];
}

// generic reduce of 4 K-split partials: out[b][off] = sum_kc P[(b*4+kc)*n + off]
__global__ __launch_bounds__(256) void reduce4_kernel(
    const float* __restrict__ P, float* __restrict__ out, int n)
{
    int idx = blockIdx.x * 256 + threadIdx.x;     // NB*n
    int b = idx / n, off = idx - b * n;
    const float* Pb = P + (size_t)b * 4 * n;
    out[idx] = Pb[off] + Pb[n + off] + Pb[2 * n + off] + Pb[3 * n + off];
}

// ---------------- exact compressed-row inputs ---------------------------------------
__global__ __launch_bounds__(256) void xc_kernel(
    const float* __restrict__ x, const float* __restrict__ wkc,
    const float* __restrict__ wvc)
{
    int idx = blockIdx.x * 256 + threadIdx.x;
    int d = idx & 1023;
    int n = (idx >> 10) & 63;
    int b = idx >> 16;
    const float* xb = x + ((size_t)(b * NS + n * NCB)) * ND + d;
    float sk = 0.f, sv = 0.f;
#pragma unroll
    for (int t = 0; t < NCB; t++) {
        float xv = xb[t * ND];
        sk += wkc[t] * xv;
        sv += wvc[t] * xv;
    }
    g_xkc[idx] = sk;
    g_xvc[idx] = sv;
}

__global__ __launch_bounds__(256) void pe_comb_kernel(
    const float* __restrict__ wpe, const float* __restrict__ wkc,
    const float* __restrict__ wvc)
{
    int d = blockIdx.x * 256 + threadIdx.x;
    float sk = 0.f, sv = 0.f;
#pragma unroll
    for (int t = 0; t < NCB; t++) {
        float p = wpe[t * ND + d];
        sk += wkc[t] * p;
        sv += wvc[t] * p;
    }
    g_pec[d] = sk;
    g_pvc[d] = sv;
}

// ---------------- top-2 ---------------------------------------------------------------
__global__ __launch_bounds__(256) void top2_kernel()
{
    const int bs = blockIdx.x * 8 + (threadIdx.x >> 5);
    const int lane = threadIdx.x & 31;
    const float* row = g_imp + (size_t)bs * 64;
    float v0 = row[lane], v1 = row[lane + 32];

    float bv; int bi;
    if (v0 >= v1) { bv = v0; bi = lane; } else { bv = v1; bi = lane + 32; }
#pragma unroll
    for (int off = 16; off > 0; off >>= 1) {
        float ov = __shfl_xor_sync(0xffffffffu, bv, off);
        int   oi = __shfl_xor_sync(0xffffffffu, bi, off);
        if (ov > bv || (ov == bv && oi < bi)) { bv = ov; bi = oi; }
    }
    int top1 = bi;
    float w0 = (lane == top1)      ? NEG : v0;
    float w1 = (lane + 32 == top1) ? NEG : v1;
    float bv2; int bi2;
    if (w0 >= w1) { bv2 = w0; bi2 = lane; } else { bv2 = w1; bi2 = lane + 32; }
#pragma unroll
    for (int off = 16; off > 0; off >>= 1) {
        float ov = __shfl_xor_sync(0xffffffffu, bv2, off);
        int   oi = __shfl_xor_sync(0xffffffffu, bi2, off);
        if (ov > bv2 || (ov == bv2 && oi < bi2)) { bv2 = ov; bi2 = oi; }
    }
    if (lane == 0) { g_top[bs * 2] = top1; g_top[bs * 2 + 1] = bi2; }
}

// ---------------- register-tiled compressed attention ---------------------------------
// grid (16 s-tiles, 16 h, 2 b), 256 threads, 4x4 outputs/thread.
__global__ __launch_bounds__(256) void comp_attn_tile_kernel()
{
    extern __shared__ float sm[];
    float* Qt = sm;                    // [d][i], stride TS
    float* Kt = sm + 64 * TS;          // [d][n]
    float* Vs = sm + 2 * 64 * TS;      // [n][d]
    float* Ps = sm + 3 * 64 * TS;      // [i][n], stride PS

    const int st = blockIdx.x, h = blockIdx.y, b = blockIdx.z;
    const int tid = threadIdx.x;
    const int ty = tid >> 4, tx = tid & 15;
    const int qbase = st * 64;

    for (int i = tid; i < 4096; i += 256) {
        int r = i >> 6, d = i & 63;
        Qt[d * TS + r] = g_q[((size_t)(b * NS + qbase + r)) * ND + h * 64 + d];
        const size_t gc = ((size_t)(b * 64 + r)) * ND + h * 64 + d;
        Kt[d * TS + r] = g_ck[gc];
        Vs[r * TS + d] = g_cv[gc];
    }
    __syncthreads();

    float s[4][4];
#pragma unroll
    for (int i = 0; i < 4; i++)
#pragma unroll
        for (int j = 0; j < 4; j++) s[i][j] = 0.f;

#pragma unroll 8
    for (int d = 0; d < 64; d++) {
        float4 qv = *(const float4*)&Qt[d * TS + ty * 4];
        float4 kv = *(const float4*)&Kt[d * TS + tx * 4];
        float qa[4] = {qv.x, qv.y, qv.z, qv.w};
        float ka[4] = {kv.x, kv.y, kv.z, kv.w};
#pragma unroll
        for (int i = 0; i < 4; i++)
#pragma unroll
            for (int j = 0; j < 4; j++) s[i][j] += qa[i] * ka[j];
    }
#pragma unroll
    for (int i = 0; i < 4; i++)
#pragma unroll
        for (int j = 0; j < 4; j++)
            Ps[(ty * 4 + i) * PS + tx * 4 + j] = s[i][j] * INVS;
    __syncthreads();

    __shared__ float rowl[64];
    if (tid < 64) {
        float* pr = Ps + tid * PS;
        float m = NEG;
#pragma unroll 8
        for (int c = 0; c < 64; c++) m = fmaxf(m, pr[c]);
        float l = 0.f;
#pragma unroll 8
        for (int c = 0; c < 64; c++) { float p = __expf(pr[c] - m); pr[c] = p; l += p; }
        rowl[tid] = 1.f / l;
    }
    __syncthreads();

    float acc[4][4];
#pragma unroll
    for (int i = 0; i < 4; i++)
#pragma unroll
        for (int j = 0; j < 4; j++) acc[i][j] = 0.f;
#pragma unroll 8
    for (int c = 0; c < 64; c++) {
        float4 vv = *(const float4*)&Vs[c * TS + tx * 4];
        float va[4] = {vv.x, vv.y, vv.z, vv.w};
#pragma unroll
        for (int i = 0; i < 4; i++) {
            float p = Ps[(ty * 4 + i) * PS + c];
#pragma unroll
            for (int j = 0; j < 4; j++) acc[i][j] += p * va[j];
        }
    }
#pragma unroll
    for (int i = 0; i < 4; i++) {
        const float rl = rowl[ty * 4 + i];
        float* orow = g_oc + ((size_t)(b * NS + qbase + ty * 4 + i)) * ND + h * 64 + tx * 4;
        float4 o = make_float4(acc[i][0] * rl, acc[i][1] * rl, acc[i][2] * rl, acc[i][3] * rl);
        *(float4*)orow = o;
    }
}

// ---------------- register-tiled sliding-window attention ------------------------------
__global__ __launch_bounds__(256) void win_attn_kernel()
{
    extern __shared__ float sm[];
    float* Qt = sm;                    // [d][i]
    float* Kt = sm + 64 * TS;          // [d][j]
    float* Vs = sm + 2 * 64 * TS;      // [c][d]
    float* Ps = sm + 3 * 64 * TS;      // [i][c]

    __shared__ float rowm[64], rowl[64], rowsc[64];

    const int qt = blockIdx.x, h = blockIdx.y, b = blockIdx.z;
    const int tid = threadIdx.x;
    const int ty = tid >> 4, tx = tid & 15;
    const int qbase = qt * 64;

    for (int i = tid; i < 4096; i += 256) {
        int r = i >> 6, d = i & 63;
        Qt[d * TS + r] = g_q[((size_t)(b * NS + qbase + r)) * ND + h * 64 + d];
    }
    if (tid < 64) { rowm[tid] = NEG; rowl[tid] = 0.f; }

    float acc[4][4];
#pragma unroll
    for (int i = 0; i < 4; i++)
#pragma unroll
        for (int j = 0; j < 4; j++) acc[i][j] = 0.f;

    const int kt_lo = (qt >= 4) ? qt - 4 : 0;
    for (int kt = kt_lo; kt <= qt; kt++) {
        const int kbase = kt * 64;
        __syncthreads();
        for (int i = tid; i < 4096; i += 256) {
            int r = i >> 6, d = i & 63;
            const size_t g = ((size_t)(b * NS + kbase + r)) * ND + h * 64 + d;
            Kt[d * TS + r] = g_k[g];
            Vs[r * TS + d] = g_v[g];
        }
        __syncthreads();

        float s[4][4];
#pragma unroll
        for (int i = 0; i < 4; i++)
#pragma unroll
            for (int j = 0; j < 4; j++) s[i][j] = 0.f;
#pragma unroll 8
        for (int d = 0; d < 64; d++) {
            float4 qv = *(const float4*)&Qt[d * TS + ty * 4];
            float4 kv = *(const float4*)&Kt[d * TS + tx * 4];
            float qa[4] = {qv.x, qv.y, qv.z, qv.w};
            float ka[4] = {kv.x, kv.y, kv.z, kv.w};
#pragma unroll
            for (int i = 0; i < 4; i++)
#pragma unroll
                for (int j = 0; j < 4; j++) s[i][j] += qa[i] * ka[j];
        }
#pragma unroll
        for (int i = 0; i < 4; i++) {
            const int qi = qbase + ty * 4 + i;
#pragma unroll
            for (int j = 0; j < 4; j++) {
                const int kj = kbase + tx * 4 + j;
                float v = (kj <= qi && qi - kj <= NWIN) ? s[i][j] * INVS : NEG;
                Ps[(ty * 4 + i) * PS + tx * 4 + j] = v;
            }
        }
        __syncthreads();

        if (tid < 64) {
            float* pr = Ps + tid * PS;
            float m = rowm[tid], mn = m;
#pragma unroll 8
            for (int c = 0; c < 64; c++) mn = fmaxf(mn, pr[c]);
            float sc = __expf(m - mn);
            float l = rowl[tid] * sc;
#pragma unroll 8
            for (int c = 0; c < 64; c++) { float p = __expf(pr[c] - mn); pr[c] = p; l += p; }
            rowm[tid] = mn; rowl[tid] = l; rowsc[tid] = sc;
        }
        __syncthreads();

#pragma unroll
        for (int i = 0; i < 4; i++) {
            const float sc = rowsc[ty * 4 + i];
#pragma unroll
            for (int j = 0; j < 4; j++) acc[i][j] *= sc;
        }
#pragma unroll 8
        for (int c = 0; c < 64; c++) {
            float4 vv = *(const float4*)&Vs[c * TS + tx * 4];
            float va[4] = {vv.x, vv.y, vv.z, vv.w};
#pragma unroll
            for (int i = 0; i < 4; i++) {
                float p = Ps[(ty * 4 + i) * PS + c];
#pragma unroll
                for (int j = 0; j < 4; j++) acc[i][j] += p * va[j];
            }
        }
    }

#pragma unroll
    for (int i = 0; i < 4; i++) {
        const float rl = 1.f / rowl[ty * 4 + i];
        float* orow = g_ow + ((size_t)(b * NS + qbase + ty * 4 + i)) * ND + h * 64 + tx * 4;
        float4 o = make_float4(acc[i][0] * rl, acc[i][1] * rl, acc[i][2] * rl, acc[i][3] * rl);
        *(float4*)orow = o;
    }
}

// ---------------- selected attention ---------------------------------------------------
__global__ __launch_bounds__(512) void sel_attn_kernel()
{
    const int bs = blockIdx.x;
    const int b  = bs >> 10, s = bs & 1023;
    const int tid = threadIdx.x;
    const int h = tid >> 5, lane = tid & 31;

    __shared__ int blk_s[2];
    if (tid < 2) blk_s[tid] = g_top[(tid * NS + s) * 2 + b];
    __syncthreads();

    const float2 q2 = *(const float2*)(g_q + bs * ND + h * 64 + lane * 2);

    float myscore = NEG;
#pragma unroll
    for (int m = 0; m < 16; m++) {
        int j = m >> 3, t = m & 7;
        int tok = blk_s[j] * NCB + t;
        float2 k2 = *(const float2*)(g_k + (j * NS + tok) * ND + h * 64 + lane * 2);
        float p = q2.x * k2.x + q2.y * k2.y;
#pragma unroll
        for (int off = 16; off > 0; off >>= 1)
            p += __shfl_xor_sync(0xffffffffu, p, off);
        p *= INVS;
        if (lane == m) myscore = p;
    }
    float mx = myscore;
#pragma unroll
    for (int off = 16; off > 0; off >>= 1)
        mx = fmaxf(mx, __shfl_xor_sync(0xffffffffu, mx, off));
    float p = __expf(myscore - mx);
    float sum = p;
#pragma unroll
    for (int off = 16; off > 0; off >>= 1)
        sum += __shfl_xor_sync(0xffffffffu, sum, off);
    float rs = 1.f / sum;

    float2 acc = make_float2(0.f, 0.f);
#pragma unroll
    for (int m = 0; m < 16; m++) {
        float pm = __shfl_sync(0xffffffffu, p, m);
        int j = m >> 3, t = m & 7;
        int tok = blk_s[j] * NCB + t;
        float2 v2 = *(const float2*)(g_v + (j * NS + tok) * ND + h * 64 + lane * 2);
        acc.x += pm * v2.x; acc.y += pm * v2.y;
    }
    acc.x *= rs; acc.y *= rs;
    *(float2*)(g_os + bs * ND + h * 64 + lane * 2) = acc;
}

// ---------------- gates + combine -------------------------------------------------------
__global__ __launch_bounds__(256) void gate_kernel(
    const float* __restrict__ x, const float* __restrict__ Wg,
    const float* __restrict__ bg)
{
    const int row = blockIdx.x * 8 + (threadIdx.x >> 5);
    const int lane = threadIdx.x & 31;
    const float* xr = x + (size_t)row * ND;
    float a0 = 0.f, a1 = 0.f, a2 = 0.f;
    for (int d = lane; d < ND; d += 32) {
        float xv = xr[d];
        a0 += xv * Wg[d * 3 + 0];
        a1 += xv * Wg[d * 3 + 1];
        a2 += xv * Wg[d * 3 + 2];
    }
#pragma unroll
    for (int off = 16; off > 0; off >>= 1) {
        a0 += __shfl_xor_sync(0xffffffffu, a0, off);
        a1 += __shfl_xor_sync(0xffffffffu, a1, off);
        a2 += __shfl_xor_sync(0xffffffffu, a2, off);
    }
    if (lane == 0) {
        g_gates[row * 3 + 0] = 1.f / (1.f + __expf(-(a0 + bg[0])));
        g_gates[row * 3 + 1] = 1.f / (1.f + __expf(-(a1 + bg[1])));
        g_gates[row * 3 + 2] = 1.f / (1.f + __expf(-(a2 + bg[2])));
    }
}

__global__ __launch_bounds__(256) void combine_kernel()
{
    int idx = blockIdx.x * 256 + threadIdx.x;
    int bs = idx >> 10;
    float g0 = g_gates[bs * 3 + 0];
    float g1 = g_gates[bs * 3 + 1];
    float g2 = g_gates[bs * 3 + 2];
    g_pre[idx] = g0 * g_oc[idx] + g1 * g_os[idx] + g2 * g_ow[idx];
}

// ---------------- launcher ---------------------------------------------------------------
extern "C" void kernel_launch(void* const* d_in, const int* in_sizes, int n_in,
                              void* d_out, int out_size)
{
    (void)in_sizes; (void)n_in; (void)out_size;
    const float* x   = (const float*)d_in[0];
    const float* Wq  = (const float*)d_in[1];
    const float* Wk  = (const float*)d_in[2];
    const float* Wv  = (const float*)d_in[3];
    const float* Wo  = (const float*)d_in[4];
    const float* bo  = (const float*)d_in[5];
    const float* Wg  = (const float*)d_in[6];
    const float* bg  = (const float*)d_in[7];
    const float* wkc = (const float*)d_in[8];
    const float* wvc = (const float*)d_in[9];
    const float* wpe = (const float*)d_in[10];
    float* out = (float*)d_out;

    void *pq, *pk, *pv, *ppre, *pah, *pal, *pwh, *pwl, *pwoh, *pwol;
    void *pxkc, *pxvc, *pck, *pcv, *ptt, *pimp, *ppec, *ppvc;
    void *pttp, *pimpp;
    cudaGetSymbolAddress(&pq,   g_q);
    cudaGetSymbolAddress(&pk,   g_k);
    cudaGetSymbolAddress(&pv,   g_v);
    cudaGetSymbolAddress(&ppre, g_pre);
    cudaGetSymbolAddress(&pah,  g_ah);
    cudaGetSymbolAddress(&pal,  g_al);
    cudaGetSymbolAddress(&pwh,  g_wh);
    cudaGetSymbolAddress(&pwl,  g_wl);
    cudaGetSymbolAddress(&pwoh, g_woh);
    cudaGetSymbolAddress(&pwol, g_wol);
    cudaGetSymbolAddress(&pxkc, g_xkc);
    cudaGetSymbolAddress(&pxvc, g_xvc);
    cudaGetSymbolAddress(&pck,  g_ck);
    cudaGetSymbolAddress(&pcv,  g_cv);
    cudaGetSymbolAddress(&ptt,  g_tt);
    cudaGetSymbolAddress(&pimp, g_imp);
    cudaGetSymbolAddress(&ppec, g_pec);
    cudaGetSymbolAddress(&ppvc, g_pvc);
    cudaGetSymbolAddress(&pttp, g_ttp);
    cudaGetSymbolAddress(&pimpp, g_impp);

    const __nv_bfloat16* ah  = (const __nv_bfloat16*)pah;
    const __nv_bfloat16* alo = (const __nv_bfloat16*)pal;
    const int NEL = NB * NS * ND;

    cudaFuncSetAttribute(mma_gemm3_kernel,
                         cudaFuncAttributeMaxDynamicSharedMemorySize, SMEM_GEMM);
    cudaFuncSetAttribute(win_attn_kernel,
                         cudaFuncAttributeMaxDynamicSharedMemorySize, SMEM_ATT);
    cudaFuncSetAttribute(comp_attn_tile_kernel,
                         cudaFuncAttributeMaxDynamicSharedMemorySize, SMEM_ATT);

    split_kernel<<<NEL / 1024, 256>>>(x, (__nv_bfloat16*)pah, (__nv_bfloat16*)pal);
    convert_w4_kernel<<<dim3(32, 32, 4), 256>>>(
        Wq, Wk, Wv, Wo,
        (__nv_bfloat16*)pwh, (__nv_bfloat16*)pwl,
        (__nv_bfloat16*)pwoh, (__nv_bfloat16*)pwol);

    // fused QKV GEMM
    mma_gemm3_kernel<<<dim3(24, 16), 256, SMEM_GEMM>>>(
        ah, alo, (const __nv_bfloat16*)pwh, (const __nv_bfloat16*)pwl,
        (float*)pq, (float*)pk, (float*)pv, wpe, 1);

    // exact fp32 ck/cv, K-split x4
    xc_kernel<<<(NB * NNC * ND) / 256, 256>>>(x, wkc, wvc);
    pe_comb_kernel<<<ND / 256, 256>>>(wpe, wkc, wvc);
    csgemm_kernel<<<dim3(16, 1, 8), 256>>>(
        (const float*)pxkc, (const float*)pxvc, Wk, Wv);
    reduce_ckcv_kernel<<<(2 * 131072) / 256, 256>>>((const float*)ppec, (const float*)ppvc);

    // exact fp32 imp, K-split x4:  Tt = ck@Wq^T ; imp = x@Tt^T
    nt_gemm_kernel<<<dim3(16, 1, 8), 256>>>((const float*)pck, Wq, (float*)pttp,
                                            1024, 64L * 1024, 0L, 64L * 1024);
    reduce4_kernel<<<(NB * 65536) / 256, 256>>>((const float*)pttp, (float*)ptt, 65536);
    nt_gemm_kernel<<<dim3(1, 16, 8), 256>>>(x, (const float*)ptt, (float*)pimpp,
                                            64, 1024L * 1024, 64L * 1024, 1024L * 64);
    reduce4_kernel<<<(NB * 65536) / 256, 256>>>((const float*)pimpp, (float*)pimp, 65536);
    top2_kernel<<<(NB * NS) / 8, 256>>>();

    // attention branches (register-tiled)
    comp_attn_tile_kernel<<<dim3(16, 16, 2), 256, SMEM_ATT>>>();
    sel_attn_kernel<<<NB * NS, 512>>>();
    win_attn_kernel<<<dim3(NS / 64, NH, NB), 256, SMEM_ATT>>>();

    // gates + combine
    gate_kernel<<<(NB * NS) / 8, 256>>>(x, Wg, bg);
    combine_kernel<<<NEL / 256, 256>>>();

    // fused OUT GEMM
    split_kernel<<<NEL / 1024, 256>>>((const float*)ppre, (__nv_bfloat16*)pah,
                                      (__nv_bfloat16*)pal);
    mma_gemm3_kernel<<<dim3(8, 16), 256, SMEM_GEMM>>>(
        ah, alo, (const __nv_bfloat16*)pwoh, (const __nv_bfloat16*)pwol,
        out, out, out, bo, 0);
}

// round 9
// speedup vs baseline: 2.3705x; 1.1978x over previous
#include <cuda_runtime.h>
#include <cuda_bf16.h>
#include <cstdint>

#define NB   2
#define NS   1024
#define ND   1024
#define NH   16
#define NHD  64
#define NNC  64
#define NCB  16
#define NSB  8
#define NJ   2
#define NWIN 256

#define INVS 0.125f
#define NEG  (-1e30f)

#define KA   1024
#define BM   128
#define BN   128
#define BK   32
#define AST  40
#define NIT3 96
#define STAGE_BYTES ((BM + BN) * AST * 2)
#define SMEM_GEMM   (4 * STAGE_BYTES)

#define TS   68
#define PS   65
#define SMEM_ATT ((3 * 64 * TS + 64 * PS) * 4)   // 68864 B

// ---------------- scratch ----------------
__device__ __align__(16) float g_q [NB*NS*ND];
__device__ __align__(16) float g_k [NB*NS*ND];
__device__ __align__(16) float g_v [NB*NS*ND];
__device__ __align__(16) float g_ck[NB*NNC*ND];
__device__ __align__(16) float g_cv[NB*NNC*ND];
__device__ __align__(16) float g_oc[NB*NS*ND];
__device__ __align__(16) float g_os[NB*NS*ND];
__device__ __align__(16) float g_ow[NB*NS*ND];
__device__ __align__(16) float g_pre[NB*NS*ND];
__device__ int   g_top[NB*NS*NJ];
__device__ __align__(16) float g_gates[NB*NS*3];
__device__ __align__(16) __nv_bfloat16 g_ah[(size_t)NB*NS*ND];
__device__ __align__(16) __nv_bfloat16 g_al[(size_t)NB*NS*ND];
__device__ __align__(16) __nv_bfloat16 g_wh[(size_t)3*ND*ND];
__device__ __align__(16) __nv_bfloat16 g_wl[(size_t)3*ND*ND];
__device__ __align__(16) __nv_bfloat16 g_woh[(size_t)ND*ND];
__device__ __align__(16) __nv_bfloat16 g_wol[(size_t)ND*ND];
__device__ __align__(16) float g_xkc[NB*NNC*ND];
__device__ __align__(16) float g_xvc[NB*NNC*ND];
__device__ __align__(16) float g_pec[ND];
__device__ __align__(16) float g_pvc[ND];
__device__ __align__(16) float g_tt [NB*NNC*ND];
__device__ __align__(16) float g_imp[NB*NS*NNC];
__device__ __align__(16) float g_cp  [2*4*128*1024];
__device__ __align__(16) float g_ttp [2*4*64*1024];
__device__ __align__(16) float g_impp[2*4*1024*64];

// ======================= PTX helpers ================================================
__device__ __forceinline__ void cp16(uint32_t d, const void* s) {
    asm volatile("cp.async.cg.shared.global [%0], [%1], 16;" :: "r"(d), "l"(s));
}
__device__ __forceinline__ void cp_commit() {
    asm volatile("cp.async.commit_group;");
}
__device__ __forceinline__ void cp_wait2() {
    asm volatile("cp.async.wait_group 2;");
}
__device__ __forceinline__ void ldsm_x4(uint32_t& r0, uint32_t& r1, uint32_t& r2, uint32_t& r3,
                                        uint32_t addr) {
    asm volatile("ldmatrix.sync.aligned.m8n8.x4.shared.b16 {%0,%1,%2,%3}, [%4];"
        : "=r"(r0), "=r"(r1), "=r"(r2), "=r"(r3) : "r"(addr));
}
__device__ __forceinline__ void mma16816(float* c, const uint32_t* a, const uint32_t* b) {
    asm volatile("mma.sync.aligned.m16n8k16.row.col.f32.bf16.bf16.f32 "
        "{%0,%1,%2,%3}, {%4,%5,%6,%7}, {%8,%9}, {%0,%1,%2,%3};"
        : "+f"(c[0]), "+f"(c[1]), "+f"(c[2]), "+f"(c[3])
        : "r"(a[0]), "r"(a[1]), "r"(a[2]), "r"(a[3]), "r"(b[0]), "r"(b[1]));
}

// ======================= split conversions =========================================
__global__ __launch_bounds__(256) void split_kernel(
    const float* __restrict__ src, __nv_bfloat16* __restrict__ hi,
    __nv_bfloat16* __restrict__ lo)
{
    int idx = (blockIdx.x * 256 + threadIdx.x) * 4;
    float4 v = *(const float4*)(src + idx);
    __nv_bfloat16 h0 = __float2bfloat16(v.x), h1 = __float2bfloat16(v.y);
    __nv_bfloat16 h2 = __float2bfloat16(v.z), h3 = __float2bfloat16(v.w);
    *(__nv_bfloat162*)(hi + idx)     = __halves2bfloat162(h0, h1);
    *(__nv_bfloat162*)(hi + idx + 2) = __halves2bfloat162(h2, h3);
    *(__nv_bfloat162*)(lo + idx) = __halves2bfloat162(
        __float2bfloat16(v.x - __bfloat162float(h0)),
        __float2bfloat16(v.y - __bfloat162float(h1)));
    *(__nv_bfloat162*)(lo + idx + 2) = __halves2bfloat162(
        __float2bfloat16(v.z - __bfloat162float(h2)),
        __float2bfloat16(v.w - __bfloat162float(h3)));
}

__global__ __launch_bounds__(256) void convert_w4_kernel(
    const float* __restrict__ W0, const float* __restrict__ W1,
    const float* __restrict__ W2, const float* __restrict__ W3,
    __nv_bfloat16* __restrict__ Wh, __nv_bfloat16* __restrict__ Wl,
    __nv_bfloat16* __restrict__ Woh, __nv_bfloat16* __restrict__ Wol)
{
    const int z = blockIdx.z;
    const float* W = (z == 0) ? W0 : (z == 1) ? W1 : (z == 2) ? W2 : W3;
    __nv_bfloat16* Dh = (z == 3) ? Woh : Wh;
    __nv_bfloat16* Dl = (z == 3) ? Wol : Wl;
    const int row_off = (z == 3) ? 0 : z * 1024;

    __shared__ float t[32][33];
    int n0 = blockIdx.x * 32, k0 = blockIdx.y * 32;
    int tx = threadIdx.x & 31, ty = threadIdx.x >> 5;
#pragma unroll
    for (int i = 0; i < 32; i += 8)
        t[ty + i][tx] = W[(k0 + ty + i) * 1024 + n0 + tx];
    __syncthreads();
#pragma unroll
    for (int i = 0; i < 32; i += 8) {
        int n = row_off + n0 + ty + i, k = k0 + tx;
        float v = t[tx][ty + i];
        __nv_bfloat16 h = __float2bfloat16(v);
        Dh[(size_t)n * 1024 + k] = h;
        Dl[(size_t)n * 1024 + k] = __float2bfloat16(v - __bfloat162float(h));
    }
}

// ======================= fused 3-term HMMA GEMM (4-stage) ===========================
__global__ __launch_bounds__(256) void mma_gemm3_kernel(
    const __nv_bfloat16* __restrict__ Ah, const __nv_bfloat16* __restrict__ Al,
    const __nv_bfloat16* __restrict__ Wh, const __nv_bfloat16* __restrict__ Wl,
    float* __restrict__ Cq, float* __restrict__ Ck, float* __restrict__ Cv,
    const float* __restrict__ extra, int qkv_mode)
{
    extern __shared__ __nv_bfloat16 smem[];

    const int tid = threadIdx.x;
    const int wid = tid >> 5, lane = tid & 31;
    const int wm = wid >> 2, wn = wid & 3;
    const int mt = blockIdx.y * BM, nt = blockIdx.x * BN;

    const uint32_t sb = (uint32_t)__cvta_generic_to_shared(smem);
    const uint32_t B_OFF = BM * AST * 2;

    const int lrow = tid >> 1;
    const int lc   = (tid & 1) * 2;
    const size_t aoff = (size_t)(mt + lrow) * KA + lc * 8;
    const size_t boff = (size_t)(nt + lrow) * KA + lc * 8;
    const __nv_bfloat16* aSrc[2] = {Ah + aoff, Al + aoff};
    const __nv_bfloat16* bSrc[2] = {Wh + boff, Wl + boff};
    const uint32_t dA = sb + (lrow * AST + lc * 8) * 2;
    const uint32_t dB = sb + B_OFF + (lrow * AST + lc * 8) * 2;

    float c[4][4][4];
#pragma unroll
    for (int i = 0; i < 4; i++)
#pragma unroll
        for (int j = 0; j < 4; j++)
#pragma unroll
            for (int r = 0; r < 4; r++) c[i][j][r] = 0.f;

    const int al  = lane & 15;
    const int ahi = lane >> 4;

#define ISSUE(j) do {                                                       \
        const int t_  = (j) >> 5;                                           \
        const int k0_ = ((j) & 31) * BK;                                    \
        const __nv_bfloat16* ga_ = aSrc[t_ == 2 ? 1 : 0] + k0_;             \
        const __nv_bfloat16* gb_ = bSrc[t_ == 1 ? 1 : 0] + k0_;             \
        const uint32_t so_ = ((j) & 3) * STAGE_BYTES;                       \
        cp16(dA + so_, ga_);       cp16(dA + so_ + 16, ga_ + 8);            \
        cp16(dB + so_, gb_);       cp16(dB + so_ + 16, gb_ + 8);            \
    } while (0)

    ISSUE(0); cp_commit();
    ISSUE(1); cp_commit();
    ISSUE(2); cp_commit();

    for (int it = 0; it < NIT3; it++) {
        cp_wait2();
        __syncthreads();
        if (it + 3 < NIT3) ISSUE(it + 3);
        cp_commit();

        const uint32_t sA = sb + (it & 3) * STAGE_BYTES;
        const uint32_t sB = sA + B_OFF;
#pragma unroll
        for (int ks = 0; ks < 2; ks++) {
            const int kg = ks * 2 + ahi;
            uint32_t a[4][4], b[4][2];
#pragma unroll
            for (int i = 0; i < 4; i++) {
                uint32_t ad = sA + ((wm * 64 + i * 16 + al) * AST + kg * 8) * 2;
                ldsm_x4(a[i][0], a[i][1], a[i][2], a[i][3], ad);
            }
#pragma unroll
            for (int jj = 0; jj < 2; jj++) {
                uint32_t bd = sB + ((wn * 32 + jj * 16 + al) * AST + kg * 8) * 2;
                uint32_t r0, r1, r2, r3;
                ldsm_x4(r0, r1, r2, r3, bd);
                b[jj * 2 + 0][0] = r0; b[jj * 2 + 1][0] = r1;
                b[jj * 2 + 0][1] = r2; b[jj * 2 + 1][1] = r3;
            }
#pragma unroll
            for (int i = 0; i < 4; i++)
#pragma unroll
                for (int j = 0; j < 4; j++) mma16816(c[i][j], a[i], b[j]);
        }
    }
#undef ISSUE

    float* dst;
    bool add_pe = false;
    int ncol0;
    if (qkv_mode) {
        const int seg = nt >> 10;
        dst = (seg == 0) ? Cq : (seg == 1 ? Ck : Cv);
        add_pe = (seg != 0);
        ncol0 = nt & 1023;
    } else {
        dst = Cq;
        ncol0 = nt;
    }

    const int mbase = mt + wm * 64;
    const int nbase = ncol0 + wn * 32;
    const int rr = lane >> 2, cc = (lane & 3) * 2;
#pragma unroll
    for (int i = 0; i < 4; i++) {
#pragma unroll
        for (int j = 0; j < 4; j++) {
            int row = mbase + i * 16 + rr;
            int col = nbase + j * 8 + cc;
            float2 v0 = make_float2(c[i][j][0], c[i][j][1]);
            float2 v1 = make_float2(c[i][j][2], c[i][j][3]);
            if (qkv_mode) {
                if (add_pe) {
                    const float* p0 = extra + (row & 15) * 1024 + col;
                    const float* p1 = extra + ((row + 8) & 15) * 1024 + col;
                    v0.x += p0[0]; v0.y += p0[1];
                    v1.x += p1[0]; v1.y += p1[1];
                }
            } else {
                v0.x += extra[col]; v0.y += extra[col + 1];
                v1.x += extra[col]; v1.y += extra[col + 1];
            }
            *(float2*)(dst + (size_t)row * 1024 + col)       = v0;
            *(float2*)(dst + (size_t)(row + 8) * 1024 + col) = v1;
        }
    }
}

// ======================= fp32 SGEMM, K-split x4 (ck/cv partials) ====================
__global__ __launch_bounds__(256) void csgemm_kernel(
    const float* __restrict__ Ak, const float* __restrict__ Av,
    const float* __restrict__ Wk, const float* __restrict__ Wv)
{
    const int path = blockIdx.z >> 2, kc = blockIdx.z & 3;
    const float* A  = path ? Av : Ak;
    const float* Bm = path ? Wv : Wk;
    float* C = g_cp + (size_t)blockIdx.z * (128 * 1024);

    __shared__ float As[16][132];
    __shared__ float Bs[16][64];

    const int tid = threadIdx.x;
    const int bn  = blockIdx.x * 64;
    const int tx  = tid & 15;
    const int ty  = tid >> 4;

    const int arow = tid >> 1;
    const int acol = (tid & 1) * 8;
    const int brow = tid >> 4;
    const int bcol = (tid & 15) * 4;

    float acc[8][4];
#pragma unroll
    for (int i = 0; i < 8; i++)
#pragma unroll
        for (int j = 0; j < 4; j++) acc[i][j] = 0.f;

    const int kbeg = kc * 256, kend = kbeg + 256;
    for (int k0 = kbeg; k0 < kend; k0 += 16) {
        float4 a0 = *(const float4*)(A + arow * 1024 + k0 + acol);
        float4 a1 = *(const float4*)(A + arow * 1024 + k0 + acol + 4);
        As[acol+0][arow] = a0.x; As[acol+1][arow] = a0.y;
        As[acol+2][arow] = a0.z; As[acol+3][arow] = a0.w;
        As[acol+4][arow] = a1.x; As[acol+5][arow] = a1.y;
        As[acol+6][arow] = a1.z; As[acol+7][arow] = a1.w;
        float4 b4 = *(const float4*)(Bm + (k0 + brow) * 1024 + bn + bcol);
        *(float4*)&Bs[brow][bcol] = b4;
        __syncthreads();

#pragma unroll
        for (int kk = 0; kk < 16; kk++) {
            float4 t0 = *(const float4*)&As[kk][ty * 8];
            float4 t1 = *(const float4*)&As[kk][ty * 8 + 4];
            float4 bb = *(const float4*)&Bs[kk][tx * 4];
            float ar[8] = {t0.x, t0.y, t0.z, t0.w, t1.x, t1.y, t1.z, t1.w};
            float br[4] = {bb.x, bb.y, bb.z, bb.w};
#pragma unroll
            for (int i = 0; i < 8; i++)
#pragma unroll
                for (int j = 0; j < 4; j++) acc[i][j] += ar[i] * br[j];
        }
        __syncthreads();
    }

#pragma unroll
    for (int i = 0; i < 8; i++) {
        int m = ty * 8 + i;
#pragma unroll
        for (int j = 0; j < 4; j++)
            C[m * 1024 + bn + tx * 4 + j] = acc[i][j];
    }
}

__global__ __launch_bounds__(256) void reduce_ckcv_kernel(
    const float* __restrict__ bk, const float* __restrict__ bv)
{
    int idx = blockIdx.x * 256 + threadIdx.x;
    int path = idx >> 17, off = idx & 131071;
    const float* P = g_cp + (size_t)path * 4 * 131072;
    float s = P[off] + P[131072 + off] + P[2 * 131072 + off] + P[3 * 131072 + off];
    s += (path ? bv : bk)[off & 1023];
    (path ? g_cv : g_ck)[off] = s;
}

// ======================= fp32 NT GEMM, K-split x4 ===================================
__global__ __launch_bounds__(256) void nt_gemm_kernel(
    const float* __restrict__ A, const float* __restrict__ B, float* __restrict__ C,
    int N, long aB, long bB, long cB)
{
    const int b = blockIdx.z >> 2, kc = blockIdx.z & 3;
    const float* Ab = A + (size_t)b * aB;
    const float* Bb = B + (size_t)b * bB;
    float* Cb = C + (size_t)blockIdx.z * cB;

    __shared__ float As[64][33];
    __shared__ float Bs[64][33];

    const int tid = threadIdx.x;
    const int row = tid >> 2;
    const int c4  = (tid & 3) * 8;
    const int ty = tid >> 4, tx = tid & 15;
    const int i0 = blockIdx.y * 64, j0 = blockIdx.x * 64;

    float acc[4][4];
#pragma unroll
    for (int i = 0; i < 4; i++)
#pragma unroll
        for (int j = 0; j < 4; j++) acc[i][j] = 0.f;

    const int kbeg = kc * 256, kend = kbeg + 256;
    for (int k0 = kbeg; k0 < kend; k0 += 32) {
        float4 a0 = *(const float4*)(Ab + (size_t)(i0 + row) * 1024 + k0 + c4);
        float4 a1 = *(const float4*)(Ab + (size_t)(i0 + row) * 1024 + k0 + c4 + 4);
        As[row][c4+0] = a0.x; As[row][c4+1] = a0.y;
        As[row][c4+2] = a0.z; As[row][c4+3] = a0.w;
        As[row][c4+4] = a1.x; As[row][c4+5] = a1.y;
        As[row][c4+6] = a1.z; As[row][c4+7] = a1.w;
        float4 b0 = *(const float4*)(Bb + (size_t)(j0 + row) * 1024 + k0 + c4);
        float4 b1 = *(const float4*)(Bb + (size_t)(j0 + row) * 1024 + k0 + c4 + 4);
        Bs[row][c4+0] = b0.x; Bs[row][c4+1] = b0.y;
        Bs[row][c4+2] = b0.z; Bs[row][c4+3] = b0.w;
        Bs[row][c4+4] = b1.x; Bs[row][c4+5] = b1.y;
        Bs[row][c4+6] = b1.z; Bs[row][c4+7] = b1.w;
        __syncthreads();

#pragma unroll 8
        for (int k = 0; k < 32; k++) {
            float ar[4], br[4];
#pragma unroll
            for (int i = 0; i < 4; i++) ar[i] = As[ty * 4 + i][k];
#pragma unroll
            for (int j = 0; j < 4; j++) br[j] = Bs[tx * 4 + j][k];
#pragma unroll
            for (int i = 0; i < 4; i++)
#pragma unroll
                for (int j = 0; j < 4; j++) acc[i][j] += ar[i] * br[j];
        }
        __syncthreads();
    }

#pragma unroll
    for (int i = 0; i < 4; i++)
#pragma unroll
        for (int j = 0; j < 4; j++)
            Cb[(size_t)(i0 + ty * 4 + i) * N + j0 + tx * 4 + j] = acc[i][j];
}

__global__ __launch_bounds__(256) void reduce4_kernel(
    const float* __restrict__ P, float* __restrict__ out, int n)
{
    int idx = blockIdx.x * 256 + threadIdx.x;
    int b = idx / n, off = idx - b * n;
    const float* Pb = P + (size_t)b * 4 * n;
    out[idx] = Pb[off] + Pb[n + off] + Pb[2 * n + off] + Pb[3 * n + off];
}

// ---------------- exact compressed-row inputs ---------------------------------------
__global__ __launch_bounds__(256) void xc_kernel(
    const float* __restrict__ x, const float* __restrict__ wkc,
    const float* __restrict__ wvc)
{
    int idx = blockIdx.x * 256 + threadIdx.x;
    int d = idx & 1023;
    int n = (idx >> 10) & 63;
    int b = idx >> 16;
    const float* xb = x + ((size_t)(b * NS + n * NCB)) * ND + d;
    float sk = 0.f, sv = 0.f;
#pragma unroll
    for (int t = 0; t < NCB; t++) {
        float xv = xb[t * ND];
        sk += wkc[t] * xv;
        sv += wvc[t] * xv;
    }
    g_xkc[idx] = sk;
    g_xvc[idx] = sv;
}

__global__ __launch_bounds__(256) void pe_comb_kernel(
    const float* __restrict__ wpe, const float* __restrict__ wkc,
    const float* __restrict__ wvc)
{
    int d = blockIdx.x * 256 + threadIdx.x;
    float sk = 0.f, sv = 0.f;
#pragma unroll
    for (int t = 0; t < NCB; t++) {
        float p = wpe[t * ND + d];
        sk += wkc[t] * p;
        sv += wvc[t] * p;
    }
    g_pec[d] = sk;
    g_pvc[d] = sv;
}

// ---------------- top-2 ---------------------------------------------------------------
__global__ __launch_bounds__(256) void top2_kernel()
{
    const int bs = blockIdx.x * 8 + (threadIdx.x >> 5);
    const int lane = threadIdx.x & 31;
    const float* row = g_imp + (size_t)bs * 64;
    float v0 = row[lane], v1 = row[lane + 32];

    float bv; int bi;
    if (v0 >= v1) { bv = v0; bi = lane; } else { bv = v1; bi = lane + 32; }
#pragma unroll
    for (int off = 16; off > 0; off >>= 1) {
        float ov = __shfl_xor_sync(0xffffffffu, bv, off);
        int   oi = __shfl_xor_sync(0xffffffffu, bi, off);
        if (ov > bv || (ov == bv && oi < bi)) { bv = ov; bi = oi; }
    }
    int top1 = bi;
    float w0 = (lane == top1)      ? NEG : v0;
    float w1 = (lane + 32 == top1) ? NEG : v1;
    float bv2; int bi2;
    if (w0 >= w1) { bv2 = w0; bi2 = lane; } else { bv2 = w1; bi2 = lane + 32; }
#pragma unroll
    for (int off = 16; off > 0; off >>= 1) {
        float ov = __shfl_xor_sync(0xffffffffu, bv2, off);
        int   oi = __shfl_xor_sync(0xffffffffu, bi2, off);
        if (ov > bv2 || (ov == bv2 && oi < bi2)) { bv2 = ov; bi2 = oi; }
    }
    if (lane == 0) { g_top[bs * 2] = top1; g_top[bs * 2 + 1] = bi2; }
}

// ---------------- register-tiled compressed attention ---------------------------------
__global__ __launch_bounds__(256) void comp_attn_tile_kernel()
{
    extern __shared__ float sm[];
    float* Qt = sm;
    float* Kt = sm + 64 * TS;
    float* Vs = sm + 2 * 64 * TS;
    float* Ps = sm + 3 * 64 * TS;

    const int st = blockIdx.x, h = blockIdx.y, b = blockIdx.z;
    const int tid = threadIdx.x;
    const int ty = tid >> 4, tx = tid & 15;
    const int qbase = st * 64;

    for (int i = tid; i < 4096; i += 256) {
        int r = i >> 6, d = i & 63;
        Qt[d * TS + r] = g_q[((size_t)(b * NS + qbase + r)) * ND + h * 64 + d];
        const size_t gc = ((size_t)(b * 64 + r)) * ND + h * 64 + d;
        Kt[d * TS + r] = g_ck[gc];
        Vs[r * TS + d] = g_cv[gc];
    }
    __syncthreads();

    float s[4][4];
#pragma unroll
    for (int i = 0; i < 4; i++)
#pragma unroll
        for (int j = 0; j < 4; j++) s[i][j] = 0.f;

#pragma unroll 8
    for (int d = 0; d < 64; d++) {
        float4 qv = *(const float4*)&Qt[d * TS + ty * 4];
        float4 kv = *(const float4*)&Kt[d * TS + tx * 4];
        float qa[4] = {qv.x, qv.y, qv.z, qv.w};
        float ka[4] = {kv.x, kv.y, kv.z, kv.w};
#pragma unroll
        for (int i = 0; i < 4; i++)
#pragma unroll
            for (int j = 0; j < 4; j++) s[i][j] += qa[i] * ka[j];
    }
#pragma unroll
    for (int i = 0; i < 4; i++)
#pragma unroll
        for (int j = 0; j < 4; j++)
            Ps[(ty * 4 + i) * PS + tx * 4 + j] = s[i][j] * INVS;
    __syncthreads();

    __shared__ float rowl[64];
    if (tid < 64) {
        float* pr = Ps + tid * PS;
        float m = NEG;
#pragma unroll 8
        for (int c = 0; c < 64; c++) m = fmaxf(m, pr[c]);
        float l = 0.f;
#pragma unroll 8
        for (int c = 0; c < 64; c++) { float p = __expf(pr[c] - m); pr[c] = p; l += p; }
        rowl[tid] = 1.f / l;
    }
    __syncthreads();

    float acc[4][4];
#pragma unroll
    for (int i = 0; i < 4; i++)
#pragma unroll
        for (int j = 0; j < 4; j++) acc[i][j] = 0.f;
#pragma unroll 8
    for (int c = 0; c < 64; c++) {
        float4 vv = *(const float4*)&Vs[c * TS + tx * 4];
        float va[4] = {vv.x, vv.y, vv.z, vv.w};
#pragma unroll
        for (int i = 0; i < 4; i++) {
            float p = Ps[(ty * 4 + i) * PS + c];
#pragma unroll
            for (int j = 0; j < 4; j++) acc[i][j] += p * va[j];
        }
    }
#pragma unroll
    for (int i = 0; i < 4; i++) {
        const float rl = rowl[ty * 4 + i];
        float* orow = g_oc + ((size_t)(b * NS + qbase + ty * 4 + i)) * ND + h * 64 + tx * 4;
        float4 o = make_float4(acc[i][0] * rl, acc[i][1] * rl, acc[i][2] * rl, acc[i][3] * rl);
        *(float4*)orow = o;
    }
}

// ---------------- register-tiled sliding-window attention ------------------------------
__global__ __launch_bounds__(256) void win_attn_kernel()
{
    extern __shared__ float sm[];
    float* Qt = sm;
    float* Kt = sm + 64 * TS;
    float* Vs = sm + 2 * 64 * TS;
    float* Ps = sm + 3 * 64 * TS;

    __shared__ float rowm[64], rowl[64], rowsc[64];

    const int qt = blockIdx.x, h = blockIdx.y, b = blockIdx.z;
    const int tid = threadIdx.x;
    const int ty = tid >> 4, tx = tid & 15;
    const int qbase = qt * 64;

    for (int i = tid; i < 4096; i += 256) {
        int r = i >> 6, d = i & 63;
        Qt[d * TS + r] = g_q[((size_t)(b * NS + qbase + r)) * ND + h * 64 + d];
    }
    if (tid < 64) { rowm[tid] = NEG; rowl[tid] = 0.f; }

    float acc[4][4];
#pragma unroll
    for (int i = 0; i < 4; i++)
#pragma unroll
        for (int j = 0; j < 4; j++) acc[i][j] = 0.f;

    const int kt_lo = (qt >= 4) ? qt - 4 : 0;
    for (int kt = kt_lo; kt <= qt; kt++) {
        const int kbase = kt * 64;
        __syncthreads();
        for (int i = tid; i < 4096; i += 256) {
            int r = i >> 6, d = i & 63;
            const size_t g = ((size_t)(b * NS + kbase + r)) * ND + h * 64 + d;
            Kt[d * TS + r] = g_k[g];
            Vs[r * TS + d] = g_v[g];
        }
        __syncthreads();

        float s[4][4];
#pragma unroll
        for (int i = 0; i < 4; i++)
#pragma unroll
            for (int j = 0; j < 4; j++) s[i][j] = 0.f;
#pragma unroll 8
        for (int d = 0; d < 64; d++) {
            float4 qv = *(const float4*)&Qt[d * TS + ty * 4];
            float4 kv = *(const float4*)&Kt[d * TS + tx * 4];
            float qa[4] = {qv.x, qv.y, qv.z, qv.w};
            float ka[4] = {kv.x, kv.y, kv.z, kv.w};
#pragma unroll
            for (int i = 0; i < 4; i++)
#pragma unroll
                for (int j = 0; j < 4; j++) s[i][j] += qa[i] * ka[j];
        }
#pragma unroll
        for (int i = 0; i < 4; i++) {
            const int qi = qbase + ty * 4 + i;
#pragma unroll
            for (int j = 0; j < 4; j++) {
                const int kj = kbase + tx * 4 + j;
                float v = (kj <= qi && qi - kj <= NWIN) ? s[i][j] * INVS : NEG;
                Ps[(ty * 4 + i) * PS + tx * 4 + j] = v;
            }
        }
        __syncthreads();

        if (tid < 64) {
            float* pr = Ps + tid * PS;
            float m = rowm[tid], mn = m;
#pragma unroll 8
            for (int c = 0; c < 64; c++) mn = fmaxf(mn, pr[c]);
            float sc = __expf(m - mn);
            float l = rowl[tid] * sc;
#pragma unroll 8
            for (int c = 0; c < 64; c++) { float p = __expf(pr[c] - mn); pr[c] = p; l += p; }
            rowm[tid] = mn; rowl[tid] = l; rowsc[tid] = sc;
        }
        __syncthreads();

#pragma unroll
        for (int i = 0; i < 4; i++) {
            const float sc = rowsc[ty * 4 + i];
#pragma unroll
            for (int j = 0; j < 4; j++) acc[i][j] *= sc;
        }
#pragma unroll 8
        for (int c = 0; c < 64; c++) {
            float4 vv = *(const float4*)&Vs[c * TS + tx * 4];
            float va[4] = {vv.x, vv.y, vv.z, vv.w};
#pragma unroll
            for (int i = 0; i < 4; i++) {
                float p = Ps[(ty * 4 + i) * PS + c];
#pragma unroll
                for (int j = 0; j < 4; j++) acc[i][j] += p * va[j];
            }
        }
    }

#pragma unroll
    for (int i = 0; i < 4; i++) {
        const float rl = 1.f / rowl[ty * 4 + i];
        float* orow = g_ow + ((size_t)(b * NS + qbase + ty * 4 + i)) * ND + h * 64 + tx * 4;
        float4 o = make_float4(acc[i][0] * rl, acc[i][1] * rl, acc[i][2] * rl, acc[i][3] * rl);
        *(float4*)orow = o;
    }
}

// ---------------- selected attention ---------------------------------------------------
__global__ __launch_bounds__(512) void sel_attn_kernel()
{
    const int bs = blockIdx.x;
    const int b  = bs >> 10, s = bs & 1023;
    const int tid = threadIdx.x;
    const int h = tid >> 5, lane = tid & 31;

    __shared__ int blk_s[2];
    if (tid < 2) blk_s[tid] = g_top[(tid * NS + s) * 2 + b];
    __syncthreads();

    const float2 q2 = *(const float2*)(g_q + bs * ND + h * 64 + lane * 2);

    float myscore = NEG;
#pragma unroll
    for (int m = 0; m < 16; m++) {
        int j = m >> 3, t = m & 7;
        int tok = blk_s[j] * NCB + t;
        float2 k2 = *(const float2*)(g_k + (j * NS + tok) * ND + h * 64 + lane * 2);
        float p = q2.x * k2.x + q2.y * k2.y;
#pragma unroll
        for (int off = 16; off > 0; off >>= 1)
            p += __shfl_xor_sync(0xffffffffu, p, off);
        p *= INVS;
        if (lane == m) myscore = p;
    }
    float mx = myscore;
#pragma unroll
    for (int off = 16; off > 0; off >>= 1)
        mx = fmaxf(mx, __shfl_xor_sync(0xffffffffu, mx, off));
    float p = __expf(myscore - mx);
    float sum = p;
#pragma unroll
    for (int off = 16; off > 0; off >>= 1)
        sum += __shfl_xor_sync(0xffffffffu, sum, off);
    float rs = 1.f / sum;

    float2 acc = make_float2(0.f, 0.f);
#pragma unroll
    for (int m = 0; m < 16; m++) {
        float pm = __shfl_sync(0xffffffffu, p, m);
        int j = m >> 3, t = m & 7;
        int tok = blk_s[j] * NCB + t;
        float2 v2 = *(const float2*)(g_v + (j * NS + tok) * ND + h * 64 + lane * 2);
        acc.x += pm * v2.x; acc.y += pm * v2.y;
    }
    acc.x *= rs; acc.y *= rs;
    *(float2*)(g_os + bs * ND + h * 64 + lane * 2) = acc;
}

// ---------------- gates + combine -------------------------------------------------------
__global__ __launch_bounds__(256) void gate_kernel(
    const float* __restrict__ x, const float* __restrict__ Wg,
    const float* __restrict__ bg)
{
    const int row = blockIdx.x * 8 + (threadIdx.x >> 5);
    const int lane = threadIdx.x & 31;
    const float* xr = x + (size_t)row * ND;
    float a0 = 0.f, a1 = 0.f, a2 = 0.f;
    for (int d = lane; d < ND; d += 32) {
        float xv = xr[d];
        a0 += xv * Wg[d * 3 + 0];
        a1 += xv * Wg[d * 3 + 1];
        a2 += xv * Wg[d * 3 + 2];
    }
#pragma unroll
    for (int off = 16; off > 0; off >>= 1) {
        a0 += __shfl_xor_sync(0xffffffffu, a0, off);
        a1 += __shfl_xor_sync(0xffffffffu, a1, off);
        a2 += __shfl_xor_sync(0xffffffffu, a2, off);
    }
    if (lane == 0) {
        g_gates[row * 3 + 0] = 1.f / (1.f + __expf(-(a0 + bg[0])));
        g_gates[row * 3 + 1] = 1.f / (1.f + __expf(-(a1 + bg[1])));
        g_gates[row * 3 + 2] = 1.f / (1.f + __expf(-(a2 + bg[2])));
    }
}

__global__ __launch_bounds__(256) void combine_kernel()
{
    int idx = blockIdx.x * 256 + threadIdx.x;
    int bs = idx >> 10;
    float g0 = g_gates[bs * 3 + 0];
    float g1 = g_gates[bs * 3 + 1];
    float g2 = g_gates[bs * 3 + 2];
    g_pre[idx] = g0 * g_oc[idx] + g1 * g_os[idx] + g2 * g_ow[idx];
}

// ---------------- launcher ---------------------------------------------------------------
extern "C" void kernel_launch(void* const* d_in, const int* in_sizes, int n_in,
                              void* d_out, int out_size)
{
    (void)in_sizes; (void)n_in; (void)out_size;
    const float* x   = (const float*)d_in[0];
    const float* Wq  = (const float*)d_in[1];
    const float* Wk  = (const float*)d_in[2];
    const float* Wv  = (const float*)d_in[3];
    const float* Wo  = (const float*)d_in[4];
    const float* bo  = (const float*)d_in[5];
    const float* Wg  = (const float*)d_in[6];
    const float* bg  = (const float*)d_in[7];
    const float* wkc = (const float*)d_in[8];
    const float* wvc = (const float*)d_in[9];
    const float* wpe = (const float*)d_in[10];
    float* out = (float*)d_out;

    void *pq, *pk, *pv, *ppre, *pah, *pal, *pwh, *pwl, *pwoh, *pwol;
    void *pxkc, *pxvc, *pck, *pcv, *ptt, *pimp, *ppec, *ppvc, *pttp, *pimpp;
    cudaGetSymbolAddress(&pq,   g_q);
    cudaGetSymbolAddress(&pk,   g_k);
    cudaGetSymbolAddress(&pv,   g_v);
    cudaGetSymbolAddress(&ppre, g_pre);
    cudaGetSymbolAddress(&pah,  g_ah);
    cudaGetSymbolAddress(&pal,  g_al);
    cudaGetSymbolAddress(&pwh,  g_wh);
    cudaGetSymbolAddress(&pwl,  g_wl);
    cudaGetSymbolAddress(&pwoh, g_woh);
    cudaGetSymbolAddress(&pwol, g_wol);
    cudaGetSymbolAddress(&pxkc, g_xkc);
    cudaGetSymbolAddress(&pxvc, g_xvc);
    cudaGetSymbolAddress(&pck,  g_ck);
    cudaGetSymbolAddress(&pcv,  g_cv);
    cudaGetSymbolAddress(&ptt,  g_tt);
    cudaGetSymbolAddress(&pimp, g_imp);
    cudaGetSymbolAddress(&ppec, g_pec);
    cudaGetSymbolAddress(&ppvc, g_pvc);
    cudaGetSymbolAddress(&pttp, g_ttp);
    cudaGetSymbolAddress(&pimpp, g_impp);

    const __nv_bfloat16* ah  = (const __nv_bfloat16*)pah;
    const __nv_bfloat16* alo = (const __nv_bfloat16*)pal;
    const int NEL = NB * NS * ND;

    // one-time setup (first call is the non-captured correctness run)
    static bool inited = false;
    static cudaStream_t sB, sC;
    static cudaEvent_t e0, e1, eB, eC;
    if (!inited) {
        cudaStreamCreateWithFlags(&sB, cudaStreamNonBlocking);
        cudaStreamCreateWithFlags(&sC, cudaStreamNonBlocking);
        cudaEventCreateWithFlags(&e0, cudaEventDisableTiming);
        cudaEventCreateWithFlags(&e1, cudaEventDisableTiming);
        cudaEventCreateWithFlags(&eB, cudaEventDisableTiming);
        cudaEventCreateWithFlags(&eC, cudaEventDisableTiming);
        cudaFuncSetAttribute(mma_gemm3_kernel,
                             cudaFuncAttributeMaxDynamicSharedMemorySize, SMEM_GEMM);
        cudaFuncSetAttribute(win_attn_kernel,
                             cudaFuncAttributeMaxDynamicSharedMemorySize, SMEM_ATT);
        cudaFuncSetAttribute(comp_attn_tile_kernel,
                             cudaFuncAttributeMaxDynamicSharedMemorySize, SMEM_ATT);
        inited = true;
    }

    // fork side streams off the main (capture-origin) stream
    cudaEventRecord(e0, 0);
    cudaStreamWaitEvent(sB, e0, 0);
    cudaStreamWaitEvent(sC, e0, 0);

    // ---- main stream: bf16 prep + QKV GEMM ----
    split_kernel<<<NEL / 1024, 256>>>(x, (__nv_bfloat16*)pah, (__nv_bfloat16*)pal);
    convert_w4_kernel<<<dim3(32, 32, 4), 256>>>(
        Wq, Wk, Wv, Wo,
        (__nv_bfloat16*)pwh, (__nv_bfloat16*)pwl,
        (__nv_bfloat16*)pwoh, (__nv_bfloat16*)pwol);
    mma_gemm3_kernel<<<dim3(24, 16), 256, SMEM_GEMM>>>(
        ah, alo, (const __nv_bfloat16*)pwh, (const __nv_bfloat16*)pwl,
        (float*)pq, (float*)pk, (float*)pv, wpe, 1);
    cudaEventRecord(e1, 0);

    // ---- stream B: exact fp32 top-k chain (independent of QKV GEMM) ----
    xc_kernel<<<(NB * NNC * ND) / 256, 256, 0, sB>>>(x, wkc, wvc);
    pe_comb_kernel<<<ND / 256, 256, 0, sB>>>(wpe, wkc, wvc);
    csgemm_kernel<<<dim3(16, 1, 8), 256, 0, sB>>>(
        (const float*)pxkc, (const float*)pxvc, Wk, Wv);
    reduce_ckcv_kernel<<<(2 * 131072) / 256, 256, 0, sB>>>(
        (const float*)ppec, (const float*)ppvc);
    nt_gemm_kernel<<<dim3(16, 1, 8), 256, 0, sB>>>(
        (const float*)pck, Wq, (float*)pttp, 1024, 64L * 1024, 0L, 64L * 1024);
    reduce4_kernel<<<(NB * 65536) / 256, 256, 0, sB>>>(
        (const float*)pttp, (float*)ptt, 65536);
    nt_gemm_kernel<<<dim3(1, 16, 8), 256, 0, sB>>>(
        x, (const float*)ptt, (float*)pimpp, 64, 1024L * 1024, 64L * 1024, 1024L * 64);
    reduce4_kernel<<<(NB * 65536) / 256, 256, 0, sB>>>(
        (const float*)pimpp, (float*)pimp, 65536);
    top2_kernel<<<(NB * NS) / 8, 256, 0, sB>>>();
    // after QKV done: comp + sel on sB (overlaps win_attn on main)
    cudaStreamWaitEvent(sB, e1, 0);
    comp_attn_tile_kernel<<<dim3(16, 16, 2), 256, SMEM_ATT, sB>>>();
    sel_attn_kernel<<<NB * NS, 512, 0, sB>>>();
    cudaEventRecord(eB, sB);

    // ---- stream C: gates (depends only on x) ----
    gate_kernel<<<(NB * NS) / 8, 256, 0, sC>>>(x, Wg, bg);
    cudaEventRecord(eC, sC);

    // ---- main: window attention, then join and finish ----
    win_attn_kernel<<<dim3(NS / 64, NH, NB), 256, SMEM_ATT>>>();
    cudaStreamWaitEvent(0, eB, 0);
    cudaStreamWaitEvent(0, eC, 0);
    combine_kernel<<<NEL / 256, 256>>>();
    split_kernel<<<NEL / 1024, 256>>>((const float*)ppre, (__nv_bfloat16*)pah,
                                      (__nv_bfloat16*)pal);
    mma_gemm3_kernel<<<dim3(8, 16), 256, SMEM_GEMM>>>(
        ah, alo, (const __nv_bfloat16*)pwoh, (const __nv_bfloat16*)pwol,
        out, out, out, bo, 0);
}

// round 10
// speedup vs baseline: 2.4529x; 1.0347x over previous
#include <cuda_runtime.h>
#include <cuda_bf16.h>
#include <cstdint>

#define NB   2
#define NS   1024
#define ND   1024
#define NH   16
#define NHD  64
#define NNC  64
#define NCB  16
#define NSB  8
#define NJ   2
#define NWIN 256

#define INVS 0.125f
#define NEG  (-1e30f)

#define KA   1024
#define BM   128
#define BN   128
#define BK   32
#define AST  40
#define NIT3 96
#define STAGE_BYTES ((BM + BN) * AST * 2)
#define SMEM_GEMM   (4 * STAGE_BYTES)

#define TS   68
#define PS   65
#define SMEM_ATT ((3 * 64 * TS + 64 * PS) * 4)   // 68864 B

// ---------------- scratch ----------------
__device__ __align__(16) float g_q [NB*NS*ND];
__device__ __align__(16) float g_k [NB*NS*ND];
__device__ __align__(16) float g_v [NB*NS*ND];
__device__ __align__(16) float g_ck[NB*NNC*ND];
__device__ __align__(16) float g_cv[NB*NNC*ND];
__device__ __align__(16) float g_oc[NB*NS*ND];
__device__ __align__(16) float g_os[NB*NS*ND];
__device__ __align__(16) float g_ow[NB*NS*ND];
__device__ int   g_top[NB*NS*NJ];
__device__ __align__(16) float g_gates[NB*NS*3];
__device__ __align__(16) __nv_bfloat16 g_ah[(size_t)NB*NS*ND];
__device__ __align__(16) __nv_bfloat16 g_al[(size_t)NB*NS*ND];
__device__ __align__(16) __nv_bfloat16 g_wh[(size_t)3*ND*ND];
__device__ __align__(16) __nv_bfloat16 g_wl[(size_t)3*ND*ND];
__device__ __align__(16) __nv_bfloat16 g_woh[(size_t)ND*ND];
__device__ __align__(16) __nv_bfloat16 g_wol[(size_t)ND*ND];
__device__ __align__(16) float g_xkc[NB*NNC*ND];
__device__ __align__(16) float g_xvc[NB*NNC*ND];
__device__ __align__(16) float g_pec[ND];
__device__ __align__(16) float g_pvc[ND];
__device__ __align__(16) float g_tt [NB*NNC*ND];
__device__ __align__(16) float g_imp[NB*NS*NNC];
__device__ __align__(16) float g_cp  [2*4*128*1024];
__device__ __align__(16) float g_ttp [2*4*64*1024];
__device__ __align__(16) float g_impp[2*4*1024*64];

// ======================= PTX helpers ================================================
__device__ __forceinline__ void cp16(uint32_t d, const void* s) {
    asm volatile("cp.async.cg.shared.global [%0], [%1], 16;" :: "r"(d), "l"(s));
}
__device__ __forceinline__ void cp_commit() {
    asm volatile("cp.async.commit_group;");
}
__device__ __forceinline__ void cp_wait2() {
    asm volatile("cp.async.wait_group 2;");
}
__device__ __forceinline__ void ldsm_x4(uint32_t& r0, uint32_t& r1, uint32_t& r2, uint32_t& r3,
                                        uint32_t addr) {
    asm volatile("ldmatrix.sync.aligned.m8n8.x4.shared.b16 {%0,%1,%2,%3}, [%4];"
        : "=r"(r0), "=r"(r1), "=r"(r2), "=r"(r3) : "r"(addr));
}
__device__ __forceinline__ void mma16816(float* c, const uint32_t* a, const uint32_t* b) {
    asm volatile("mma.sync.aligned.m16n8k16.row.col.f32.bf16.bf16.f32 "
        "{%0,%1,%2,%3}, {%4,%5,%6,%7}, {%8,%9}, {%0,%1,%2,%3};"
        : "+f"(c[0]), "+f"(c[1]), "+f"(c[2]), "+f"(c[3])
        : "r"(a[0]), "r"(a[1]), "r"(a[2]), "r"(a[3]), "r"(b[0]), "r"(b[1]));
}

// ======================= split conversions =========================================
__global__ __launch_bounds__(256) void split_kernel(
    const float* __restrict__ src, __nv_bfloat16* __restrict__ hi,
    __nv_bfloat16* __restrict__ lo)
{
    int idx = (blockIdx.x * 256 + threadIdx.x) * 4;
    float4 v = *(const float4*)(src + idx);
    __nv_bfloat16 h0 = __float2bfloat16(v.x), h1 = __float2bfloat16(v.y);
    __nv_bfloat16 h2 = __float2bfloat16(v.z), h3 = __float2bfloat16(v.w);
    *(__nv_bfloat162*)(hi + idx)     = __halves2bfloat162(h0, h1);
    *(__nv_bfloat162*)(hi + idx + 2) = __halves2bfloat162(h2, h3);
    *(__nv_bfloat162*)(lo + idx) = __halves2bfloat162(
        __float2bfloat16(v.x - __bfloat162float(h0)),
        __float2bfloat16(v.y - __bfloat162float(h1)));
    *(__nv_bfloat162*)(lo + idx + 2) = __halves2bfloat162(
        __float2bfloat16(v.z - __bfloat162float(h2)),
        __float2bfloat16(v.w - __bfloat162float(h3)));
}

// z=0..2 -> Wq/Wk/Wv into g_wh/g_wl at row_off z*1024
__global__ __launch_bounds__(256) void convert_w3_kernel(
    const float* __restrict__ W0, const float* __restrict__ W1,
    const float* __restrict__ W2,
    __nv_bfloat16* __restrict__ Wh, __nv_bfloat16* __restrict__ Wl)
{
    const int z = blockIdx.z;
    const float* W = (z == 0) ? W0 : (z == 1) ? W1 : W2;
    const int row_off = z * 1024;

    __shared__ float t[32][33];
    int n0 = blockIdx.x * 32, k0 = blockIdx.y * 32;
    int tx = threadIdx.x & 31, ty = threadIdx.x >> 5;
#pragma unroll
    for (int i = 0; i < 32; i += 8)
        t[ty + i][tx] = W[(k0 + ty + i) * 1024 + n0 + tx];
    __syncthreads();
#pragma unroll
    for (int i = 0; i < 32; i += 8) {
        int n = row_off + n0 + ty + i, k = k0 + tx;
        float v = t[tx][ty + i];
        __nv_bfloat16 h = __float2bfloat16(v);
        Wh[(size_t)n * 1024 + k] = h;
        Wl[(size_t)n * 1024 + k] = __float2bfloat16(v - __bfloat162float(h));
    }
}

__global__ __launch_bounds__(256) void convert_w1_kernel(
    const float* __restrict__ W,
    __nv_bfloat16* __restrict__ Wh, __nv_bfloat16* __restrict__ Wl)
{
    __shared__ float t[32][33];
    int n0 = blockIdx.x * 32, k0 = blockIdx.y * 32;
    int tx = threadIdx.x & 31, ty = threadIdx.x >> 5;
#pragma unroll
    for (int i = 0; i < 32; i += 8)
        t[ty + i][tx] = W[(k0 + ty + i) * 1024 + n0 + tx];
    __syncthreads();
#pragma unroll
    for (int i = 0; i < 32; i += 8) {
        int n = n0 + ty + i, k = k0 + tx;
        float v = t[tx][ty + i];
        __nv_bfloat16 h = __float2bfloat16(v);
        Wh[(size_t)n * 1024 + k] = h;
        Wl[(size_t)n * 1024 + k] = __float2bfloat16(v - __bfloat162float(h));
    }
}

// ======================= fused 3-term HMMA GEMM (4-stage, 2 CTA/SM) =================
__global__ void __launch_bounds__(256, 2) mma_gemm3_kernel(
    const __nv_bfloat16* __restrict__ Ah, const __nv_bfloat16* __restrict__ Al,
    const __nv_bfloat16* __restrict__ Wh, const __nv_bfloat16* __restrict__ Wl,
    float* __restrict__ Cq, float* __restrict__ Ck, float* __restrict__ Cv,
    const float* __restrict__ extra, int qkv_mode)
{
    extern __shared__ __nv_bfloat16 smem[];

    const int tid = threadIdx.x;
    const int wid = tid >> 5, lane = tid & 31;
    const int wm = wid >> 2, wn = wid & 3;
    const int mt = blockIdx.y * BM, nt = blockIdx.x * BN;

    const uint32_t sb = (uint32_t)__cvta_generic_to_shared(smem);
    const uint32_t B_OFF = BM * AST * 2;

    const int lrow = tid >> 1;
    const int lc   = (tid & 1) * 2;
    const size_t aoff = (size_t)(mt + lrow) * KA + lc * 8;
    const size_t boff = (size_t)(nt + lrow) * KA + lc * 8;
    const __nv_bfloat16* aSrc[2] = {Ah + aoff, Al + aoff};
    const __nv_bfloat16* bSrc[2] = {Wh + boff, Wl + boff};
    const uint32_t dA = sb + (lrow * AST + lc * 8) * 2;
    const uint32_t dB = sb + B_OFF + (lrow * AST + lc * 8) * 2;

    float c[4][4][4];
#pragma unroll
    for (int i = 0; i < 4; i++)
#pragma unroll
        for (int j = 0; j < 4; j++)
#pragma unroll
            for (int r = 0; r < 4; r++) c[i][j][r] = 0.f;

    const int al  = lane & 15;
    const int ahi = lane >> 4;

#define ISSUE(j) do {                                                       \
        const int t_  = (j) >> 5;                                           \
        const int k0_ = ((j) & 31) * BK;                                    \
        const __nv_bfloat16* ga_ = aSrc[t_ == 2 ? 1 : 0] + k0_;             \
        const __nv_bfloat16* gb_ = bSrc[t_ == 1 ? 1 : 0] + k0_;             \
        const uint32_t so_ = ((j) & 3) * STAGE_BYTES;                       \
        cp16(dA + so_, ga_);       cp16(dA + so_ + 16, ga_ + 8);            \
        cp16(dB + so_, gb_);       cp16(dB + so_ + 16, gb_ + 8);            \
    } while (0)

    ISSUE(0); cp_commit();
    ISSUE(1); cp_commit();
    ISSUE(2); cp_commit();

    for (int it = 0; it < NIT3; it++) {
        cp_wait2();
        __syncthreads();
        if (it + 3 < NIT3) ISSUE(it + 3);
        cp_commit();

        const uint32_t sA = sb + (it & 3) * STAGE_BYTES;
        const uint32_t sB = sA + B_OFF;
#pragma unroll
        for (int ks = 0; ks < 2; ks++) {
            const int kg = ks * 2 + ahi;
            uint32_t a[4][4], b[4][2];
#pragma unroll
            for (int i = 0; i < 4; i++) {
                uint32_t ad = sA + ((wm * 64 + i * 16 + al) * AST + kg * 8) * 2;
                ldsm_x4(a[i][0], a[i][1], a[i][2], a[i][3], ad);
            }
#pragma unroll
            for (int jj = 0; jj < 2; jj++) {
                uint32_t bd = sB + ((wn * 32 + jj * 16 + al) * AST + kg * 8) * 2;
                uint32_t r0, r1, r2, r3;
                ldsm_x4(r0, r1, r2, r3, bd);
                b[jj * 2 + 0][0] = r0; b[jj * 2 + 1][0] = r1;
                b[jj * 2 + 0][1] = r2; b[jj * 2 + 1][1] = r3;
            }
#pragma unroll
            for (int i = 0; i < 4; i++)
#pragma unroll
                for (int j = 0; j < 4; j++) mma16816(c[i][j], a[i], b[j]);
        }
    }
#undef ISSUE

    float* dst;
    bool add_pe = false;
    int ncol0;
    if (qkv_mode) {
        const int seg = nt >> 10;
        dst = (seg == 0) ? Cq : (seg == 1 ? Ck : Cv);
        add_pe = (seg != 0);
        ncol0 = nt & 1023;
    } else {
        dst = Cq;
        ncol0 = nt;
    }

    const int mbase = mt + wm * 64;
    const int nbase = ncol0 + wn * 32;
    const int rr = lane >> 2, cc = (lane & 3) * 2;
#pragma unroll
    for (int i = 0; i < 4; i++) {
#pragma unroll
        for (int j = 0; j < 4; j++) {
            int row = mbase + i * 16 + rr;
            int col = nbase + j * 8 + cc;
            float2 v0 = make_float2(c[i][j][0], c[i][j][1]);
            float2 v1 = make_float2(c[i][j][2], c[i][j][3]);
            if (qkv_mode) {
                if (add_pe) {
                    const float* p0 = extra + (row & 15) * 1024 + col;
                    const float* p1 = extra + ((row + 8) & 15) * 1024 + col;
                    v0.x += p0[0]; v0.y += p0[1];
                    v1.x += p1[0]; v1.y += p1[1];
                }
            } else {
                v0.x += extra[col]; v0.y += extra[col + 1];
                v1.x += extra[col]; v1.y += extra[col + 1];
            }
            *(float2*)(dst + (size_t)row * 1024 + col)       = v0;
            *(float2*)(dst + (size_t)(row + 8) * 1024 + col) = v1;
        }
    }
}

// ======================= fp32 SGEMM, K-split x4 (ck/cv partials) ====================
__global__ __launch_bounds__(256) void csgemm_kernel(
    const float* __restrict__ Ak, const float* __restrict__ Av,
    const float* __restrict__ Wk, const float* __restrict__ Wv)
{
    const int path = blockIdx.z >> 2, kc = blockIdx.z & 3;
    const float* A  = path ? Av : Ak;
    const float* Bm = path ? Wv : Wk;
    float* C = g_cp + (size_t)blockIdx.z * (128 * 1024);

    __shared__ float As[16][132];
    __shared__ float Bs[16][64];

    const int tid = threadIdx.x;
    const int bn  = blockIdx.x * 64;
    const int tx  = tid & 15;
    const int ty  = tid >> 4;

    const int arow = tid >> 1;
    const int acol = (tid & 1) * 8;
    const int brow = tid >> 4;
    const int bcol = (tid & 15) * 4;

    float acc[8][4];
#pragma unroll
    for (int i = 0; i < 8; i++)
#pragma unroll
        for (int j = 0; j < 4; j++) acc[i][j] = 0.f;

    const int kbeg = kc * 256, kend = kbeg + 256;
    for (int k0 = kbeg; k0 < kend; k0 += 16) {
        float4 a0 = *(const float4*)(A + arow * 1024 + k0 + acol);
        float4 a1 = *(const float4*)(A + arow * 1024 + k0 + acol + 4);
        As[acol+0][arow] = a0.x; As[acol+1][arow] = a0.y;
        As[acol+2][arow] = a0.z; As[acol+3][arow] = a0.w;
        As[acol+4][arow] = a1.x; As[acol+5][arow] = a1.y;
        As[acol+6][arow] = a1.z; As[acol+7][arow] = a1.w;
        float4 b4 = *(const float4*)(Bm + (k0 + brow) * 1024 + bn + bcol);
        *(float4*)&Bs[brow][bcol] = b4;
        __syncthreads();

#pragma unroll
        for (int kk = 0; kk < 16; kk++) {
            float4 t0 = *(const float4*)&As[kk][ty * 8];
            float4 t1 = *(const float4*)&As[kk][ty * 8 + 4];
            float4 bb = *(const float4*)&Bs[kk][tx * 4];
            float ar[8] = {t0.x, t0.y, t0.z, t0.w, t1.x, t1.y, t1.z, t1.w};
            float br[4] = {bb.x, bb.y, bb.z, bb.w};
#pragma unroll
            for (int i = 0; i < 8; i++)
#pragma unroll
                for (int j = 0; j < 4; j++) acc[i][j] += ar[i] * br[j];
        }
        __syncthreads();
    }

#pragma unroll
    for (int i = 0; i < 8; i++) {
        int m = ty * 8 + i;
#pragma unroll
        for (int j = 0; j < 4; j++)
            C[m * 1024 + bn + tx * 4 + j] = acc[i][j];
    }
}

__global__ __launch_bounds__(256) void reduce_ckcv_kernel(
    const float* __restrict__ bk, const float* __restrict__ bv)
{
    int idx = blockIdx.x * 256 + threadIdx.x;
    int path = idx >> 17, off = idx & 131071;
    const float* P = g_cp + (size_t)path * 4 * 131072;
    float s = P[off] + P[131072 + off] + P[2 * 131072 + off] + P[3 * 131072 + off];
    s += (path ? bv : bk)[off & 1023];
    (path ? g_cv : g_ck)[off] = s;
}

// ======================= fp32 NT GEMM, K-split x4 ===================================
__global__ __launch_bounds__(256) void nt_gemm_kernel(
    const float* __restrict__ A, const float* __restrict__ B, float* __restrict__ C,
    int N, long aB, long bB, long cB)
{
    const int b = blockIdx.z >> 2, kc = blockIdx.z & 3;
    const float* Ab = A + (size_t)b * aB;
    const float* Bb = B + (size_t)b * bB;
    float* Cb = C + (size_t)blockIdx.z * cB;

    __shared__ float As[64][33];
    __shared__ float Bs[64][33];

    const int tid = threadIdx.x;
    const int row = tid >> 2;
    const int c4  = (tid & 3) * 8;
    const int ty = tid >> 4, tx = tid & 15;
    const int i0 = blockIdx.y * 64, j0 = blockIdx.x * 64;

    float acc[4][4];
#pragma unroll
    for (int i = 0; i < 4; i++)
#pragma unroll
        for (int j = 0; j < 4; j++) acc[i][j] = 0.f;

    const int kbeg = kc * 256, kend = kbeg + 256;
    for (int k0 = kbeg; k0 < kend; k0 += 32) {
        float4 a0 = *(const float4*)(Ab + (size_t)(i0 + row) * 1024 + k0 + c4);
        float4 a1 = *(const float4*)(Ab + (size_t)(i0 + row) * 1024 + k0 + c4 + 4);
        As[row][c4+0] = a0.x; As[row][c4+1] = a0.y;
        As[row][c4+2] = a0.z; As[row][c4+3] = a0.w;
        As[row][c4+4] = a1.x; As[row][c4+5] = a1.y;
        As[row][c4+6] = a1.z; As[row][c4+7] = a1.w;
        float4 b0 = *(const float4*)(Bb + (size_t)(j0 + row) * 1024 + k0 + c4);
        float4 b1 = *(const float4*)(Bb + (size_t)(j0 + row) * 1024 + k0 + c4 + 4);
        Bs[row][c4+0] = b0.x; Bs[row][c4+1] = b0.y;
        Bs[row][c4+2] = b0.z; Bs[row][c4+3] = b0.w;
        Bs[row][c4+4] = b1.x; Bs[row][c4+5] = b1.y;
        Bs[row][c4+6] = b1.z; Bs[row][c4+7] = b1.w;
        __syncthreads();

#pragma unroll 8
        for (int k = 0; k < 32; k++) {
            float ar[4], br[4];
#pragma unroll
            for (int i = 0; i < 4; i++) ar[i] = As[ty * 4 + i][k];
#pragma unroll
            for (int j = 0; j < 4; j++) br[j] = Bs[tx * 4 + j][k];
#pragma unroll
            for (int i = 0; i < 4; i++)
#pragma unroll
                for (int j = 0; j < 4; j++) acc[i][j] += ar[i] * br[j];
        }
        __syncthreads();
    }

#pragma unroll
    for (int i = 0; i < 4; i++)
#pragma unroll
        for (int j = 0; j < 4; j++)
            Cb[(size_t)(i0 + ty * 4 + i) * N + j0 + tx * 4 + j] = acc[i][j];
}

__global__ __launch_bounds__(256) void reduce4_kernel(
    const float* __restrict__ P, float* __restrict__ out, int n)
{
    int idx = blockIdx.x * 256 + threadIdx.x;
    int b = idx / n, off = idx - b * n;
    const float* Pb = P + (size_t)b * 4 * n;
    out[idx] = Pb[off] + Pb[n + off] + Pb[2 * n + off] + Pb[3 * n + off];
}

// ---------------- exact compressed-row inputs ---------------------------------------
__global__ __launch_bounds__(256) void xc_kernel(
    const float* __restrict__ x, const float* __restrict__ wkc,
    const float* __restrict__ wvc)
{
    int idx = blockIdx.x * 256 + threadIdx.x;
    int d = idx & 1023;
    int n = (idx >> 10) & 63;
    int b = idx >> 16;
    const float* xb = x + ((size_t)(b * NS + n * NCB)) * ND + d;
    float sk = 0.f, sv = 0.f;
#pragma unroll
    for (int t = 0; t < NCB; t++) {
        float xv = xb[t * ND];
        sk += wkc[t] * xv;
        sv += wvc[t] * xv;
    }
    g_xkc[idx] = sk;
    g_xvc[idx] = sv;
}

__global__ __launch_bounds__(256) void pe_comb_kernel(
    const float* __restrict__ wpe, const float* __restrict__ wkc,
    const float* __restrict__ wvc)
{
    int d = blockIdx.x * 256 + threadIdx.x;
    float sk = 0.f, sv = 0.f;
#pragma unroll
    for (int t = 0; t < NCB; t++) {
        float p = wpe[t * ND + d];
        sk += wkc[t] * p;
        sv += wvc[t] * p;
    }
    g_pec[d] = sk;
    g_pvc[d] = sv;
}

// ---------------- top-2 ---------------------------------------------------------------
__global__ __launch_bounds__(256) void top2_kernel()
{
    const int bs = blockIdx.x * 8 + (threadIdx.x >> 5);
    const int lane = threadIdx.x & 31;
    const float* row = g_imp + (size_t)bs * 64;
    float v0 = row[lane], v1 = row[lane + 32];

    float bv; int bi;
    if (v0 >= v1) { bv = v0; bi = lane; } else { bv = v1; bi = lane + 32; }
#pragma unroll
    for (int off = 16; off > 0; off >>= 1) {
        float ov = __shfl_xor_sync(0xffffffffu, bv, off);
        int   oi = __shfl_xor_sync(0xffffffffu, bi, off);
        if (ov > bv || (ov == bv && oi < bi)) { bv = ov; bi = oi; }
    }
    int top1 = bi;
    float w0 = (lane == top1)      ? NEG : v0;
    float w1 = (lane + 32 == top1) ? NEG : v1;
    float bv2; int bi2;
    if (w0 >= w1) { bv2 = w0; bi2 = lane; } else { bv2 = w1; bi2 = lane + 32; }
#pragma unroll
    for (int off = 16; off > 0; off >>= 1) {
        float ov = __shfl_xor_sync(0xffffffffu, bv2, off);
        int   oi = __shfl_xor_sync(0xffffffffu, bi2, off);
        if (ov > bv2 || (ov == bv2 && oi < bi2)) { bv2 = ov; bi2 = oi; }
    }
    if (lane == 0) { g_top[bs * 2] = top1; g_top[bs * 2 + 1] = bi2; }
}

// ---------------- register-tiled compressed attention ---------------------------------
__global__ __launch_bounds__(256) void comp_attn_tile_kernel()
{
    extern __shared__ float sm[];
    float* Qt = sm;
    float* Kt = sm + 64 * TS;
    float* Vs = sm + 2 * 64 * TS;
    float* Ps = sm + 3 * 64 * TS;

    const int st = blockIdx.x, h = blockIdx.y, b = blockIdx.z;
    const int tid = threadIdx.x;
    const int ty = tid >> 4, tx = tid & 15;
    const int qbase = st * 64;

    for (int i = tid; i < 4096; i += 256) {
        int r = i >> 6, d = i & 63;
        Qt[d * TS + r] = g_q[((size_t)(b * NS + qbase + r)) * ND + h * 64 + d];
        const size_t gc = ((size_t)(b * 64 + r)) * ND + h * 64 + d;
        Kt[d * TS + r] = g_ck[gc];
        Vs[r * TS + d] = g_cv[gc];
    }
    __syncthreads();

    float s[4][4];
#pragma unroll
    for (int i = 0; i < 4; i++)
#pragma unroll
        for (int j = 0; j < 4; j++) s[i][j] = 0.f;

#pragma unroll 8
    for (int d = 0; d < 64; d++) {
        float4 qv = *(const float4*)&Qt[d * TS + ty * 4];
        float4 kv = *(const float4*)&Kt[d * TS + tx * 4];
        float qa[4] = {qv.x, qv.y, qv.z, qv.w};
        float ka[4] = {kv.x, kv.y, kv.z, kv.w};
#pragma unroll
        for (int i = 0; i < 4; i++)
#pragma unroll
            for (int j = 0; j < 4; j++) s[i][j] += qa[i] * ka[j];
    }
#pragma unroll
    for (int i = 0; i < 4; i++)
#pragma unroll
        for (int j = 0; j < 4; j++)
            Ps[(ty * 4 + i) * PS + tx * 4 + j] = s[i][j] * INVS;
    __syncthreads();

    __shared__ float rowl[64];
    if (tid < 64) {
        float* pr = Ps + tid * PS;
        float m = NEG;
#pragma unroll 8
        for (int c = 0; c < 64; c++) m = fmaxf(m, pr[c]);
        float l = 0.f;
#pragma unroll 8
        for (int c = 0; c < 64; c++) { float p = __expf(pr[c] - m); pr[c] = p; l += p; }
        rowl[tid] = 1.f / l;
    }
    __syncthreads();

    float acc[4][4];
#pragma unroll
    for (int i = 0; i < 4; i++)
#pragma unroll
        for (int j = 0; j < 4; j++) acc[i][j] = 0.f;
#pragma unroll 8
    for (int c = 0; c < 64; c++) {
        float4 vv = *(const float4*)&Vs[c * TS + tx * 4];
        float va[4] = {vv.x, vv.y, vv.z, vv.w};
#pragma unroll
        for (int i = 0; i < 4; i++) {
            float p = Ps[(ty * 4 + i) * PS + c];
#pragma unroll
            for (int j = 0; j < 4; j++) acc[i][j] += p * va[j];
        }
    }
#pragma unroll
    for (int i = 0; i < 4; i++) {
        const float rl = rowl[ty * 4 + i];
        float* orow = g_oc + ((size_t)(b * NS + qbase + ty * 4 + i)) * ND + h * 64 + tx * 4;
        float4 o = make_float4(acc[i][0] * rl, acc[i][1] * rl, acc[i][2] * rl, acc[i][3] * rl);
        *(float4*)orow = o;
    }
}

// ---------------- register-tiled sliding-window attention ------------------------------
__global__ __launch_bounds__(256) void win_attn_kernel()
{
    extern __shared__ float sm[];
    float* Qt = sm;
    float* Kt = sm + 64 * TS;
    float* Vs = sm + 2 * 64 * TS;
    float* Ps = sm + 3 * 64 * TS;

    __shared__ float rowm[64], rowl[64], rowsc[64];

    const int qt = blockIdx.x, h = blockIdx.y, b = blockIdx.z;
    const int tid = threadIdx.x;
    const int ty = tid >> 4, tx = tid & 15;
    const int qbase = qt * 64;

    for (int i = tid; i < 4096; i += 256) {
        int r = i >> 6, d = i & 63;
        Qt[d * TS + r] = g_q[((size_t)(b * NS + qbase + r)) * ND + h * 64 + d];
    }
    if (tid < 64) { rowm[tid] = NEG; rowl[tid] = 0.f; }

    float acc[4][4];
#pragma unroll
    for (int i = 0; i < 4; i++)
#pragma unroll
        for (int j = 0; j < 4; j++) acc[i][j] = 0.f;

    const int kt_lo = (qt >= 4) ? qt - 4 : 0;
    for (int kt = kt_lo; kt <= qt; kt++) {
        const int kbase = kt * 64;
        __syncthreads();
        for (int i = tid; i < 4096; i += 256) {
            int r = i >> 6, d = i & 63;
            const size_t g = ((size_t)(b * NS + kbase + r)) * ND + h * 64 + d;
            Kt[d * TS + r] = g_k[g];
            Vs[r * TS + d] = g_v[g];
        }
        __syncthreads();

        float s[4][4];
#pragma unroll
        for (int i = 0; i < 4; i++)
#pragma unroll
            for (int j = 0; j < 4; j++) s[i][j] = 0.f;
#pragma unroll 8
        for (int d = 0; d < 64; d++) {
            float4 qv = *(const float4*)&Qt[d * TS + ty * 4];
            float4 kv = *(const float4*)&Kt[d * TS + tx * 4];
            float qa[4] = {qv.x, qv.y, qv.z, qv.w};
            float ka[4] = {kv.x, kv.y, kv.z, kv.w};
#pragma unroll
            for (int i = 0; i < 4; i++)
#pragma unroll
                for (int j = 0; j < 4; j++) s[i][j] += qa[i] * ka[j];
        }
#pragma unroll
        for (int i = 0; i < 4; i++) {
            const int qi = qbase + ty * 4 + i;
#pragma unroll
            for (int j = 0; j < 4; j++) {
                const int kj = kbase + tx * 4 + j;
                float v = (kj <= qi && qi - kj <= NWIN) ? s[i][j] * INVS : NEG;
                Ps[(ty * 4 + i) * PS + tx * 4 + j] = v;
            }
        }
        __syncthreads();

        if (tid < 64) {
            float* pr = Ps + tid * PS;
            float m = rowm[tid], mn = m;
#pragma unroll 8
            for (int c = 0; c < 64; c++) mn = fmaxf(mn, pr[c]);
            float sc = __expf(m - mn);
            float l = rowl[tid] * sc;
#pragma unroll 8
            for (int c = 0; c < 64; c++) { float p = __expf(pr[c] - mn); pr[c] = p; l += p; }
            rowm[tid] = mn; rowl[tid] = l; rowsc[tid] = sc;
        }
        __syncthreads();

#pragma unroll
        for (int i = 0; i < 4; i++) {
            const float sc = rowsc[ty * 4 + i];
#pragma unroll
            for (int j = 0; j < 4; j++) acc[i][j] *= sc;
        }
#pragma unroll 8
        for (int c = 0; c < 64; c++) {
            float4 vv = *(const float4*)&Vs[c * TS + tx * 4];
            float va[4] = {vv.x, vv.y, vv.z, vv.w};
#pragma unroll
            for (int i = 0; i < 4; i++) {
                float p = Ps[(ty * 4 + i) * PS + c];
#pragma unroll
                for (int j = 0; j < 4; j++) acc[i][j] += p * va[j];
            }
        }
    }

#pragma unroll
    for (int i = 0; i < 4; i++) {
        const float rl = 1.f / rowl[ty * 4 + i];
        float* orow = g_ow + ((size_t)(b * NS + qbase + ty * 4 + i)) * ND + h * 64 + tx * 4;
        float4 o = make_float4(acc[i][0] * rl, acc[i][1] * rl, acc[i][2] * rl, acc[i][3] * rl);
        *(float4*)orow = o;
    }
}

// ---------------- selected attention ---------------------------------------------------
__global__ __launch_bounds__(512) void sel_attn_kernel()
{
    const int bs = blockIdx.x;
    const int b  = bs >> 10, s = bs & 1023;
    const int tid = threadIdx.x;
    const int h = tid >> 5, lane = tid & 31;

    __shared__ int blk_s[2];
    if (tid < 2) blk_s[tid] = g_top[(tid * NS + s) * 2 + b];
    __syncthreads();

    const float2 q2 = *(const float2*)(g_q + bs * ND + h * 64 + lane * 2);

    float myscore = NEG;
#pragma unroll
    for (int m = 0; m < 16; m++) {
        int j = m >> 3, t = m & 7;
        int tok = blk_s[j] * NCB + t;
        float2 k2 = *(const float2*)(g_k + (j * NS + tok) * ND + h * 64 + lane * 2);
        float p = q2.x * k2.x + q2.y * k2.y;
#pragma unroll
        for (int off = 16; off > 0; off >>= 1)
            p += __shfl_xor_sync(0xffffffffu, p, off);
        p *= INVS;
        if (lane == m) myscore = p;
    }
    float mx = myscore;
#pragma unroll
    for (int off = 16; off > 0; off >>= 1)
        mx = fmaxf(mx, __shfl_xor_sync(0xffffffffu, mx, off));
    float p = __expf(myscore - mx);
    float sum = p;
#pragma unroll
    for (int off = 16; off > 0; off >>= 1)
        sum += __shfl_xor_sync(0xffffffffu, sum, off);
    float rs = 1.f / sum;

    float2 acc = make_float2(0.f, 0.f);
#pragma unroll
    for (int m = 0; m < 16; m++) {
        float pm = __shfl_sync(0xffffffffu, p, m);
        int j = m >> 3, t = m & 7;
        int tok = blk_s[j] * NCB + t;
        float2 v2 = *(const float2*)(g_v + (j * NS + tok) * ND + h * 64 + lane * 2);
        acc.x += pm * v2.x; acc.y += pm * v2.y;
    }
    acc.x *= rs; acc.y *= rs;
    *(float2*)(g_os + bs * ND + h * 64 + lane * 2) = acc;
}

// ---------------- gates -----------------------------------------------------------------
__global__ __launch_bounds__(256) void gate_kernel(
    const float* __restrict__ x, const float* __restrict__ Wg,
    const float* __restrict__ bg)
{
    const int row = blockIdx.x * 8 + (threadIdx.x >> 5);
    const int lane = threadIdx.x & 31;
    const float* xr = x + (size_t)row * ND;
    float a0 = 0.f, a1 = 0.f, a2 = 0.f;
    for (int d = lane; d < ND; d += 32) {
        float xv = xr[d];
        a0 += xv * Wg[d * 3 + 0];
        a1 += xv * Wg[d * 3 + 1];
        a2 += xv * Wg[d * 3 + 2];
    }
#pragma unroll
    for (int off = 16; off > 0; off >>= 1) {
        a0 += __shfl_xor_sync(0xffffffffu, a0, off);
        a1 += __shfl_xor_sync(0xffffffffu, a1, off);
        a2 += __shfl_xor_sync(0xffffffffu, a2, off);
    }
    if (lane == 0) {
        g_gates[row * 3 + 0] = 1.f / (1.f + __expf(-(a0 + bg[0])));
        g_gates[row * 3 + 1] = 1.f / (1.f + __expf(-(a1 + bg[1])));
        g_gates[row * 3 + 2] = 1.f / (1.f + __expf(-(a2 + bg[2])));
    }
}

// ---------------- fused combine + bf16-split (writes GEMM inputs directly) --------------
__global__ __launch_bounds__(256) void combine_split_kernel()
{
    int idx = (blockIdx.x * 256 + threadIdx.x) * 4;
    int bs = idx >> 10;
    float g0 = g_gates[bs * 3 + 0];
    float g1 = g_gates[bs * 3 + 1];
    float g2 = g_gates[bs * 3 + 2];
    float4 oc = *(const float4*)(g_oc + idx);
    float4 os = *(const float4*)(g_os + idx);
    float4 ow = *(const float4*)(g_ow + idx);
    float v0 = g0 * oc.x + g1 * os.x + g2 * ow.x;
    float v1 = g0 * oc.y + g1 * os.y + g2 * ow.y;
    float v2 = g0 * oc.z + g1 * os.z + g2 * ow.z;
    float v3 = g0 * oc.w + g1 * os.w + g2 * ow.w;
    __nv_bfloat16 h0 = __float2bfloat16(v0), h1 = __float2bfloat16(v1);
    __nv_bfloat16 h2 = __float2bfloat16(v2), h3 = __float2bfloat16(v3);
    *(__nv_bfloat162*)(g_ah + idx)     = __halves2bfloat162(h0, h1);
    *(__nv_bfloat162*)(g_ah + idx + 2) = __halves2bfloat162(h2, h3);
    *(__nv_bfloat162*)(g_al + idx) = __halves2bfloat162(
        __float2bfloat16(v0 - __bfloat162float(h0)),
        __float2bfloat16(v1 - __bfloat162float(h1)));
    *(__nv_bfloat162*)(g_al + idx + 2) = __halves2bfloat162(
        __float2bfloat16(v2 - __bfloat162float(h2)),
        __float2bfloat16(v3 - __bfloat162float(h3)));
}

// ---------------- launcher ---------------------------------------------------------------
extern "C" void kernel_launch(void* const* d_in, const int* in_sizes, int n_in,
                              void* d_out, int out_size)
{
    (void)in_sizes; (void)n_in; (void)out_size;
    const float* x   = (const float*)d_in[0];
    const float* Wq  = (const float*)d_in[1];
    const float* Wk  = (const float*)d_in[2];
    const float* Wv  = (const float*)d_in[3];
    const float* Wo  = (const float*)d_in[4];
    const float* bo  = (const float*)d_in[5];
    const float* Wg  = (const float*)d_in[6];
    const float* bg  = (const float*)d_in[7];
    const float* wkc = (const float*)d_in[8];
    const float* wvc = (const float*)d_in[9];
    const float* wpe = (const float*)d_in[10];
    float* out = (float*)d_out;

    void *pq, *pk, *pv, *pah, *pal, *pwh, *pwl, *pwoh, *pwol;
    void *pxkc, *pxvc, *pck, *pcv, *ptt, *pimp, *ppec, *ppvc, *pttp, *pimpp;
    cudaGetSymbolAddress(&pq,   g_q);
    cudaGetSymbolAddress(&pk,   g_k);
    cudaGetSymbolAddress(&pv,   g_v);
    cudaGetSymbolAddress(&pah,  g_ah);
    cudaGetSymbolAddress(&pal,  g_al);
    cudaGetSymbolAddress(&pwh,  g_wh);
    cudaGetSymbolAddress(&pwl,  g_wl);
    cudaGetSymbolAddress(&pwoh, g_woh);
    cudaGetSymbolAddress(&pwol, g_wol);
    cudaGetSymbolAddress(&pxkc, g_xkc);
    cudaGetSymbolAddress(&pxvc, g_xvc);
    cudaGetSymbolAddress(&pck,  g_ck);
    cudaGetSymbolAddress(&pcv,  g_cv);
    cudaGetSymbolAddress(&ptt,  g_tt);
    cudaGetSymbolAddress(&pimp, g_imp);
    cudaGetSymbolAddress(&ppec, g_pec);
    cudaGetSymbolAddress(&ppvc, g_pvc);
    cudaGetSymbolAddress(&pttp, g_ttp);
    cudaGetSymbolAddress(&pimpp, g_impp);

    const __nv_bfloat16* ah  = (const __nv_bfloat16*)pah;
    const __nv_bfloat16* alo = (const __nv_bfloat16*)pal;
    const int NEL = NB * NS * ND;

    static bool inited = false;
    static cudaStream_t sB, sC;
    static cudaEvent_t e0, e1, eB, eC;
    if (!inited) {
        cudaStreamCreateWithFlags(&sB, cudaStreamNonBlocking);
        cudaStreamCreateWithFlags(&sC, cudaStreamNonBlocking);
        cudaEventCreateWithFlags(&e0, cudaEventDisableTiming);
        cudaEventCreateWithFlags(&e1, cudaEventDisableTiming);
        cudaEventCreateWithFlags(&eB, cudaEventDisableTiming);
        cudaEventCreateWithFlags(&eC, cudaEventDisableTiming);
        cudaFuncSetAttribute(mma_gemm3_kernel,
                             cudaFuncAttributeMaxDynamicSharedMemorySize, SMEM_GEMM);
        cudaFuncSetAttribute(win_attn_kernel,
                             cudaFuncAttributeMaxDynamicSharedMemorySize, SMEM_ATT);
        cudaFuncSetAttribute(comp_attn_tile_kernel,
                             cudaFuncAttributeMaxDynamicSharedMemorySize, SMEM_ATT);
        inited = true;
    }

    cudaEventRecord(e0, 0);
    cudaStreamWaitEvent(sB, e0, 0);
    cudaStreamWaitEvent(sC, e0, 0);

    // ---- main stream: bf16 prep + QKV GEMM ----
    split_kernel<<<NEL / 1024, 256>>>(x, (__nv_bfloat16*)pah, (__nv_bfloat16*)pal);
    convert_w3_kernel<<<dim3(32, 32, 3), 256>>>(
        Wq, Wk, Wv, (__nv_bfloat16*)pwh, (__nv_bfloat16*)pwl);
    mma_gemm3_kernel<<<dim3(24, 16), 256, SMEM_GEMM>>>(
        ah, alo, (const __nv_bfloat16*)pwh, (const __nv_bfloat16*)pwl,
        (float*)pq, (float*)pk, (float*)pv, wpe, 1);
    cudaEventRecord(e1, 0);

    // ---- stream B: exact fp32 top-k chain ----
    xc_kernel<<<(NB * NNC * ND) / 256, 256, 0, sB>>>(x, wkc, wvc);
    pe_comb_kernel<<<ND / 256, 256, 0, sB>>>(wpe, wkc, wvc);
    csgemm_kernel<<<dim3(16, 1, 8), 256, 0, sB>>>(
        (const float*)pxkc, (const float*)pxvc, Wk, Wv);
    reduce_ckcv_kernel<<<(2 * 131072) / 256, 256, 0, sB>>>(
        (const float*)ppec, (const float*)ppvc);
    nt_gemm_kernel<<<dim3(16, 1, 8), 256, 0, sB>>>(
        (const float*)pck, Wq, (float*)pttp, 1024, 64L * 1024, 0L, 64L * 1024);
    reduce4_kernel<<<(NB * 65536) / 256, 256, 0, sB>>>(
        (const float*)pttp, (float*)ptt, 65536);
    nt_gemm_kernel<<<dim3(1, 16, 8), 256, 0, sB>>>(
        x, (const float*)ptt, (float*)pimpp, 64, 1024L * 1024, 64L * 1024, 1024L * 64);
    reduce4_kernel<<<(NB * 65536) / 256, 256, 0, sB>>>(
        (const float*)pimpp, (float*)pimp, 65536);
    top2_kernel<<<(NB * NS) / 8, 256, 0, sB>>>();
    cudaStreamWaitEvent(sB, e1, 0);
    comp_attn_tile_kernel<<<dim3(16, 16, 2), 256, SMEM_ATT, sB>>>();
    sel_attn_kernel<<<NB * NS, 512, 0, sB>>>();
    cudaEventRecord(eB, sB);

    // ---- stream C: gates + Wo conversion (off critical path) ----
    gate_kernel<<<(NB * NS) / 8, 256, 0, sC>>>(x, Wg, bg);
    convert_w1_kernel<<<dim3(32, 32), 256, 0, sC>>>(
        Wo, (__nv_bfloat16*)pwoh, (__nv_bfloat16*)pwol);
    cudaEventRecord(eC, sC);

    // ---- main: window attention, join, fused combine+split, OUT GEMM ----
    win_attn_kernel<<<dim3(NS / 64, NH, NB), 256, SMEM_ATT>>>();
    cudaStreamWaitEvent(0, eB, 0);
    cudaStreamWaitEvent(0, eC, 0);
    combine_split_kernel<<<NEL / 1024, 256>>>();
    mma_gemm3_kernel<<<dim3(8, 16), 256, SMEM_GEMM>>>(
        ah, alo, (const __nv_bfloat16*)pwoh, (const __nv_bfloat16*)pwol,
        out, out, out, bo, 0);
}